// round 5
// baseline (speedup 1.0000x reference)
#include <cuda_runtime.h>
#include <cstdint>

// Problem dims (fixed by the benchmark)
#define B_DIM 8
#define C_DIM 256
#define N_TOK 1024           // text tokens
#define M_PIX 9216           // 96*96
#define L_DIM 2048           // B*C
#define TEXT_B_STRIDE  262144    // 1024*256
#define IMG_B_STRIDE   2359296   // 256*9216

#define NITER 50
// EPSILON = 0.1 ; K = exp(-cost/eps) = exp(-10*cost) ; T = exp(-cost*eps)=exp(-0.1*cost)
#define CONV_TOL_SQ 1e-4f    // (0.01)^2
#define DENOM_SHIFT 100.0f

// ---------------- device scratch (no mallocs allowed) ----------------
__device__ float g_cost[(size_t)N_TOK * M_PIX];  // 37.75 MB; becomes T in-place
__device__ float g_sqA[N_TOK];
__device__ float g_sqB[M_PIX];
__device__ float g_u[N_TOK];
__device__ float g_v[M_PIX];
__device__ float g_normU[64];
__device__ float g_normV[64];
__device__ unsigned g_bar_count;
__device__ unsigned g_bar_gen;

// ---------------- init (runs every launch; graph-replay safe) ----------------
__global__ void k_init() {
    int tid = blockIdx.x * blockDim.x + threadIdx.x;
    if (tid < N_TOK) g_u[tid] = 1.0f;
    if (tid < M_PIX) { g_v[tid] = 1.0f; g_sqB[tid] = 0.0f; }
    if (tid < 64) { g_normU[tid] = 0.0f; g_normV[tid] = 0.0f; }
    if (tid == 0) { g_bar_count = 0u; g_bar_gen = 0u; }
}

// ---------------- squared norms ----------------
__global__ void k_sq_text(const float* __restrict__ text) {
    __shared__ float sh[256];
    int n = blockIdx.x;
    int c = threadIdx.x; // 256 threads, one per channel
    float s = 0.0f;
#pragma unroll
    for (int b = 0; b < B_DIM; ++b) {
        float x = text[(size_t)b * TEXT_B_STRIDE + (size_t)n * C_DIM + c];
        s += x * x;
    }
    sh[c] = s; __syncthreads();
    for (int off = 128; off > 0; off >>= 1) {
        if (c < off) sh[c] += sh[c + off];
        __syncthreads();
    }
    if (c == 0) g_sqA[n] = sh[0];
}

__global__ void k_sq_image(const float* __restrict__ image) {
    int m = blockIdx.x * 256 + threadIdx.x;     // grid.x = 36
    int l0 = blockIdx.y * 256;                  // grid.y = 8
    float s = 0.0f;
    for (int l = l0; l < l0 + 256; ++l) {
        float x = image[(size_t)l * M_PIX + m];
        s += x * x;
    }
    atomicAdd(&g_sqB[m], s);
}

// ---------------- GEMM common config ----------------
#define BM 128
#define BN 128
#define BK 16
// 256 threads, 16x16 thread grid, 8x8 micro-tile

// GEMM1: cost[n,m] = sqrt(max(sqA[n]+sqB[m]-2*sum_l A[l,n]*Bf[l,m], 1e-12))
// A[l,n] = text[b,n,c] (l=b*256+c) ; Bf[l,m] = image[b,c,m]
__global__ void k_gemm1_cost(const float* __restrict__ text,
                             const float* __restrict__ image) {
    __shared__ float As[BK][BM];  // [l][n]
    __shared__ float Bs[BK][BN];  // [l][m]
    const int tid = threadIdx.x;
    const int ty = tid >> 4, tx = tid & 15;
    const int m0 = blockIdx.x * BN;   // 72 tiles
    const int n0 = blockIdx.y * BM;   // 8 tiles
    float acc[8][8] = {};
    for (int kt = 0; kt < L_DIM; kt += BK) {
        const int bb = kt >> 8, cc0 = kt & 255;
        const float* tbase = text + (size_t)bb * TEXT_B_STRIDE + cc0;
#pragma unroll
        for (int it = 0; it < 2; ++it) {
            int lin = tid + it * 256;
            int row = lin >> 2, q = lin & 3;
            float4 v = *(const float4*)(tbase + (size_t)(n0 + row) * C_DIM + q * 4);
            As[q * 4 + 0][row] = v.x; As[q * 4 + 1][row] = v.y;
            As[q * 4 + 2][row] = v.z; As[q * 4 + 3][row] = v.w;
        }
        const float* ibase = image + (size_t)bb * IMG_B_STRIDE + (size_t)cc0 * M_PIX + m0;
#pragma unroll
        for (int it = 0; it < 2; ++it) {
            int lin = tid + it * 256;
            int dl = lin >> 5, q = lin & 31;
            float4 v = *(const float4*)(ibase + (size_t)dl * M_PIX + q * 4);
            *(float4*)&Bs[dl][q * 4] = v;
        }
        __syncthreads();
#pragma unroll
        for (int k = 0; k < BK; ++k) {
            float ra[8], rb[8];
#pragma unroll
            for (int i = 0; i < 8; ++i) ra[i] = As[k][ty * 8 + i];
#pragma unroll
            for (int j = 0; j < 8; ++j) rb[j] = Bs[k][tx * 8 + j];
#pragma unroll
            for (int i = 0; i < 8; ++i)
#pragma unroll
                for (int j = 0; j < 8; ++j)
                    acc[i][j] = fmaf(ra[i], rb[j], acc[i][j]);
        }
        __syncthreads();
    }
    // epilogue: cost
#pragma unroll
    for (int i = 0; i < 8; ++i) {
        int n = n0 + ty * 8 + i;
        float sa = g_sqA[n];
        float out[8];
#pragma unroll
        for (int j = 0; j < 8; ++j) {
            int m = m0 + tx * 8 + j;
            float sq = sa + g_sqB[m] - 2.0f * acc[i][j];
            out[j] = sqrtf(fmaxf(sq, 1e-12f));
        }
        float* p = g_cost + (size_t)n * M_PIX + m0 + tx * 8;
        *(float4*)p = make_float4(out[0], out[1], out[2], out[3]);
        *(float4*)(p + 4) = make_float4(out[4], out[5], out[6], out[7]);
    }
}

// ---------------- Sinkhorn: one persistent kernel, software grid barrier ----------------
__device__ __forceinline__ void grid_barrier(unsigned e, int nctas) {
    __syncthreads();
    if (threadIdx.x == 0) {
        __threadfence();
        unsigned t = atomicAdd(&g_bar_count, 1u) + 1u;
        if (t == (unsigned)nctas * e) {
            atomicExch(&g_bar_gen, e);
        } else {
            while (*((volatile unsigned*)&g_bar_gen) < e) __nanosleep(64);
        }
        __threadfence();
    }
    __syncthreads();
}

__global__ void k_sinkhorn() {
    __shared__ float sred[256];
    const int cta = blockIdx.x;
    const int tid = threadIdx.x;
    const int NC = gridDim.x;  // 148, all resident
    unsigned epoch = 0;
    for (int it = 0; it < NITER; ++it) {
        // ---- phase U: un = 1/(sum_m K[n,m]*v[m] + 100) ----
        for (int n = cta; n < N_TOK; n += NC) {
            const float* row = g_cost + (size_t)n * M_PIX;
            float s = 0.0f;
            for (int m = tid; m < M_PIX; m += 256)
                s += __expf(-10.0f * row[m]) * __ldcg(&g_v[m]);
            sred[tid] = s; __syncthreads();
            for (int off = 128; off > 0; off >>= 1) {
                if (tid < off) sred[tid] += sred[tid + off];
                __syncthreads();
            }
            if (tid == 0) {
                float un = 1.0f / (sred[0] + DENOM_SHIFT);
                float d = un - g_u[n];
                atomicAdd(&g_normU[it], d * d);
                g_u[n] = un;
            }
            __syncthreads();
        }
        ++epoch; grid_barrier(epoch, NC);
        // ---- phase V: vn = 1/(sum_n K[n,m]*u[n] + 100) ----
        for (int blk = cta; blk < (M_PIX / 64); blk += NC) {   // 144 column blocks of 64
            int col0 = blk * 64;
            int c = tid & 63, sl = tid >> 6;
            float t = 0.0f;
            for (int n = sl; n < N_TOK; n += 4)
                t += __expf(-10.0f * g_cost[(size_t)n * M_PIX + col0 + c]) * __ldcg(&g_u[n]);
            sred[tid] = t; __syncthreads();
            if (tid < 64) {
                float tt = sred[tid] + sred[tid + 64] + sred[tid + 128] + sred[tid + 192];
                int m = col0 + tid;
                float vn = 1.0f / (tt + DENOM_SHIFT);
                float d = vn - g_v[m];
                atomicAdd(&g_normV[it], d * d);
                g_v[m] = vn;
            }
            __syncthreads();
        }
        ++epoch; grid_barrier(epoch, NC);
        // ---- convergence: identical decision on all CTAs ----
        float nu = __ldcg(&g_normU[it]);
        float nv = __ldcg(&g_normV[it]);
        if (nu < CONV_TOL_SQ && nv < CONV_TOL_SQ) break;   // == reference freeze
    }
}

// ---------------- T = exp(-0.1*cost) * u[n] * v[m]  (in-place over g_cost) ----------------
__global__ void k_make_T() {
    int n = blockIdx.y;                        // 1024
    int m = blockIdx.x * 256 + threadIdx.x;    // 36*256
    size_t i = (size_t)n * M_PIX + m;
    g_cost[i] = expf(-0.1f * g_cost[i]) * g_u[n] * g_v[m];
}

// GEMM2: aligned_text[b,n,c] = sum_m Bf[l,m]*T[n,m],  l = b*256+c
// thread-tile rows = n (ty), cols = l (tx)  -> c-contiguous stores
__global__ void k_gemm2_text(const float* __restrict__ image,
                             float* __restrict__ out_text) {
    __shared__ float As[BK][BM];  // T: [dm][n]
    __shared__ float Bs[BK][BN];  // Bf: [dm][l]
    const int tid = threadIdx.x;
    const int ty = tid >> 4, tx = tid & 15;
    const int l0 = blockIdx.x * BN;   // 16 tiles
    const int n0 = blockIdx.y * BM;   // 8 tiles
    const int bb = l0 >> 8, cc0 = l0 & 255;
    float acc[8][8] = {};
    for (int kt = 0; kt < M_PIX; kt += BK) {
#pragma unroll
        for (int it = 0; it < 2; ++it) {
            int lin = tid + it * 256;
            int row = lin >> 2, q = lin & 3;
            float4 v = *(const float4*)(g_cost + (size_t)(n0 + row) * M_PIX + kt + q * 4);
            As[q * 4 + 0][row] = v.x; As[q * 4 + 1][row] = v.y;
            As[q * 4 + 2][row] = v.z; As[q * 4 + 3][row] = v.w;
        }
#pragma unroll
        for (int it = 0; it < 2; ++it) {
            int lin = tid + it * 256;
            int row = lin >> 2, q = lin & 3;  // row = l offset in tile
            float4 v = *(const float4*)(image + (size_t)bb * IMG_B_STRIDE +
                                        (size_t)(cc0 + row) * M_PIX + kt + q * 4);
            Bs[q * 4 + 0][row] = v.x; Bs[q * 4 + 1][row] = v.y;
            Bs[q * 4 + 2][row] = v.z; Bs[q * 4 + 3][row] = v.w;
        }
        __syncthreads();
#pragma unroll
        for (int k = 0; k < BK; ++k) {
            float ra[8], rb[8];
#pragma unroll
            for (int i = 0; i < 8; ++i) ra[i] = As[k][ty * 8 + i];
#pragma unroll
            for (int j = 0; j < 8; ++j) rb[j] = Bs[k][tx * 8 + j];
#pragma unroll
            for (int i = 0; i < 8; ++i)
#pragma unroll
                for (int j = 0; j < 8; ++j)
                    acc[i][j] = fmaf(ra[i], rb[j], acc[i][j]);
        }
        __syncthreads();
    }
    const int ctile = cc0 + tx * 8;
#pragma unroll
    for (int i = 0; i < 8; ++i) {
        int n = n0 + ty * 8 + i;
        float* p = out_text + (size_t)bb * TEXT_B_STRIDE + (size_t)n * C_DIM + ctile;
        *(float4*)p = make_float4(acc[i][0], acc[i][1], acc[i][2], acc[i][3]);
        *(float4*)(p + 4) = make_float4(acc[i][4], acc[i][5], acc[i][6], acc[i][7]);
    }
}

// GEMM3: aligned_image[b,c,m] = sum_n A[l,n]*T[n,m],  A[l,n]=text[b,n,c]
// thread-tile rows = l (ty), cols = m (tx)
__global__ void k_gemm3_image(const float* __restrict__ text,
                              float* __restrict__ out_img) {
    __shared__ float As[BK][BM];  // A: [dn][l]
    __shared__ float Bs[BK][BN];  // T: [dn][m]
    const int tid = threadIdx.x;
    const int ty = tid >> 4, tx = tid & 15;
    const int m0 = blockIdx.x * BN;   // 72 tiles
    const int l0 = blockIdx.y * BM;   // 16 tiles
    const int bb = l0 >> 8, cc0 = l0 & 255;
    float acc[8][8] = {};
    for (int kt = 0; kt < N_TOK; kt += BK) {
#pragma unroll
        for (int it = 0; it < 2; ++it) {
            int lin = tid + it * 256;
            int dn = lin >> 5, q = lin & 31;
            float4 v = *(const float4*)(text + (size_t)bb * TEXT_B_STRIDE +
                                        (size_t)(kt + dn) * C_DIM + cc0 + q * 4);
            *(float4*)&As[dn][q * 4] = v;
        }
#pragma unroll
        for (int it = 0; it < 2; ++it) {
            int lin = tid + it * 256;
            int dn = lin >> 5, q = lin & 31;
            float4 v = *(const float4*)(g_cost + (size_t)(kt + dn) * M_PIX + m0 + q * 4);
            *(float4*)&Bs[dn][q * 4] = v;
        }
        __syncthreads();
#pragma unroll
        for (int k = 0; k < BK; ++k) {
            float ra[8], rb[8];
#pragma unroll
            for (int i = 0; i < 8; ++i) ra[i] = As[k][ty * 8 + i];
#pragma unroll
            for (int j = 0; j < 8; ++j) rb[j] = Bs[k][tx * 8 + j];
#pragma unroll
            for (int i = 0; i < 8; ++i)
#pragma unroll
                for (int j = 0; j < 8; ++j)
                    acc[i][j] = fmaf(ra[i], rb[j], acc[i][j]);
        }
        __syncthreads();
    }
#pragma unroll
    for (int i = 0; i < 8; ++i) {
        int c = cc0 + ty * 8 + i;
        float* p = out_img + (size_t)bb * IMG_B_STRIDE + (size_t)c * M_PIX + m0 + tx * 8;
        *(float4*)p = make_float4(acc[i][0], acc[i][1], acc[i][2], acc[i][3]);
        *(float4*)(p + 4) = make_float4(acc[i][4], acc[i][5], acc[i][6], acc[i][7]);
    }
}

// ---------------- launch ----------------
extern "C" void kernel_launch(void* const* d_in, const int* in_sizes, int n_in,
                              void* d_out, int out_size) {
    const float* text  = (const float*)d_in[0];   // [8,1024,256]
    const float* image = (const float*)d_in[1];   // [8,256,96,96]
    float* out_text = (float*)d_out;                       // [8,1024,256]
    float* out_img  = out_text + (size_t)B_DIM * N_TOK * C_DIM;  // [8,256,96,96]

    k_init<<<36, 256>>>();
    k_sq_text<<<N_TOK, 256>>>(text);
    k_sq_image<<<dim3(M_PIX / 256, L_DIM / 256), 256>>>(image);
    k_gemm1_cost<<<dim3(M_PIX / BN, N_TOK / BM), 256>>>(text, image);
    k_sinkhorn<<<148, 256>>>();
    k_make_T<<<dim3(M_PIX / 256, N_TOK), 256>>>();
    k_gemm2_text<<<dim3(L_DIM / BN, N_TOK / BM), 256>>>(image, out_text);
    k_gemm3_image<<<dim3(M_PIX / BN, L_DIM / BM), 256>>>(text, out_img);
}

// round 7
// speedup vs baseline: 1.9671x; 1.9671x over previous
#include <cuda_runtime.h>
#include <cuda_bf16.h>
#include <cstdint>

// ---------------- problem dims ----------------
#define B_DIM 8
#define C_DIM 256
#define N_TOK 1024
#define M_PIX 9216
#define L_DIM 2048
#define TEXT_B_STRIDE  262144    // 1024*256
#define IMG_B_STRIDE   2359296   // 256*9216

#define NITER 50
#define CONV_TOL_SQ 1e-4f
#define DENOM_SHIFT 100.0f

// ---------------- device scratch (statics; no mallocs) ----------------
__device__ float g_cost[(size_t)N_TOK * M_PIX];  // 37.75 MB
__device__ float g_sqA[N_TOK];
__device__ float g_sqB[M_PIX];
__device__ float g_u[N_TOK];
__device__ float g_v[M_PIX];
__device__ float g_normU[64];
__device__ float g_normV[64];
__device__ unsigned g_bar_count;
__device__ unsigned g_bar_gen;

// split-bf16 operand buffers (K-major, hi/lo)
__device__ __nv_bfloat16 g_tA1h[(size_t)N_TOK * L_DIM];  // text  [n][l]
__device__ __nv_bfloat16 g_tA1l[(size_t)N_TOK * L_DIM];
__device__ __nv_bfloat16 g_tA3h[(size_t)L_DIM * N_TOK];  // text  [l][n]
__device__ __nv_bfloat16 g_tA3l[(size_t)L_DIM * N_TOK];
__device__ __nv_bfloat16 g_iB1h[(size_t)M_PIX * L_DIM];  // image [m][l]
__device__ __nv_bfloat16 g_iB1l[(size_t)M_PIX * L_DIM];
__device__ __nv_bfloat16 g_iB2h[(size_t)L_DIM * M_PIX];  // image [l][m]
__device__ __nv_bfloat16 g_iB2l[(size_t)L_DIM * M_PIX];
__device__ __nv_bfloat16 g_T2h[(size_t)N_TOK * M_PIX];   // T [n][m]
__device__ __nv_bfloat16 g_T2l[(size_t)N_TOK * M_PIX];
__device__ __nv_bfloat16 g_T3h[(size_t)M_PIX * N_TOK];   // T [m][n]
__device__ __nv_bfloat16 g_T3l[(size_t)M_PIX * N_TOK];

// ---------------- helpers ----------------
__device__ __forceinline__ uint32_t smem_to_u32(const void* p) {
    uint32_t a;
    asm("{ .reg .u64 t; cvta.to.shared.u64 t, %1; cvt.u32.u64 %0, t; }" : "=r"(a) : "l"(p));
    return a;
}

// ldmatrix x4 (sm_75+; base-target safe)
__device__ __forceinline__ void ldsm_x4(uint32_t* r, uint32_t a) {
    asm volatile("ldmatrix.sync.aligned.m8n8.x4.shared.b16 {%0,%1,%2,%3}, [%4];"
                 : "=r"(r[0]), "=r"(r[1]), "=r"(r[2]), "=r"(r[3]) : "r"(a));
}
// bf16 mma.sync (sm_80+; base-target safe)
__device__ __forceinline__ void mma_bf16(float* c, const uint32_t* a, const uint32_t* b) {
    asm volatile(
        "mma.sync.aligned.m16n8k16.row.col.f32.bf16.bf16.f32 "
        "{%0,%1,%2,%3}, {%4,%5,%6,%7}, {%8,%9}, {%0,%1,%2,%3};"
        : "+f"(c[0]), "+f"(c[1]), "+f"(c[2]), "+f"(c[3])
        : "r"(a[0]), "r"(a[1]), "r"(a[2]), "r"(a[3]), "r"(b[0]), "r"(b[1]));
}

// ---------------- init ----------------
__global__ void k_init() {
    int tid = blockIdx.x * blockDim.x + threadIdx.x;
    if (tid < N_TOK) g_u[tid] = 1.0f;
    if (tid < M_PIX) { g_v[tid] = 1.0f; g_sqB[tid] = 0.0f; }
    if (tid < 64) { g_normU[tid] = 0.0f; g_normV[tid] = 0.0f; }
    if (tid == 0) { g_bar_count = 0u; g_bar_gen = 0u; }
}

// ---------------- squared norms ----------------
__global__ void k_sq_text(const float* __restrict__ text) {
    __shared__ float sh[256];
    int n = blockIdx.x, c = threadIdx.x;
    float s = 0.0f;
#pragma unroll
    for (int b = 0; b < B_DIM; ++b) {
        float x = text[(size_t)b * TEXT_B_STRIDE + (size_t)n * C_DIM + c];
        s += x * x;
    }
    sh[c] = s; __syncthreads();
    for (int off = 128; off > 0; off >>= 1) {
        if (c < off) sh[c] += sh[c + off];
        __syncthreads();
    }
    if (c == 0) g_sqA[n] = sh[0];
}

__global__ void k_sq_image(const float* __restrict__ image) {
    int m = blockIdx.x * 256 + threadIdx.x;
    int l0 = blockIdx.y * 256;
    float s = 0.0f;
    for (int l = l0; l < l0 + 256; ++l) {
        float x = image[(size_t)l * M_PIX + m];
        s += x * x;
    }
    atomicAdd(&g_sqB[m], s);
}

// ---------------- split helpers ----------------
__device__ __forceinline__ void split_bf(float x, __nv_bfloat16& h, __nv_bfloat16& l) {
    h = __float2bfloat16_rn(x);
    l = __float2bfloat16_rn(x - __bfloat162float(h));
}

// ---------------- pack kernels (tiled smem transposes) ----------------
__global__ void k_pack_text(const float* __restrict__ text) {
    __shared__ float t[32][33];
    int b = blockIdx.z, n0 = blockIdx.y * 32, c0 = blockIdx.x * 32;
    int tx = threadIdx.x, ty = threadIdx.y;
    for (int i = ty; i < 32; i += 8)
        t[i][tx] = text[(size_t)b * TEXT_B_STRIDE + (size_t)(n0 + i) * C_DIM + c0 + tx];
    __syncthreads();
    for (int i = ty; i < 32; i += 8) {
        __nv_bfloat16 h, l; split_bf(t[i][tx], h, l);
        size_t o = (size_t)(n0 + i) * L_DIM + b * C_DIM + c0 + tx;
        g_tA1h[o] = h; g_tA1l[o] = l;
    }
    for (int i = ty; i < 32; i += 8) {
        __nv_bfloat16 h, l; split_bf(t[tx][i], h, l);
        size_t o = (size_t)(b * C_DIM + c0 + i) * N_TOK + n0 + tx;
        g_tA3h[o] = h; g_tA3l[o] = l;
    }
}

__global__ void k_pack_image(const float* __restrict__ image) {
    __shared__ float t[32][33];
    int l0 = blockIdx.y * 32, m0 = blockIdx.x * 32;
    int tx = threadIdx.x, ty = threadIdx.y;
    for (int i = ty; i < 32; i += 8)
        t[i][tx] = image[(size_t)(l0 + i) * M_PIX + m0 + tx];
    __syncthreads();
    for (int i = ty; i < 32; i += 8) {
        __nv_bfloat16 h, l; split_bf(t[i][tx], h, l);
        size_t o = (size_t)(l0 + i) * M_PIX + m0 + tx;
        g_iB2h[o] = h; g_iB2l[o] = l;
    }
    for (int i = ty; i < 32; i += 8) {
        __nv_bfloat16 h, l; split_bf(t[tx][i], h, l);
        size_t o = (size_t)(m0 + i) * L_DIM + l0 + tx;
        g_iB1h[o] = h; g_iB1l[o] = l;
    }
}

__global__ void k_pack_T() {
    __shared__ float t[32][33];
    int n0 = blockIdx.y * 32, m0 = blockIdx.x * 32;
    int tx = threadIdx.x, ty = threadIdx.y;
    for (int i = ty; i < 32; i += 8) {
        float c = g_cost[(size_t)(n0 + i) * M_PIX + m0 + tx];
        t[i][tx] = expf(-0.1f * c) * g_u[n0 + i] * g_v[m0 + tx];
    }
    __syncthreads();
    for (int i = ty; i < 32; i += 8) {
        __nv_bfloat16 h, l; split_bf(t[i][tx], h, l);
        size_t o = (size_t)(n0 + i) * M_PIX + m0 + tx;
        g_T2h[o] = h; g_T2l[o] = l;
    }
    for (int i = ty; i < 32; i += 8) {
        __nv_bfloat16 h, l; split_bf(t[tx][i], h, l);
        size_t o = (size_t)(m0 + i) * N_TOK + n0 + tx;
        g_T3h[o] = h; g_T3l[o] = l;
    }
}

// ---------------- mma.sync GEMM: 128x64 CTA tile, BK=32, split-bf16 ----------------
// rows = blockIdx.y*128 (operand A, [row][k]); cols = blockIdx.x*64 (operand B, [col][k])
// ID 0: cost  = tA1[n][l] x iB1[m][l], K=2048, sqrt epilogue -> g_cost
// ID 1: textO = T2 [n][m] x iB2[l][m], K=9216 -> out_text[b][n][c]
// ID 2: imgO  = tA3[l][n] x T3 [m][n], K=1024 -> out_img[l][m]
#define SPAD 40   // 32 + 8 pad (80B row stride: conflict-free ldmatrix)

template <int ID>
__global__ void __launch_bounds__(256, 2) k_mma_gemm(float* __restrict__ out) {
    const __nv_bfloat16 *Ah_, *Al_, *Bh_, *Bl_;
    int Ktot;
    if (ID == 0) { Ah_ = g_tA1h; Al_ = g_tA1l; Bh_ = g_iB1h; Bl_ = g_iB1l; Ktot = L_DIM; }
    else if (ID == 1) { Ah_ = g_T2h; Al_ = g_T2l; Bh_ = g_iB2h; Bl_ = g_iB2l; Ktot = M_PIX; }
    else { Ah_ = g_tA3h; Al_ = g_tA3l; Bh_ = g_T3h; Bl_ = g_T3l; Ktot = N_TOK; }

    __shared__ __nv_bfloat16 sAh[128 * SPAD], sAl[128 * SPAD];
    __shared__ __nv_bfloat16 sBh[64 * SPAD],  sBl[64 * SPAD];

    const int tid = threadIdx.x, wid = tid >> 5, lane = tid & 31;
    const int wy = wid >> 1, wx = wid & 1;            // warp grid 4x2, warp tile 32x32
    const int row0 = blockIdx.y * 128, col0 = blockIdx.x * 64;

    float acc[2][4][4] = {};   // [mt][nt][frag]

    // ldmatrix per-lane source coordinates
    const int a_r = lane & 15, a_c = (lane >> 4) << 3;
    const int b_r = (lane & 7) + (((lane >> 4) & 1) << 3), b_c = ((lane >> 3) & 1) << 3;
    const uint32_t sAh_b = smem_to_u32(sAh), sAl_b = smem_to_u32(sAl);
    const uint32_t sBh_b = smem_to_u32(sBh), sBl_b = smem_to_u32(sBl);

    for (int k0 = 0; k0 < Ktot; k0 += 32) {
        // global -> smem: A 128x32 (hi/lo), B 64x32 (hi/lo), 16B chunks
#pragma unroll
        for (int i = 0; i < 2; ++i) {
            int idx = tid + (i << 8);
            int r = idx >> 2, c = (idx & 3) << 3;
            size_t g = (size_t)(row0 + r) * Ktot + k0 + c;
            *(uint4*)(&sAh[r * SPAD + c]) = *(const uint4*)(Ah_ + g);
            *(uint4*)(&sAl[r * SPAD + c]) = *(const uint4*)(Al_ + g);
        }
        {
            int r = tid >> 2, c = (tid & 3) << 3;
            size_t g = (size_t)(col0 + r) * Ktot + k0 + c;
            *(uint4*)(&sBh[r * SPAD + c]) = *(const uint4*)(Bh_ + g);
            *(uint4*)(&sBl[r * SPAD + c]) = *(const uint4*)(Bl_ + g);
        }
        __syncthreads();
#pragma unroll
        for (int kk = 0; kk < 2; ++kk) {
            uint32_t ah[2][4], al[2][4], bh[2][4], bl[2][4];
#pragma unroll
            for (int mt = 0; mt < 2; ++mt) {
                uint32_t off = (uint32_t)((wy * 32 + mt * 16 + a_r) * SPAD + kk * 16 + a_c) * 2;
                ldsm_x4(ah[mt], sAh_b + off);
                ldsm_x4(al[mt], sAl_b + off);
            }
#pragma unroll
            for (int p = 0; p < 2; ++p) {
                uint32_t off = (uint32_t)((wx * 32 + p * 16 + b_r) * SPAD + kk * 16 + b_c) * 2;
                ldsm_x4(bh[p], sBh_b + off);
                ldsm_x4(bl[p], sBl_b + off);
            }
#pragma unroll
            for (int mt = 0; mt < 2; ++mt)
#pragma unroll
                for (int nt = 0; nt < 4; ++nt) {
                    const uint32_t bhi[2] = { bh[nt >> 1][(nt & 1) * 2],
                                              bh[nt >> 1][(nt & 1) * 2 + 1] };
                    const uint32_t blo[2] = { bl[nt >> 1][(nt & 1) * 2],
                                              bl[nt >> 1][(nt & 1) * 2 + 1] };
                    mma_bf16(acc[mt][nt], ah[mt], bhi);   // Ah*Bh
                    mma_bf16(acc[mt][nt], ah[mt], blo);   // Ah*Bl
                    mma_bf16(acc[mt][nt], al[mt], bhi);   // Al*Bh
                }
        }
        __syncthreads();
    }

    // ---------------- epilogue ----------------
    const int rbase = row0 + wy * 32 + (lane >> 2);
    const int cbase = col0 + wx * 32 + ((lane & 3) << 1);
#pragma unroll
    for (int mt = 0; mt < 2; ++mt) {
        int rA = rbase + mt * 16, rB = rA + 8;
#pragma unroll
        for (int nt = 0; nt < 4; ++nt) {
            int cc = cbase + nt * 8;
            float d0 = acc[mt][nt][0], d1 = acc[mt][nt][1];
            float d2 = acc[mt][nt][2], d3 = acc[mt][nt][3];
            if (ID == 0) {
                float sb0 = g_sqB[cc], sb1 = g_sqB[cc + 1];
                float saA = g_sqA[rA], saB = g_sqA[rB];
                float2 oA, oB;
                oA.x = sqrtf(fmaxf(saA + sb0 - 2.0f * d0, 1e-12f));
                oA.y = sqrtf(fmaxf(saA + sb1 - 2.0f * d1, 1e-12f));
                oB.x = sqrtf(fmaxf(saB + sb0 - 2.0f * d2, 1e-12f));
                oB.y = sqrtf(fmaxf(saB + sb1 - 2.0f * d3, 1e-12f));
                *(float2*)(g_cost + (size_t)rA * M_PIX + cc) = oA;
                *(float2*)(g_cost + (size_t)rB * M_PIX + cc) = oB;
            } else if (ID == 1) {
                int b = cc >> 8, c = cc & 255;   // col = l
                float* pA = out + (size_t)b * TEXT_B_STRIDE + (size_t)rA * C_DIM + c;
                float* pB = out + (size_t)b * TEXT_B_STRIDE + (size_t)rB * C_DIM + c;
                *(float2*)pA = make_float2(d0, d1);
                *(float2*)pB = make_float2(d2, d3);
            } else {
                *(float2*)(out + (size_t)rA * M_PIX + cc) = make_float2(d0, d1);
                *(float2*)(out + (size_t)rB * M_PIX + cc) = make_float2(d2, d3);
            }
        }
    }
}

// ---------------- Sinkhorn (persistent kernel, honest convergence break) ----------------
__device__ __forceinline__ void grid_barrier(unsigned e, int nctas) {
    __syncthreads();
    if (threadIdx.x == 0) {
        __threadfence();
        unsigned t = atomicAdd(&g_bar_count, 1u) + 1u;
        if (t == (unsigned)nctas * e) {
            atomicExch(&g_bar_gen, e);
        } else {
            while (*((volatile unsigned*)&g_bar_gen) < e) __nanosleep(64);
        }
        __threadfence();
    }
    __syncthreads();
}

__global__ void k_sinkhorn() {
    __shared__ float sred[256];
    const int cta = blockIdx.x;
    const int tid = threadIdx.x;
    const int NC = gridDim.x;
    unsigned epoch = 0;
    for (int it = 0; it < NITER; ++it) {
        for (int n = cta; n < N_TOK; n += NC) {
            const float* row = g_cost + (size_t)n * M_PIX;
            float s = 0.0f;
            for (int m = tid; m < M_PIX; m += 256)
                s += __expf(-10.0f * row[m]) * __ldcg(&g_v[m]);
            sred[tid] = s; __syncthreads();
            for (int off = 128; off > 0; off >>= 1) {
                if (tid < off) sred[tid] += sred[tid + off];
                __syncthreads();
            }
            if (tid == 0) {
                float un = 1.0f / (sred[0] + DENOM_SHIFT);
                float d = un - g_u[n];
                atomicAdd(&g_normU[it], d * d);
                g_u[n] = un;
            }
            __syncthreads();
        }
        ++epoch; grid_barrier(epoch, NC);
        for (int blk = cta; blk < (M_PIX / 64); blk += NC) {
            int col0 = blk * 64;
            int c = tid & 63, sl = tid >> 6;
            float t = 0.0f;
            for (int n = sl; n < N_TOK; n += 4)
                t += __expf(-10.0f * g_cost[(size_t)n * M_PIX + col0 + c]) * __ldcg(&g_u[n]);
            sred[tid] = t; __syncthreads();
            if (tid < 64) {
                float tt = sred[tid] + sred[tid + 64] + sred[tid + 128] + sred[tid + 192];
                int m = col0 + tid;
                float vn = 1.0f / (tt + DENOM_SHIFT);
                float d = vn - g_v[m];
                atomicAdd(&g_normV[it], d * d);
                g_v[m] = vn;
            }
            __syncthreads();
        }
        ++epoch; grid_barrier(epoch, NC);
        float nu = __ldcg(&g_normU[it]);
        float nv = __ldcg(&g_normV[it]);
        if (nu < CONV_TOL_SQ && nv < CONV_TOL_SQ) break;
    }
}

// ---------------- launch ----------------
extern "C" void kernel_launch(void* const* d_in, const int* in_sizes, int n_in,
                              void* d_out, int out_size) {
    const float* text  = (const float*)d_in[0];
    const float* image = (const float*)d_in[1];
    float* out_text = (float*)d_out;
    float* out_img  = out_text + (size_t)B_DIM * N_TOK * C_DIM;

    k_init<<<36, 256>>>();
    k_sq_text<<<N_TOK, 256>>>(text);
    k_sq_image<<<dim3(M_PIX / 256, L_DIM / 256), 256>>>(image);
    k_pack_text<<<dim3(C_DIM / 32, N_TOK / 32, B_DIM), dim3(32, 8)>>>(text);
    k_pack_image<<<dim3(M_PIX / 32, L_DIM / 32), dim3(32, 8)>>>(image);

    // GEMM1: cost (rows n: 8, cols m: 144)
    k_mma_gemm<0><<<dim3(M_PIX / 64, N_TOK / 128), 256>>>(nullptr);

    k_sinkhorn<<<148, 256>>>();
    k_pack_T<<<dim3(M_PIX / 32, N_TOK / 32), dim3(32, 8)>>>();

    // GEMM2: out_text (rows n: 8, cols l: 32)
    k_mma_gemm<1><<<dim3(L_DIM / 64, N_TOK / 128), 256>>>(out_text);
    // GEMM3: out_img (rows l: 16, cols m: 144)
    k_mma_gemm<2><<<dim3(M_PIX / 64, L_DIM / 128), 256>>>(out_img);
}

// round 8
// speedup vs baseline: 2.1027x; 1.0689x over previous
#include <cuda_runtime.h>
#include <cuda_bf16.h>
#include <cstdint>

// ---------------- problem dims ----------------
#define B_DIM 8
#define C_DIM 256
#define N_TOK 1024
#define M_PIX 9216
#define L_DIM 2048
#define TEXT_B_STRIDE  262144    // 1024*256
#define IMG_B_STRIDE   2359296   // 256*9216

#define NITER 50
#define CONV_TOL_SQ 1e-4f
#define DENOM_SHIFT 100.0f

// ---------------- device scratch (statics; no mallocs) ----------------
__device__ float g_cost[(size_t)N_TOK * M_PIX];  // 37.75 MB
__device__ float g_sqA[N_TOK];
__device__ float g_sqB[M_PIX];
__device__ float g_u[N_TOK];
__device__ float g_v[M_PIX];
__device__ float g_normU[64];
__device__ float g_normV[64];
__device__ unsigned g_bar_count;
__device__ unsigned g_bar_gen;

// split-bf16 operand buffers (K-major, hi/lo)
__device__ __nv_bfloat16 g_tA1h[(size_t)N_TOK * L_DIM];  // text  [n][l]
__device__ __nv_bfloat16 g_tA1l[(size_t)N_TOK * L_DIM];
__device__ __nv_bfloat16 g_tA3h[(size_t)L_DIM * N_TOK];  // text  [l][n]
__device__ __nv_bfloat16 g_tA3l[(size_t)L_DIM * N_TOK];
__device__ __nv_bfloat16 g_iB1h[(size_t)M_PIX * L_DIM];  // image [m][l]
__device__ __nv_bfloat16 g_iB1l[(size_t)M_PIX * L_DIM];
__device__ __nv_bfloat16 g_iB2h[(size_t)L_DIM * M_PIX];  // image [l][m]
__device__ __nv_bfloat16 g_iB2l[(size_t)L_DIM * M_PIX];
__device__ __nv_bfloat16 g_T2h[(size_t)N_TOK * M_PIX];   // T [n][m]
__device__ __nv_bfloat16 g_T2l[(size_t)N_TOK * M_PIX];
__device__ __nv_bfloat16 g_T3h[(size_t)M_PIX * N_TOK];   // T [m][n]
__device__ __nv_bfloat16 g_T3l[(size_t)M_PIX * N_TOK];

// ---------------- helpers ----------------
__device__ __forceinline__ uint32_t smem_to_u32(const void* p) {
    uint32_t a;
    asm("{ .reg .u64 t; cvta.to.shared.u64 t, %1; cvt.u32.u64 %0, t; }" : "=r"(a) : "l"(p));
    return a;
}
__device__ __forceinline__ void ldsm_x4(uint32_t* r, uint32_t a) {
    asm volatile("ldmatrix.sync.aligned.m8n8.x4.shared.b16 {%0,%1,%2,%3}, [%4];"
                 : "=r"(r[0]), "=r"(r[1]), "=r"(r[2]), "=r"(r[3]) : "r"(a));
}
__device__ __forceinline__ void mma_bf16(float* c, const uint32_t* a, const uint32_t* b) {
    asm volatile(
        "mma.sync.aligned.m16n8k16.row.col.f32.bf16.bf16.f32 "
        "{%0,%1,%2,%3}, {%4,%5,%6,%7}, {%8,%9}, {%0,%1,%2,%3};"
        : "+f"(c[0]), "+f"(c[1]), "+f"(c[2]), "+f"(c[3])
        : "r"(a[0]), "r"(a[1]), "r"(a[2]), "r"(a[3]), "r"(b[0]), "r"(b[1]));
}
__device__ __forceinline__ void cp16(uint32_t dst, const void* src) {
    asm volatile("cp.async.cg.shared.global [%0], [%1], 16;" :: "r"(dst), "l"(src));
}
__device__ __forceinline__ void cp_commit() {
    asm volatile("cp.async.commit_group;" ::: "memory");
}
template <int N>
__device__ __forceinline__ void cp_wait() {
    asm volatile("cp.async.wait_group %0;" :: "n"(N) : "memory");
}

// ---------------- init ----------------
__global__ void k_init() {
    int tid = blockIdx.x * blockDim.x + threadIdx.x;
    if (tid < N_TOK) g_u[tid] = 1.0f;
    if (tid < M_PIX) { g_v[tid] = 1.0f; g_sqB[tid] = 0.0f; }
    if (tid < 64) { g_normU[tid] = 0.0f; g_normV[tid] = 0.0f; }
    if (tid == 0) { g_bar_count = 0u; g_bar_gen = 0u; }
}

// ---------------- squared norms ----------------
__global__ void k_sq_text(const float* __restrict__ text) {
    __shared__ float sh[256];
    int n = blockIdx.x, c = threadIdx.x;
    float s = 0.0f;
#pragma unroll
    for (int b = 0; b < B_DIM; ++b) {
        float x = text[(size_t)b * TEXT_B_STRIDE + (size_t)n * C_DIM + c];
        s += x * x;
    }
    sh[c] = s; __syncthreads();
    for (int off = 128; off > 0; off >>= 1) {
        if (c < off) sh[c] += sh[c + off];
        __syncthreads();
    }
    if (c == 0) g_sqA[n] = sh[0];
}

__global__ void k_sq_image(const float* __restrict__ image) {
    int m = blockIdx.x * 256 + threadIdx.x;
    int l0 = blockIdx.y * 256;
    float s = 0.0f;
    for (int l = l0; l < l0 + 256; ++l) {
        float x = image[(size_t)l * M_PIX + m];
        s += x * x;
    }
    atomicAdd(&g_sqB[m], s);
}

// ---------------- split helpers ----------------
__device__ __forceinline__ void split_bf(float x, __nv_bfloat16& h, __nv_bfloat16& l) {
    h = __float2bfloat16_rn(x);
    l = __float2bfloat16_rn(x - __bfloat162float(h));
}

// ---------------- pack kernels (tiled smem transposes) ----------------
__global__ void k_pack_text(const float* __restrict__ text) {
    __shared__ float t[32][33];
    int b = blockIdx.z, n0 = blockIdx.y * 32, c0 = blockIdx.x * 32;
    int tx = threadIdx.x, ty = threadIdx.y;
    for (int i = ty; i < 32; i += 8)
        t[i][tx] = text[(size_t)b * TEXT_B_STRIDE + (size_t)(n0 + i) * C_DIM + c0 + tx];
    __syncthreads();
    for (int i = ty; i < 32; i += 8) {
        __nv_bfloat16 h, l; split_bf(t[i][tx], h, l);
        size_t o = (size_t)(n0 + i) * L_DIM + b * C_DIM + c0 + tx;
        g_tA1h[o] = h; g_tA1l[o] = l;
    }
    for (int i = ty; i < 32; i += 8) {
        __nv_bfloat16 h, l; split_bf(t[tx][i], h, l);
        size_t o = (size_t)(b * C_DIM + c0 + i) * N_TOK + n0 + tx;
        g_tA3h[o] = h; g_tA3l[o] = l;
    }
}

__global__ void k_pack_image(const float* __restrict__ image) {
    __shared__ float t[32][33];
    int l0 = blockIdx.y * 32, m0 = blockIdx.x * 32;
    int tx = threadIdx.x, ty = threadIdx.y;
    for (int i = ty; i < 32; i += 8)
        t[i][tx] = image[(size_t)(l0 + i) * M_PIX + m0 + tx];
    __syncthreads();
    for (int i = ty; i < 32; i += 8) {
        __nv_bfloat16 h, l; split_bf(t[i][tx], h, l);
        size_t o = (size_t)(l0 + i) * M_PIX + m0 + tx;
        g_iB2h[o] = h; g_iB2l[o] = l;
    }
    for (int i = ty; i < 32; i += 8) {
        __nv_bfloat16 h, l; split_bf(t[tx][i], h, l);
        size_t o = (size_t)(m0 + i) * L_DIM + l0 + tx;
        g_iB1h[o] = h; g_iB1l[o] = l;
    }
}

__global__ void k_pack_T() {
    __shared__ float t[32][33];
    int n0 = blockIdx.y * 32, m0 = blockIdx.x * 32;
    int tx = threadIdx.x, ty = threadIdx.y;
    for (int i = ty; i < 32; i += 8) {
        float c = g_cost[(size_t)(n0 + i) * M_PIX + m0 + tx];
        t[i][tx] = expf(-0.1f * c) * g_u[n0 + i] * g_v[m0 + tx];
    }
    __syncthreads();
    for (int i = ty; i < 32; i += 8) {
        __nv_bfloat16 h, l; split_bf(t[i][tx], h, l);
        size_t o = (size_t)(n0 + i) * M_PIX + m0 + tx;
        g_T2h[o] = h; g_T2l[o] = l;
    }
    for (int i = ty; i < 32; i += 8) {
        __nv_bfloat16 h, l; split_bf(t[tx][i], h, l);
        size_t o = (size_t)(m0 + i) * N_TOK + n0 + tx;
        g_T3h[o] = h; g_T3l[o] = l;
    }
}

// ---------------- mma.sync GEMM: 128x128 CTA tile, BK=32, cp.async double-buffered ----------------
// rows = blockIdx.y*128 (A, [row][k]); cols = blockIdx.x*128 (B, [col][k])
// ID 0: cost  = tA1[n][l] x iB1[m][l], K=2048, sqrt epilogue -> g_cost
// ID 1: textO = T2 [n][m] x iB2[l][m], K=9216 -> out_text[b][n][c]
// ID 2: imgO  = tA3[l][n] x T3 [m][n], K=1024 -> out_img[l][m]
#define SPAD 40                      // 32 + 8 pad (80B row stride: conflict-free ldmatrix)
#define TILE_BYTES (128 * SPAD * 2)  // 10240 per operand array
#define OFF_AH 0
#define OFF_AL (TILE_BYTES)
#define OFF_BH (2 * TILE_BYTES)
#define OFF_BL (3 * TILE_BYTES)
#define STAGE_BYTES (4 * TILE_BYTES) // 40960
#define SMEM_TOTAL_GEMM (2 * STAGE_BYTES)

template <int ID>
__global__ void __launch_bounds__(256, 1) k_mma_gemm(float* __restrict__ out) {
    extern __shared__ char sm[];
    const __nv_bfloat16 *Ah_, *Al_, *Bh_, *Bl_;
    int Ktot;
    if (ID == 0) { Ah_ = g_tA1h; Al_ = g_tA1l; Bh_ = g_iB1h; Bl_ = g_iB1l; Ktot = L_DIM; }
    else if (ID == 1) { Ah_ = g_T2h; Al_ = g_T2l; Bh_ = g_iB2h; Bl_ = g_iB2l; Ktot = M_PIX; }
    else { Ah_ = g_tA3h; Al_ = g_tA3l; Bh_ = g_T3h; Bl_ = g_T3l; Ktot = N_TOK; }

    const int tid = threadIdx.x, wid = tid >> 5, lane = tid & 31;
    const int wy = wid >> 1, wx = wid & 1;   // warp grid 4x2; warp tile 32(rows) x 64(cols)
    const int row0 = blockIdx.y * 128, col0 = blockIdx.x * 128;
    const uint32_t smb = smem_to_u32(sm);

    float acc[2][8][4] = {};   // [mt][nt][frag]

    // per-thread load coords (shared by A and B tiles: 512 16B-chunks each)
    const int ld_r = tid >> 2, ld_c = (tid & 3) << 3;

    // ldmatrix per-lane coords (same mapping as Round 7 — verified correct)
    const int a_r = lane & 15, a_c = (lane >> 4) << 3;
    const int b_r = (lane & 7) + (((lane >> 4) & 1) << 3), b_c = ((lane >> 3) & 1) << 3;

    const int KCH = Ktot >> 5;

    auto issue = [&](int kc, int buf) {
        const int k0 = kc << 5;
        const uint32_t sb = smb + buf * STAGE_BYTES;
#pragma unroll
        for (int i = 0; i < 2; ++i) {
            int r = ld_r + i * 64;
            uint32_t so = (uint32_t)(r * SPAD + ld_c) * 2;
            size_t ga = (size_t)(row0 + r) * Ktot + k0 + ld_c;
            size_t gb = (size_t)(col0 + r) * Ktot + k0 + ld_c;
            cp16(sb + OFF_AH + so, Ah_ + ga);
            cp16(sb + OFF_AL + so, Al_ + ga);
            cp16(sb + OFF_BH + so, Bh_ + gb);
            cp16(sb + OFF_BL + so, Bl_ + gb);
        }
        cp_commit();
    };

    issue(0, 0);
    for (int kc = 0; kc < KCH; ++kc) {
        const int cur = kc & 1;
        if (kc + 1 < KCH) { issue(kc + 1, cur ^ 1); cp_wait<1>(); }
        else              { cp_wait<0>(); }
        __syncthreads();
        const uint32_t sb = smb + cur * STAGE_BYTES;
#pragma unroll
        for (int kk = 0; kk < 2; ++kk) {
            uint32_t ah[2][4], al[2][4], bh[4][4], bl[4][4];
#pragma unroll
            for (int mt = 0; mt < 2; ++mt) {
                uint32_t off = (uint32_t)((wy * 32 + mt * 16 + a_r) * SPAD + kk * 16 + a_c) * 2;
                ldsm_x4(ah[mt], sb + OFF_AH + off);
                ldsm_x4(al[mt], sb + OFF_AL + off);
            }
#pragma unroll
            for (int p = 0; p < 4; ++p) {
                uint32_t off = (uint32_t)((wx * 64 + p * 16 + b_r) * SPAD + kk * 16 + b_c) * 2;
                ldsm_x4(bh[p], sb + OFF_BH + off);
                ldsm_x4(bl[p], sb + OFF_BL + off);
            }
#pragma unroll
            for (int mt = 0; mt < 2; ++mt)
#pragma unroll
                for (int nt = 0; nt < 8; ++nt) {
                    const uint32_t bhi[2] = { bh[nt >> 1][(nt & 1) * 2],
                                              bh[nt >> 1][(nt & 1) * 2 + 1] };
                    const uint32_t blo[2] = { bl[nt >> 1][(nt & 1) * 2],
                                              bl[nt >> 1][(nt & 1) * 2 + 1] };
                    mma_bf16(acc[mt][nt], ah[mt], bhi);   // Ah*Bh
                    mma_bf16(acc[mt][nt], ah[mt], blo);   // Ah*Bl
                    mma_bf16(acc[mt][nt], al[mt], bhi);   // Al*Bh
                }
        }
        __syncthreads();
    }

    // ---------------- epilogue ----------------
    const int rbase = row0 + wy * 32 + (lane >> 2);
    const int cbase = col0 + wx * 64 + ((lane & 3) << 1);
#pragma unroll
    for (int mt = 0; mt < 2; ++mt) {
        int rA = rbase + mt * 16, rB = rA + 8;
#pragma unroll
        for (int nt = 0; nt < 8; ++nt) {
            int cc = cbase + nt * 8;
            float d0 = acc[mt][nt][0], d1 = acc[mt][nt][1];
            float d2 = acc[mt][nt][2], d3 = acc[mt][nt][3];
            if (ID == 0) {
                float sb0 = g_sqB[cc], sb1 = g_sqB[cc + 1];
                float saA = g_sqA[rA], saB = g_sqA[rB];
                float2 oA, oB;
                oA.x = sqrtf(fmaxf(saA + sb0 - 2.0f * d0, 1e-12f));
                oA.y = sqrtf(fmaxf(saA + sb1 - 2.0f * d1, 1e-12f));
                oB.x = sqrtf(fmaxf(saB + sb0 - 2.0f * d2, 1e-12f));
                oB.y = sqrtf(fmaxf(saB + sb1 - 2.0f * d3, 1e-12f));
                *(float2*)(g_cost + (size_t)rA * M_PIX + cc) = oA;
                *(float2*)(g_cost + (size_t)rB * M_PIX + cc) = oB;
            } else if (ID == 1) {
                int b = cc >> 8, c = cc & 255;   // col = l
                float* pA = out + (size_t)b * TEXT_B_STRIDE + (size_t)rA * C_DIM + c;
                float* pB = out + (size_t)b * TEXT_B_STRIDE + (size_t)rB * C_DIM + c;
                *(float2*)pA = make_float2(d0, d1);
                *(float2*)pB = make_float2(d2, d3);
            } else {
                *(float2*)(out + (size_t)rA * M_PIX + cc) = make_float2(d0, d1);
                *(float2*)(out + (size_t)rB * M_PIX + cc) = make_float2(d2, d3);
            }
        }
    }
}

// ---------------- Sinkhorn (persistent kernel, honest convergence break) ----------------
__device__ __forceinline__ void grid_barrier(unsigned e, int nctas) {
    __syncthreads();
    if (threadIdx.x == 0) {
        __threadfence();
        unsigned t = atomicAdd(&g_bar_count, 1u) + 1u;
        if (t == (unsigned)nctas * e) {
            atomicExch(&g_bar_gen, e);
        } else {
            while (*((volatile unsigned*)&g_bar_gen) < e) __nanosleep(64);
        }
        __threadfence();
    }
    __syncthreads();
}

__global__ void k_sinkhorn() {
    __shared__ float sred[256];
    const int cta = blockIdx.x;
    const int tid = threadIdx.x;
    const int NC = gridDim.x;
    unsigned epoch = 0;
    for (int it = 0; it < NITER; ++it) {
        for (int n = cta; n < N_TOK; n += NC) {
            const float* row = g_cost + (size_t)n * M_PIX;
            float s = 0.0f;
            for (int m = tid; m < M_PIX; m += 256)
                s += __expf(-10.0f * row[m]) * __ldcg(&g_v[m]);
            sred[tid] = s; __syncthreads();
            for (int off = 128; off > 0; off >>= 1) {
                if (tid < off) sred[tid] += sred[tid + off];
                __syncthreads();
            }
            if (tid == 0) {
                float un = 1.0f / (sred[0] + DENOM_SHIFT);
                float d = un - g_u[n];
                atomicAdd(&g_normU[it], d * d);
                g_u[n] = un;
            }
            __syncthreads();
        }
        ++epoch; grid_barrier(epoch, NC);
        for (int blk = cta; blk < (M_PIX / 64); blk += NC) {
            int col0 = blk * 64;
            int c = tid & 63, sl = tid >> 6;
            float t = 0.0f;
            for (int n = sl; n < N_TOK; n += 4)
                t += __expf(-10.0f * g_cost[(size_t)n * M_PIX + col0 + c]) * __ldcg(&g_u[n]);
            sred[tid] = t; __syncthreads();
            if (tid < 64) {
                float tt = sred[tid] + sred[tid + 64] + sred[tid + 128] + sred[tid + 192];
                int m = col0 + tid;
                float vn = 1.0f / (tt + DENOM_SHIFT);
                float d = vn - g_v[m];
                atomicAdd(&g_normV[it], d * d);
                g_v[m] = vn;
            }
            __syncthreads();
        }
        ++epoch; grid_barrier(epoch, NC);
        float nu = __ldcg(&g_normU[it]);
        float nv = __ldcg(&g_normV[it]);
        if (nu < CONV_TOL_SQ && nv < CONV_TOL_SQ) break;
    }
}

// ---------------- launch ----------------
extern "C" void kernel_launch(void* const* d_in, const int* in_sizes, int n_in,
                              void* d_out, int out_size) {
    const float* text  = (const float*)d_in[0];
    const float* image = (const float*)d_in[1];
    float* out_text = (float*)d_out;
    float* out_img  = out_text + (size_t)B_DIM * N_TOK * C_DIM;

    cudaFuncSetAttribute(k_mma_gemm<0>, cudaFuncAttributeMaxDynamicSharedMemorySize, SMEM_TOTAL_GEMM);
    cudaFuncSetAttribute(k_mma_gemm<1>, cudaFuncAttributeMaxDynamicSharedMemorySize, SMEM_TOTAL_GEMM);
    cudaFuncSetAttribute(k_mma_gemm<2>, cudaFuncAttributeMaxDynamicSharedMemorySize, SMEM_TOTAL_GEMM);

    k_init<<<36, 256>>>();
    k_sq_text<<<N_TOK, 256>>>(text);
    k_sq_image<<<dim3(M_PIX / 256, L_DIM / 256), 256>>>(image);
    k_pack_text<<<dim3(C_DIM / 32, N_TOK / 32, B_DIM), dim3(32, 8)>>>(text);
    k_pack_image<<<dim3(M_PIX / 32, L_DIM / 32), dim3(32, 8)>>>(image);

    // GEMM1: cost (rows n: 8, cols m: 72)
    k_mma_gemm<0><<<dim3(M_PIX / 128, N_TOK / 128), 256, SMEM_TOTAL_GEMM>>>(nullptr);

    k_sinkhorn<<<148, 256>>>();
    k_pack_T<<<dim3(M_PIX / 32, N_TOK / 32), dim3(32, 8)>>>();

    // GEMM2: out_text (rows n: 8, cols l: 16)
    k_mma_gemm<1><<<dim3(L_DIM / 128, N_TOK / 128), 256, SMEM_TOTAL_GEMM>>>(out_text);
    // GEMM3: out_img (rows l: 16, cols m: 72)
    k_mma_gemm<2><<<dim3(M_PIX / 128, L_DIM / 128), 256, SMEM_TOTAL_GEMM>>>(out_img);
}

// round 9
// speedup vs baseline: 2.5742x; 1.2242x over previous
#include <cuda_runtime.h>
#include <cuda_bf16.h>
#include <cstdint>

// ---------------- problem dims ----------------
#define B_DIM 8
#define C_DIM 256
#define N_TOK 1024
#define M_PIX 9216
#define L_DIM 2048
#define TEXT_B_STRIDE  262144    // 1024*256
#define IMG_B_STRIDE   2359296   // 256*9216

#define NITER 50
#define CONV_TOL_SQ 1e-4f
#define DENOM_SHIFT 100.0f

// ---------------- device scratch (statics; no mallocs) ----------------
__device__ float g_cost[(size_t)N_TOK * M_PIX];  // 37.75 MB
__device__ float g_sqA[N_TOK];
__device__ float g_sqB[M_PIX];
__device__ float g_u[N_TOK];
__device__ float g_v[M_PIX];
__device__ float g_normU[64];
__device__ float g_normV[64];
__device__ unsigned g_bar_count;
__device__ unsigned g_bar_gen;

// bf16 operand buffers (K-major). GEMM1 uses hi-only; GEMM2/3 use hi+lo.
__device__ __nv_bfloat16 g_tA1h[(size_t)N_TOK * L_DIM];  // text  [n][l] (hi only)
__device__ __nv_bfloat16 g_iB1h[(size_t)M_PIX * L_DIM];  // image [m][l] (hi only)
__device__ __nv_bfloat16 g_tA3h[(size_t)L_DIM * N_TOK];  // text  [l][n]
__device__ __nv_bfloat16 g_tA3l[(size_t)L_DIM * N_TOK];
__device__ __nv_bfloat16 g_iB2h[(size_t)L_DIM * M_PIX];  // image [l][m]
__device__ __nv_bfloat16 g_iB2l[(size_t)L_DIM * M_PIX];
__device__ __nv_bfloat16 g_T2h[(size_t)N_TOK * M_PIX];   // T [n][m]
__device__ __nv_bfloat16 g_T2l[(size_t)N_TOK * M_PIX];
__device__ __nv_bfloat16 g_T3h[(size_t)M_PIX * N_TOK];   // T [m][n]
__device__ __nv_bfloat16 g_T3l[(size_t)M_PIX * N_TOK];

// ---------------- helpers ----------------
__device__ __forceinline__ uint32_t smem_to_u32(const void* p) {
    uint32_t a;
    asm("{ .reg .u64 t; cvta.to.shared.u64 t, %1; cvt.u32.u64 %0, t; }" : "=r"(a) : "l"(p));
    return a;
}
__device__ __forceinline__ void ldsm_x4(uint32_t* r, uint32_t a) {
    asm volatile("ldmatrix.sync.aligned.m8n8.x4.shared.b16 {%0,%1,%2,%3}, [%4];"
                 : "=r"(r[0]), "=r"(r[1]), "=r"(r[2]), "=r"(r[3]) : "r"(a));
}
__device__ __forceinline__ void mma_bf16(float* c, const uint32_t* a, const uint32_t* b) {
    asm volatile(
        "mma.sync.aligned.m16n8k16.row.col.f32.bf16.bf16.f32 "
        "{%0,%1,%2,%3}, {%4,%5,%6,%7}, {%8,%9}, {%0,%1,%2,%3};"
        : "+f"(c[0]), "+f"(c[1]), "+f"(c[2]), "+f"(c[3])
        : "r"(a[0]), "r"(a[1]), "r"(a[2]), "r"(a[3]), "r"(b[0]), "r"(b[1]));
}
__device__ __forceinline__ void cp16(uint32_t dst, const void* src) {
    asm volatile("cp.async.cg.shared.global [%0], [%1], 16;" :: "r"(dst), "l"(src));
}
__device__ __forceinline__ void cp_commit() {
    asm volatile("cp.async.commit_group;" ::: "memory");
}
template <int N>
__device__ __forceinline__ void cp_wait() {
    asm volatile("cp.async.wait_group %0;" :: "n"(N) : "memory");
}

// ---------------- init ----------------
__global__ void k_init() {
    int tid = blockIdx.x * blockDim.x + threadIdx.x;
    if (tid < N_TOK) g_u[tid] = 1.0f;
    if (tid < M_PIX) { g_v[tid] = 1.0f; g_sqB[tid] = 0.0f; }
    if (tid < 64) { g_normU[tid] = 0.0f; g_normV[tid] = 0.0f; }
    if (tid == 0) { g_bar_count = 0u; g_bar_gen = 0u; }
}

// ---------------- squared norms ----------------
__global__ void k_sq_text(const float* __restrict__ text) {
    __shared__ float sh[256];
    int n = blockIdx.x, c = threadIdx.x;
    float s = 0.0f;
#pragma unroll
    for (int b = 0; b < B_DIM; ++b) {
        float x = text[(size_t)b * TEXT_B_STRIDE + (size_t)n * C_DIM + c];
        s += x * x;
    }
    sh[c] = s; __syncthreads();
    for (int off = 128; off > 0; off >>= 1) {
        if (c < off) sh[c] += sh[c + off];
        __syncthreads();
    }
    if (c == 0) g_sqA[n] = sh[0];
}

__global__ void k_sq_image(const float* __restrict__ image) {
    int m = blockIdx.x * 256 + threadIdx.x;
    int l0 = blockIdx.y * 256;
    float s = 0.0f;
    for (int l = l0; l < l0 + 256; ++l) {
        float x = image[(size_t)l * M_PIX + m];
        s += x * x;
    }
    atomicAdd(&g_sqB[m], s);
}

// ---------------- split helpers ----------------
__device__ __forceinline__ void split_bf(float x, __nv_bfloat16& h, __nv_bfloat16& l) {
    h = __float2bfloat16_rn(x);
    l = __float2bfloat16_rn(x - __bfloat162float(h));
}

// ---------------- pack kernels (tiled smem transposes) ----------------
__global__ void k_pack_text(const float* __restrict__ text) {
    __shared__ float t[32][33];
    int b = blockIdx.z, n0 = blockIdx.y * 32, c0 = blockIdx.x * 32;
    int tx = threadIdx.x, ty = threadIdx.y;
    for (int i = ty; i < 32; i += 8)
        t[i][tx] = text[(size_t)b * TEXT_B_STRIDE + (size_t)(n0 + i) * C_DIM + c0 + tx];
    __syncthreads();
    for (int i = ty; i < 32; i += 8) {
        // GEMM1 A operand: hi only
        size_t o = (size_t)(n0 + i) * L_DIM + b * C_DIM + c0 + tx;
        g_tA1h[o] = __float2bfloat16_rn(t[i][tx]);
    }
    for (int i = ty; i < 32; i += 8) {
        __nv_bfloat16 h, l; split_bf(t[tx][i], h, l);
        size_t o = (size_t)(b * C_DIM + c0 + i) * N_TOK + n0 + tx;
        g_tA3h[o] = h; g_tA3l[o] = l;
    }
}

__global__ void k_pack_image(const float* __restrict__ image) {
    __shared__ float t[32][33];
    int l0 = blockIdx.y * 32, m0 = blockIdx.x * 32;
    int tx = threadIdx.x, ty = threadIdx.y;
    for (int i = ty; i < 32; i += 8)
        t[i][tx] = image[(size_t)(l0 + i) * M_PIX + m0 + tx];
    __syncthreads();
    for (int i = ty; i < 32; i += 8) {
        __nv_bfloat16 h, l; split_bf(t[i][tx], h, l);
        size_t o = (size_t)(l0 + i) * M_PIX + m0 + tx;
        g_iB2h[o] = h; g_iB2l[o] = l;
    }
    for (int i = ty; i < 32; i += 8) {
        // GEMM1 B operand: hi only
        size_t o = (size_t)(m0 + i) * L_DIM + l0 + tx;
        g_iB1h[o] = __float2bfloat16_rn(t[tx][i]);
    }
}

__global__ void k_pack_T() {
    __shared__ float t[32][33];
    int n0 = blockIdx.y * 32, m0 = blockIdx.x * 32;
    int tx = threadIdx.x, ty = threadIdx.y;
    for (int i = ty; i < 32; i += 8) {
        float c = g_cost[(size_t)(n0 + i) * M_PIX + m0 + tx];
        t[i][tx] = expf(-0.1f * c) * g_u[n0 + i] * g_v[m0 + tx];
    }
    __syncthreads();
    for (int i = ty; i < 32; i += 8) {
        __nv_bfloat16 h, l; split_bf(t[i][tx], h, l);
        size_t o = (size_t)(n0 + i) * M_PIX + m0 + tx;
        g_T2h[o] = h; g_T2l[o] = l;
    }
    for (int i = ty; i < 32; i += 8) {
        __nv_bfloat16 h, l; split_bf(t[tx][i], h, l);
        size_t o = (size_t)(m0 + i) * N_TOK + n0 + tx;
        g_T3h[o] = h; g_T3l[o] = l;
    }
}

// ---------------- shared GEMM geometry ----------------
#define SPAD 40                      // 32 + 8 pad (80B row stride: conflict-free ldmatrix)
#define TILE_BYTES (128 * SPAD * 2)  // 10240 per operand array

// =====================================================================
// GEMM1: plain bf16 single-term. cost[n,m] = sqrt(sqA+sqB-2*Ah.Bh)
// A = g_tA1h [n][l], B = g_iB1h [m][l], K = 2048. 2 CTAs/SM.
// =====================================================================
#define G1_OFF_A 0
#define G1_OFF_B (TILE_BYTES)
#define G1_STAGE (2 * TILE_BYTES)        // 20480
#define G1_SMEM  (2 * G1_STAGE)          // 40960

__global__ void __launch_bounds__(256, 2) k_gemm1() {
    extern __shared__ char sm[];
    const int tid = threadIdx.x, wid = tid >> 5, lane = tid & 31;
    const int wy = wid >> 1, wx = wid & 1;   // warp tile 32(rows) x 64(cols)
    const int row0 = blockIdx.y * 128, col0 = blockIdx.x * 128;
    const uint32_t smb = smem_to_u32(sm);

    float acc[2][8][4] = {};

    const int ld_r = tid >> 2, ld_c = (tid & 3) << 3;
    const int a_r = lane & 15, a_c = (lane >> 4) << 3;
    const int b_r = (lane & 7) + (((lane >> 4) & 1) << 3), b_c = ((lane >> 3) & 1) << 3;

    const int KCH = L_DIM >> 5;

    auto issue = [&](int kc, int buf) {
        const int k0 = kc << 5;
        const uint32_t sb = smb + buf * G1_STAGE;
#pragma unroll
        for (int i = 0; i < 2; ++i) {
            int r = ld_r + i * 64;
            uint32_t so = (uint32_t)(r * SPAD + ld_c) * 2;
            cp16(sb + G1_OFF_A + so, g_tA1h + (size_t)(row0 + r) * L_DIM + k0 + ld_c);
            cp16(sb + G1_OFF_B + so, g_iB1h + (size_t)(col0 + r) * L_DIM + k0 + ld_c);
        }
        cp_commit();
    };

    issue(0, 0);
    for (int kc = 0; kc < KCH; ++kc) {
        const int cur = kc & 1;
        if (kc + 1 < KCH) { issue(kc + 1, cur ^ 1); cp_wait<1>(); }
        else              { cp_wait<0>(); }
        __syncthreads();
        const uint32_t sb = smb + cur * G1_STAGE;
#pragma unroll
        for (int kk = 0; kk < 2; ++kk) {
            uint32_t ah[2][4], bh[4][4];
#pragma unroll
            for (int mt = 0; mt < 2; ++mt) {
                uint32_t off = (uint32_t)((wy * 32 + mt * 16 + a_r) * SPAD + kk * 16 + a_c) * 2;
                ldsm_x4(ah[mt], sb + G1_OFF_A + off);
            }
#pragma unroll
            for (int p = 0; p < 4; ++p) {
                uint32_t off = (uint32_t)((wx * 64 + p * 16 + b_r) * SPAD + kk * 16 + b_c) * 2;
                ldsm_x4(bh[p], sb + G1_OFF_B + off);
            }
#pragma unroll
            for (int mt = 0; mt < 2; ++mt)
#pragma unroll
                for (int nt = 0; nt < 8; ++nt) {
                    const uint32_t bhi[2] = { bh[nt >> 1][(nt & 1) * 2],
                                              bh[nt >> 1][(nt & 1) * 2 + 1] };
                    mma_bf16(acc[mt][nt], ah[mt], bhi);
                }
        }
        __syncthreads();
    }

    const int rbase = row0 + wy * 32 + (lane >> 2);
    const int cbase = col0 + wx * 64 + ((lane & 3) << 1);
#pragma unroll
    for (int mt = 0; mt < 2; ++mt) {
        int rA = rbase + mt * 16, rB = rA + 8;
        float saA = g_sqA[rA], saB = g_sqA[rB];
#pragma unroll
        for (int nt = 0; nt < 8; ++nt) {
            int cc = cbase + nt * 8;
            float sb0 = g_sqB[cc], sb1 = g_sqB[cc + 1];
            float2 oA, oB;
            oA.x = sqrtf(fmaxf(saA + sb0 - 2.0f * acc[mt][nt][0], 1e-12f));
            oA.y = sqrtf(fmaxf(saA + sb1 - 2.0f * acc[mt][nt][1], 1e-12f));
            oB.x = sqrtf(fmaxf(saB + sb0 - 2.0f * acc[mt][nt][2], 1e-12f));
            oB.y = sqrtf(fmaxf(saB + sb1 - 2.0f * acc[mt][nt][3], 1e-12f));
            *(float2*)(g_cost + (size_t)rA * M_PIX + cc) = oA;
            *(float2*)(g_cost + (size_t)rB * M_PIX + cc) = oB;
        }
    }
}

// =====================================================================
// GEMM2/3: split-bf16 3-term (unchanged Round-8 core)
// ID 1: textO = T2 [n][m] x iB2[l][m], K=9216 -> out_text[b][n][c]
// ID 2: imgO  = tA3[l][n] x T3 [m][n], K=1024 -> out_img[l][m]
// =====================================================================
#define OFF_AH 0
#define OFF_AL (TILE_BYTES)
#define OFF_BH (2 * TILE_BYTES)
#define OFF_BL (3 * TILE_BYTES)
#define STAGE_BYTES (4 * TILE_BYTES) // 40960
#define SMEM_TOTAL_GEMM (2 * STAGE_BYTES)

template <int ID>
__global__ void __launch_bounds__(256, 1) k_mma_gemm(float* __restrict__ out) {
    extern __shared__ char sm[];
    const __nv_bfloat16 *Ah_, *Al_, *Bh_, *Bl_;
    int Ktot;
    if (ID == 1) { Ah_ = g_T2h; Al_ = g_T2l; Bh_ = g_iB2h; Bl_ = g_iB2l; Ktot = M_PIX; }
    else { Ah_ = g_tA3h; Al_ = g_tA3l; Bh_ = g_T3h; Bl_ = g_T3l; Ktot = N_TOK; }

    const int tid = threadIdx.x, wid = tid >> 5, lane = tid & 31;
    const int wy = wid >> 1, wx = wid & 1;   // warp tile 32(rows) x 64(cols)
    const int row0 = blockIdx.y * 128, col0 = blockIdx.x * 128;
    const uint32_t smb = smem_to_u32(sm);

    float acc[2][8][4] = {};

    const int ld_r = tid >> 2, ld_c = (tid & 3) << 3;
    const int a_r = lane & 15, a_c = (lane >> 4) << 3;
    const int b_r = (lane & 7) + (((lane >> 4) & 1) << 3), b_c = ((lane >> 3) & 1) << 3;

    const int KCH = Ktot >> 5;

    auto issue = [&](int kc, int buf) {
        const int k0 = kc << 5;
        const uint32_t sb = smb + buf * STAGE_BYTES;
#pragma unroll
        for (int i = 0; i < 2; ++i) {
            int r = ld_r + i * 64;
            uint32_t so = (uint32_t)(r * SPAD + ld_c) * 2;
            size_t ga = (size_t)(row0 + r) * Ktot + k0 + ld_c;
            size_t gb = (size_t)(col0 + r) * Ktot + k0 + ld_c;
            cp16(sb + OFF_AH + so, Ah_ + ga);
            cp16(sb + OFF_AL + so, Al_ + ga);
            cp16(sb + OFF_BH + so, Bh_ + gb);
            cp16(sb + OFF_BL + so, Bl_ + gb);
        }
        cp_commit();
    };

    issue(0, 0);
    for (int kc = 0; kc < KCH; ++kc) {
        const int cur = kc & 1;
        if (kc + 1 < KCH) { issue(kc + 1, cur ^ 1); cp_wait<1>(); }
        else              { cp_wait<0>(); }
        __syncthreads();
        const uint32_t sb = smb + cur * STAGE_BYTES;
#pragma unroll
        for (int kk = 0; kk < 2; ++kk) {
            uint32_t ah[2][4], al[2][4], bh[4][4], bl[4][4];
#pragma unroll
            for (int mt = 0; mt < 2; ++mt) {
                uint32_t off = (uint32_t)((wy * 32 + mt * 16 + a_r) * SPAD + kk * 16 + a_c) * 2;
                ldsm_x4(ah[mt], sb + OFF_AH + off);
                ldsm_x4(al[mt], sb + OFF_AL + off);
            }
#pragma unroll
            for (int p = 0; p < 4; ++p) {
                uint32_t off = (uint32_t)((wx * 64 + p * 16 + b_r) * SPAD + kk * 16 + b_c) * 2;
                ldsm_x4(bh[p], sb + OFF_BH + off);
                ldsm_x4(bl[p], sb + OFF_BL + off);
            }
#pragma unroll
            for (int mt = 0; mt < 2; ++mt)
#pragma unroll
                for (int nt = 0; nt < 8; ++nt) {
                    const uint32_t bhi[2] = { bh[nt >> 1][(nt & 1) * 2],
                                              bh[nt >> 1][(nt & 1) * 2 + 1] };
                    const uint32_t blo[2] = { bl[nt >> 1][(nt & 1) * 2],
                                              bl[nt >> 1][(nt & 1) * 2 + 1] };
                    mma_bf16(acc[mt][nt], ah[mt], bhi);   // Ah*Bh
                    mma_bf16(acc[mt][nt], ah[mt], blo);   // Ah*Bl
                    mma_bf16(acc[mt][nt], al[mt], bhi);   // Al*Bh
                }
        }
        __syncthreads();
    }

    // ---------------- epilogue ----------------
    const int rbase = row0 + wy * 32 + (lane >> 2);
    const int cbase = col0 + wx * 64 + ((lane & 3) << 1);
#pragma unroll
    for (int mt = 0; mt < 2; ++mt) {
        int rA = rbase + mt * 16, rB = rA + 8;
#pragma unroll
        for (int nt = 0; nt < 8; ++nt) {
            int cc = cbase + nt * 8;
            float d0 = acc[mt][nt][0], d1 = acc[mt][nt][1];
            float d2 = acc[mt][nt][2], d3 = acc[mt][nt][3];
            if (ID == 1) {
                int b = cc >> 8, c = cc & 255;   // col = l
                float* pA = out + (size_t)b * TEXT_B_STRIDE + (size_t)rA * C_DIM + c;
                float* pB = out + (size_t)b * TEXT_B_STRIDE + (size_t)rB * C_DIM + c;
                *(float2*)pA = make_float2(d0, d1);
                *(float2*)pB = make_float2(d2, d3);
            } else {
                *(float2*)(out + (size_t)rA * M_PIX + cc) = make_float2(d0, d1);
                *(float2*)(out + (size_t)rB * M_PIX + cc) = make_float2(d2, d3);
            }
        }
    }
}

// ---------------- Sinkhorn (persistent kernel, honest convergence break) ----------------
__device__ __forceinline__ void grid_barrier(unsigned e, int nctas) {
    __syncthreads();
    if (threadIdx.x == 0) {
        __threadfence();
        unsigned t = atomicAdd(&g_bar_count, 1u) + 1u;
        if (t == (unsigned)nctas * e) {
            atomicExch(&g_bar_gen, e);
        } else {
            while (*((volatile unsigned*)&g_bar_gen) < e) __nanosleep(64);
        }
        __threadfence();
    }
    __syncthreads();
}

__global__ void k_sinkhorn() {
    __shared__ float sred[256];
    const int cta = blockIdx.x;
    const int tid = threadIdx.x;
    const int NC = gridDim.x;
    unsigned epoch = 0;
    for (int it = 0; it < NITER; ++it) {
        for (int n = cta; n < N_TOK; n += NC) {
            const float* row = g_cost + (size_t)n * M_PIX;
            float s = 0.0f;
            for (int m = tid; m < M_PIX; m += 256)
                s += __expf(-10.0f * row[m]) * __ldcg(&g_v[m]);
            sred[tid] = s; __syncthreads();
            for (int off = 128; off > 0; off >>= 1) {
                if (tid < off) sred[tid] += sred[tid + off];
                __syncthreads();
            }
            if (tid == 0) {
                float un = 1.0f / (sred[0] + DENOM_SHIFT);
                float d = un - g_u[n];
                atomicAdd(&g_normU[it], d * d);
                g_u[n] = un;
            }
            __syncthreads();
        }
        ++epoch; grid_barrier(epoch, NC);
        for (int blk = cta; blk < (M_PIX / 64); blk += NC) {
            int col0 = blk * 64;
            int c = tid & 63, sl = tid >> 6;
            float t = 0.0f;
            for (int n = sl; n < N_TOK; n += 4)
                t += __expf(-10.0f * g_cost[(size_t)n * M_PIX + col0 + c]) * __ldcg(&g_u[n]);
            sred[tid] = t; __syncthreads();
            if (tid < 64) {
                float tt = sred[tid] + sred[tid + 64] + sred[tid + 128] + sred[tid + 192];
                int m = col0 + tid;
                float vn = 1.0f / (tt + DENOM_SHIFT);
                float d = vn - g_v[m];
                atomicAdd(&g_normV[it], d * d);
                g_v[m] = vn;
            }
            __syncthreads();
        }
        ++epoch; grid_barrier(epoch, NC);
        float nu = __ldcg(&g_normU[it]);
        float nv = __ldcg(&g_normV[it]);
        if (nu < CONV_TOL_SQ && nv < CONV_TOL_SQ) break;
    }
}

// ---------------- launch ----------------
extern "C" void kernel_launch(void* const* d_in, const int* in_sizes, int n_in,
                              void* d_out, int out_size) {
    const float* text  = (const float*)d_in[0];
    const float* image = (const float*)d_in[1];
    float* out_text = (float*)d_out;
    float* out_img  = out_text + (size_t)B_DIM * N_TOK * C_DIM;

    cudaFuncSetAttribute(k_gemm1, cudaFuncAttributeMaxDynamicSharedMemorySize, G1_SMEM);
    cudaFuncSetAttribute(k_mma_gemm<1>, cudaFuncAttributeMaxDynamicSharedMemorySize, SMEM_TOTAL_GEMM);
    cudaFuncSetAttribute(k_mma_gemm<2>, cudaFuncAttributeMaxDynamicSharedMemorySize, SMEM_TOTAL_GEMM);

    k_init<<<36, 256>>>();
    k_sq_text<<<N_TOK, 256>>>(text);
    k_sq_image<<<dim3(M_PIX / 256, L_DIM / 256), 256>>>(image);
    k_pack_text<<<dim3(C_DIM / 32, N_TOK / 32, B_DIM), dim3(32, 8)>>>(text);
    k_pack_image<<<dim3(M_PIX / 32, L_DIM / 32), dim3(32, 8)>>>(image);

    // GEMM1: cost (rows n: 8, cols m: 72), single-term bf16
    k_gemm1<<<dim3(M_PIX / 128, N_TOK / 128), 256, G1_SMEM>>>();

    k_sinkhorn<<<148, 256>>>();
    k_pack_T<<<dim3(M_PIX / 32, N_TOK / 32), dim3(32, 8)>>>();

    // GEMM2: out_text (rows n: 8, cols l: 16)
    k_mma_gemm<1><<<dim3(L_DIM / 128, N_TOK / 128), 256, SMEM_TOTAL_GEMM>>>(out_text);
    // GEMM3: out_img (rows l: 16, cols m: 72)
    k_mma_gemm<2><<<dim3(M_PIX / 128, L_DIM / 128), 256, SMEM_TOTAL_GEMM>>>(out_img);
}

// round 10
// speedup vs baseline: 2.7705x; 1.0763x over previous
#include <cuda_runtime.h>
#include <cuda_bf16.h>
#include <cstdint>

// ---------------- problem dims ----------------
#define B_DIM 8
#define C_DIM 256
#define N_TOK 1024
#define M_PIX 9216
#define L_DIM 2048
#define TEXT_B_STRIDE  262144    // 1024*256
#define IMG_B_STRIDE   2359296   // 256*9216

#define NITER 50
#define CONV_TOL_SQ 1e-4f
#define DENOM_SHIFT 100.0f

// ---------------- device scratch (statics; no mallocs) ----------------
__device__ float g_cost[(size_t)N_TOK * M_PIX];  // 37.75 MB
__device__ float g_sqA[N_TOK];
__device__ float g_sqB[M_PIX];
__device__ float g_u[N_TOK];
__device__ float g_v[M_PIX];
__device__ float g_normU[64];
__device__ float g_normV[64];
__device__ unsigned g_bar_count;
__device__ unsigned g_bar_gen;

// bf16 operand buffers (K-major). GEMM1 uses hi-only; GEMM2/3 use hi+lo.
__device__ __nv_bfloat16 g_tA1h[(size_t)N_TOK * L_DIM];  // text  [n][l] (hi only)
__device__ __nv_bfloat16 g_iB1h[(size_t)M_PIX * L_DIM];  // image [m][l] (hi only)
__device__ __nv_bfloat16 g_tA3h[(size_t)L_DIM * N_TOK];  // text  [l][n]
__device__ __nv_bfloat16 g_tA3l[(size_t)L_DIM * N_TOK];
__device__ __nv_bfloat16 g_iB2h[(size_t)L_DIM * M_PIX];  // image [l][m]
__device__ __nv_bfloat16 g_iB2l[(size_t)L_DIM * M_PIX];
__device__ __nv_bfloat16 g_T2h[(size_t)N_TOK * M_PIX];   // T [n][m]
__device__ __nv_bfloat16 g_T2l[(size_t)N_TOK * M_PIX];
__device__ __nv_bfloat16 g_T3h[(size_t)M_PIX * N_TOK];   // T [m][n]
__device__ __nv_bfloat16 g_T3l[(size_t)M_PIX * N_TOK];

// ---------------- helpers ----------------
__device__ __forceinline__ uint32_t smem_to_u32(const void* p) {
    uint32_t a;
    asm("{ .reg .u64 t; cvta.to.shared.u64 t, %1; cvt.u32.u64 %0, t; }" : "=r"(a) : "l"(p));
    return a;
}
__device__ __forceinline__ void ldsm_x4(uint32_t* r, uint32_t a) {
    asm volatile("ldmatrix.sync.aligned.m8n8.x4.shared.b16 {%0,%1,%2,%3}, [%4];"
                 : "=r"(r[0]), "=r"(r[1]), "=r"(r[2]), "=r"(r[3]) : "r"(a));
}
__device__ __forceinline__ void mma_bf16(float* c, const uint32_t* a, const uint32_t* b) {
    asm volatile(
        "mma.sync.aligned.m16n8k16.row.col.f32.bf16.bf16.f32 "
        "{%0,%1,%2,%3}, {%4,%5,%6,%7}, {%8,%9}, {%0,%1,%2,%3};"
        : "+f"(c[0]), "+f"(c[1]), "+f"(c[2]), "+f"(c[3])
        : "r"(a[0]), "r"(a[1]), "r"(a[2]), "r"(a[3]), "r"(b[0]), "r"(b[1]));
}
__device__ __forceinline__ void cp16(uint32_t dst, const void* src) {
    asm volatile("cp.async.cg.shared.global [%0], [%1], 16;" :: "r"(dst), "l"(src));
}
__device__ __forceinline__ void cp_commit() {
    asm volatile("cp.async.commit_group;" ::: "memory");
}
template <int N>
__device__ __forceinline__ void cp_wait() {
    asm volatile("cp.async.wait_group %0;" :: "n"(N) : "memory");
}

// ---------------- init ----------------
__global__ void k_init() {
    int tid = blockIdx.x * blockDim.x + threadIdx.x;
    if (tid < N_TOK) g_u[tid] = 1.0f;
    if (tid < M_PIX) { g_v[tid] = 1.0f; g_sqB[tid] = 0.0f; }
    if (tid < 64) { g_normU[tid] = 0.0f; g_normV[tid] = 0.0f; }
    if (tid == 0) { g_bar_count = 0u; g_bar_gen = 0u; }
}

// ---------------- squared norms ----------------
__global__ void k_sq_text(const float* __restrict__ text) {
    __shared__ float sh[256];
    int n = blockIdx.x, c = threadIdx.x;
    float s = 0.0f;
#pragma unroll
    for (int b = 0; b < B_DIM; ++b) {
        float x = text[(size_t)b * TEXT_B_STRIDE + (size_t)n * C_DIM + c];
        s += x * x;
    }
    sh[c] = s; __syncthreads();
    for (int off = 128; off > 0; off >>= 1) {
        if (c < off) sh[c] += sh[c + off];
        __syncthreads();
    }
    if (c == 0) g_sqA[n] = sh[0];
}

__global__ void k_sq_image(const float* __restrict__ image) {
    int m = blockIdx.x * 256 + threadIdx.x;
    int l0 = blockIdx.y * 256;
    float s = 0.0f;
    for (int l = l0; l < l0 + 256; ++l) {
        float x = image[(size_t)l * M_PIX + m];
        s += x * x;
    }
    atomicAdd(&g_sqB[m], s);
}

// ---------------- split helpers ----------------
__device__ __forceinline__ void split_bf(float x, __nv_bfloat16& h, __nv_bfloat16& l) {
    h = __float2bfloat16_rn(x);
    l = __float2bfloat16_rn(x - __bfloat162float(h));
}

// ---------------- pack kernels (tiled smem transposes) ----------------
__global__ void k_pack_text(const float* __restrict__ text) {
    __shared__ float t[32][33];
    int b = blockIdx.z, n0 = blockIdx.y * 32, c0 = blockIdx.x * 32;
    int tx = threadIdx.x, ty = threadIdx.y;
    for (int i = ty; i < 32; i += 8)
        t[i][tx] = text[(size_t)b * TEXT_B_STRIDE + (size_t)(n0 + i) * C_DIM + c0 + tx];
    __syncthreads();
    for (int i = ty; i < 32; i += 8) {
        size_t o = (size_t)(n0 + i) * L_DIM + b * C_DIM + c0 + tx;
        g_tA1h[o] = __float2bfloat16_rn(t[i][tx]);
    }
    for (int i = ty; i < 32; i += 8) {
        __nv_bfloat16 h, l; split_bf(t[tx][i], h, l);
        size_t o = (size_t)(b * C_DIM + c0 + i) * N_TOK + n0 + tx;
        g_tA3h[o] = h; g_tA3l[o] = l;
    }
}

__global__ void k_pack_image(const float* __restrict__ image) {
    __shared__ float t[32][33];
    int l0 = blockIdx.y * 32, m0 = blockIdx.x * 32;
    int tx = threadIdx.x, ty = threadIdx.y;
    for (int i = ty; i < 32; i += 8)
        t[i][tx] = image[(size_t)(l0 + i) * M_PIX + m0 + tx];
    __syncthreads();
    for (int i = ty; i < 32; i += 8) {
        __nv_bfloat16 h, l; split_bf(t[i][tx], h, l);
        size_t o = (size_t)(l0 + i) * M_PIX + m0 + tx;
        g_iB2h[o] = h; g_iB2l[o] = l;
    }
    for (int i = ty; i < 32; i += 8) {
        size_t o = (size_t)(m0 + i) * L_DIM + l0 + tx;
        g_iB1h[o] = __float2bfloat16_rn(t[tx][i]);
    }
}

__global__ void k_pack_T() {
    __shared__ float t[32][33];
    int n0 = blockIdx.y * 32, m0 = blockIdx.x * 32;
    int tx = threadIdx.x, ty = threadIdx.y;
    for (int i = ty; i < 32; i += 8) {
        float c = g_cost[(size_t)(n0 + i) * M_PIX + m0 + tx];
        t[i][tx] = expf(-0.1f * c) * g_u[n0 + i] * g_v[m0 + tx];
    }
    __syncthreads();
    for (int i = ty; i < 32; i += 8) {
        __nv_bfloat16 h, l; split_bf(t[i][tx], h, l);
        size_t o = (size_t)(n0 + i) * M_PIX + m0 + tx;
        g_T2h[o] = h; g_T2l[o] = l;
    }
    for (int i = ty; i < 32; i += 8) {
        __nv_bfloat16 h, l; split_bf(t[tx][i], h, l);
        size_t o = (size_t)(m0 + i) * N_TOK + n0 + tx;
        g_T3h[o] = h; g_T3l[o] = l;
    }
}

// ---------------- shared GEMM geometry ----------------
#define SPAD 40                      // 32 + 8 pad (80B row stride: conflict-free ldmatrix)
#define TILE_BYTES (128 * SPAD * 2)  // 10240 per operand array

// =====================================================================
// GEMM1: plain bf16 single-term, 3-stage cp.async, 1 barrier/iter, 2 CTAs/SM.
// cost[n,m] = sqrt(sqA+sqB-2*Ah.Bh); A=g_tA1h[n][l], B=g_iB1h[m][l], K=2048
// =====================================================================
#define G1_OFF_A 0
#define G1_OFF_B (TILE_BYTES)
#define G1_STAGE (2 * TILE_BYTES)        // 20480
#define G1_SMEM  (3 * G1_STAGE)          // 61440

__global__ void __launch_bounds__(256, 2) k_gemm1() {
    extern __shared__ char sm[];
    const int tid = threadIdx.x, wid = tid >> 5, lane = tid & 31;
    const int wy = wid >> 1, wx = wid & 1;   // warp tile 32(rows) x 64(cols)
    const int row0 = blockIdx.y * 128, col0 = blockIdx.x * 128;
    const uint32_t smb = smem_to_u32(sm);

    float acc[2][8][4] = {};

    const int ld_r = tid >> 2, ld_c = (tid & 3) << 3;
    const int a_r = lane & 15, a_c = (lane >> 4) << 3;
    const int b_r = (lane & 7) + (((lane >> 4) & 1) << 3), b_c = ((lane >> 3) & 1) << 3;

    const int KCH = L_DIM >> 5;

    auto issue = [&](int kc) {
        if (kc < KCH) {
            const int k0 = kc << 5;
            const uint32_t sb = smb + (kc % 3) * G1_STAGE;
#pragma unroll
            for (int i = 0; i < 2; ++i) {
                int r = ld_r + i * 64;
                uint32_t so = (uint32_t)(r * SPAD + ld_c) * 2;
                cp16(sb + G1_OFF_A + so, g_tA1h + (size_t)(row0 + r) * L_DIM + k0 + ld_c);
                cp16(sb + G1_OFF_B + so, g_iB1h + (size_t)(col0 + r) * L_DIM + k0 + ld_c);
            }
        }
        cp_commit();
    };

    issue(0); issue(1);
    for (int kc = 0; kc < KCH; ++kc) {
        cp_wait<1>();
        __syncthreads();          // stage kc landed; all warps done with stage kc-1
        issue(kc + 2);            // overwrites stage kc-1's buffer — safe post-barrier
        const uint32_t sb = smb + (kc % 3) * G1_STAGE;
#pragma unroll
        for (int kk = 0; kk < 2; ++kk) {
            uint32_t ah[2][4], bh[4][4];
#pragma unroll
            for (int mt = 0; mt < 2; ++mt) {
                uint32_t off = (uint32_t)((wy * 32 + mt * 16 + a_r) * SPAD + kk * 16 + a_c) * 2;
                ldsm_x4(ah[mt], sb + G1_OFF_A + off);
            }
#pragma unroll
            for (int p = 0; p < 4; ++p) {
                uint32_t off = (uint32_t)((wx * 64 + p * 16 + b_r) * SPAD + kk * 16 + b_c) * 2;
                ldsm_x4(bh[p], sb + G1_OFF_B + off);
            }
#pragma unroll
            for (int mt = 0; mt < 2; ++mt)
#pragma unroll
                for (int nt = 0; nt < 8; ++nt) {
                    const uint32_t bhi[2] = { bh[nt >> 1][(nt & 1) * 2],
                                              bh[nt >> 1][(nt & 1) * 2 + 1] };
                    mma_bf16(acc[mt][nt], ah[mt], bhi);
                }
        }
    }

    const int rbase = row0 + wy * 32 + (lane >> 2);
    const int cbase = col0 + wx * 64 + ((lane & 3) << 1);
#pragma unroll
    for (int mt = 0; mt < 2; ++mt) {
        int rA = rbase + mt * 16, rB = rA + 8;
        float saA = g_sqA[rA], saB = g_sqA[rB];
#pragma unroll
        for (int nt = 0; nt < 8; ++nt) {
            int cc = cbase + nt * 8;
            float sb0 = g_sqB[cc], sb1 = g_sqB[cc + 1];
            float2 oA, oB;
            oA.x = sqrtf(fmaxf(saA + sb0 - 2.0f * acc[mt][nt][0], 1e-12f));
            oA.y = sqrtf(fmaxf(saA + sb1 - 2.0f * acc[mt][nt][1], 1e-12f));
            oB.x = sqrtf(fmaxf(saB + sb0 - 2.0f * acc[mt][nt][2], 1e-12f));
            oB.y = sqrtf(fmaxf(saB + sb1 - 2.0f * acc[mt][nt][3], 1e-12f));
            *(float2*)(g_cost + (size_t)rA * M_PIX + cc) = oA;
            *(float2*)(g_cost + (size_t)rB * M_PIX + cc) = oB;
        }
    }
}

// =====================================================================
// GEMM2+3 fused launch: split-bf16 3-term, 3-stage cp.async, 1 barrier/iter.
// Flat grid of 1280 CTAs: first 128 = GEMM2 (long K=9216, starts first),
// remaining 1152 = GEMM3 (K=1024) backfill.
//   GEMM2: textO = T2 [n][m] x iB2[l][m] -> out_text[b][n][c]
//   GEMM3: imgO  = tA3[l][n] x T3 [m][n] -> out_img[l][m]
// =====================================================================
#define OFF_AH 0
#define OFF_AL (TILE_BYTES)
#define OFF_BH (2 * TILE_BYTES)
#define OFF_BL (3 * TILE_BYTES)
#define STAGE_BYTES (4 * TILE_BYTES)     // 40960
#define SMEM_G23 (3 * STAGE_BYTES)       // 122880

#define G2_BLOCKS 128                    // (L_DIM/128)*(N_TOK/128) = 16*8

__global__ void __launch_bounds__(256, 1) k_gemm23(float* __restrict__ out_text,
                                                   float* __restrict__ out_img) {
    extern __shared__ char sm[];
    const int bid = blockIdx.x;
    const bool isG2 = (bid < G2_BLOCKS);
    int bx, by;
    if (isG2) { bx = bid & 15; by = bid >> 4; }                 // 16 x 8
    else { int b = bid - G2_BLOCKS; bx = b % 72; by = b / 72; } // 72 x 16

    const __nv_bfloat16 *Ah_, *Al_, *Bh_, *Bl_;
    int Ktot; float* out;
    if (isG2) { Ah_ = g_T2h; Al_ = g_T2l; Bh_ = g_iB2h; Bl_ = g_iB2l; Ktot = M_PIX; out = out_text; }
    else      { Ah_ = g_tA3h; Al_ = g_tA3l; Bh_ = g_T3h; Bl_ = g_T3l; Ktot = N_TOK; out = out_img; }

    const int tid = threadIdx.x, wid = tid >> 5, lane = tid & 31;
    const int wy = wid >> 1, wx = wid & 1;   // warp tile 32(rows) x 64(cols)
    const int row0 = by * 128, col0 = bx * 128;
    const uint32_t smb = smem_to_u32(sm);

    float acc[2][8][4] = {};

    const int ld_r = tid >> 2, ld_c = (tid & 3) << 3;
    const int a_r = lane & 15, a_c = (lane >> 4) << 3;
    const int b_r = (lane & 7) + (((lane >> 4) & 1) << 3), b_c = ((lane >> 3) & 1) << 3;

    const int KCH = Ktot >> 5;

    auto issue = [&](int kc) {
        if (kc < KCH) {
            const int k0 = kc << 5;
            const uint32_t sb = smb + (kc % 3) * STAGE_BYTES;
#pragma unroll
            for (int i = 0; i < 2; ++i) {
                int r = ld_r + i * 64;
                uint32_t so = (uint32_t)(r * SPAD + ld_c) * 2;
                size_t ga = (size_t)(row0 + r) * Ktot + k0 + ld_c;
                size_t gb = (size_t)(col0 + r) * Ktot + k0 + ld_c;
                cp16(sb + OFF_AH + so, Ah_ + ga);
                cp16(sb + OFF_AL + so, Al_ + ga);
                cp16(sb + OFF_BH + so, Bh_ + gb);
                cp16(sb + OFF_BL + so, Bl_ + gb);
            }
        }
        cp_commit();
    };

    issue(0); issue(1);
    for (int kc = 0; kc < KCH; ++kc) {
        cp_wait<1>();
        __syncthreads();
        issue(kc + 2);
        const uint32_t sb = smb + (kc % 3) * STAGE_BYTES;
#pragma unroll
        for (int kk = 0; kk < 2; ++kk) {
            uint32_t ah[2][4], al[2][4], bh[4][4], bl[4][4];
#pragma unroll
            for (int mt = 0; mt < 2; ++mt) {
                uint32_t off = (uint32_t)((wy * 32 + mt * 16 + a_r) * SPAD + kk * 16 + a_c) * 2;
                ldsm_x4(ah[mt], sb + OFF_AH + off);
                ldsm_x4(al[mt], sb + OFF_AL + off);
            }
#pragma unroll
            for (int p = 0; p < 4; ++p) {
                uint32_t off = (uint32_t)((wx * 64 + p * 16 + b_r) * SPAD + kk * 16 + b_c) * 2;
                ldsm_x4(bh[p], sb + OFF_BH + off);
                ldsm_x4(bl[p], sb + OFF_BL + off);
            }
#pragma unroll
            for (int mt = 0; mt < 2; ++mt)
#pragma unroll
                for (int nt = 0; nt < 8; ++nt) {
                    const uint32_t bhi[2] = { bh[nt >> 1][(nt & 1) * 2],
                                              bh[nt >> 1][(nt & 1) * 2 + 1] };
                    const uint32_t blo[2] = { bl[nt >> 1][(nt & 1) * 2],
                                              bl[nt >> 1][(nt & 1) * 2 + 1] };
                    mma_bf16(acc[mt][nt], ah[mt], bhi);   // Ah*Bh
                    mma_bf16(acc[mt][nt], ah[mt], blo);   // Ah*Bl
                    mma_bf16(acc[mt][nt], al[mt], bhi);   // Al*Bh
                }
        }
    }

    // ---------------- epilogue ----------------
    const int rbase = row0 + wy * 32 + (lane >> 2);
    const int cbase = col0 + wx * 64 + ((lane & 3) << 1);
#pragma unroll
    for (int mt = 0; mt < 2; ++mt) {
        int rA = rbase + mt * 16, rB = rA + 8;
#pragma unroll
        for (int nt = 0; nt < 8; ++nt) {
            int cc = cbase + nt * 8;
            float d0 = acc[mt][nt][0], d1 = acc[mt][nt][1];
            float d2 = acc[mt][nt][2], d3 = acc[mt][nt][3];
            if (isG2) {
                int b = cc >> 8, c = cc & 255;   // col = l
                float* pA = out + (size_t)b * TEXT_B_STRIDE + (size_t)rA * C_DIM + c;
                float* pB = out + (size_t)b * TEXT_B_STRIDE + (size_t)rB * C_DIM + c;
                *(float2*)pA = make_float2(d0, d1);
                *(float2*)pB = make_float2(d2, d3);
            } else {
                *(float2*)(out + (size_t)rA * M_PIX + cc) = make_float2(d0, d1);
                *(float2*)(out + (size_t)rB * M_PIX + cc) = make_float2(d2, d3);
            }
        }
    }
}

// ---------------- Sinkhorn (persistent kernel, honest convergence break) ----------------
__device__ __forceinline__ void grid_barrier(unsigned e, int nctas) {
    __syncthreads();
    if (threadIdx.x == 0) {
        __threadfence();
        unsigned t = atomicAdd(&g_bar_count, 1u) + 1u;
        if (t == (unsigned)nctas * e) {
            atomicExch(&g_bar_gen, e);
        } else {
            while (*((volatile unsigned*)&g_bar_gen) < e) __nanosleep(64);
        }
        __threadfence();
    }
    __syncthreads();
}

__global__ void k_sinkhorn() {
    __shared__ float sred[256];
    const int cta = blockIdx.x;
    const int tid = threadIdx.x;
    const int NC = gridDim.x;
    unsigned epoch = 0;
    for (int it = 0; it < NITER; ++it) {
        for (int n = cta; n < N_TOK; n += NC) {
            const float* row = g_cost + (size_t)n * M_PIX;
            float s = 0.0f;
            for (int m = tid; m < M_PIX; m += 256)
                s += __expf(-10.0f * row[m]) * __ldcg(&g_v[m]);
            sred[tid] = s; __syncthreads();
            for (int off = 128; off > 0; off >>= 1) {
                if (tid < off) sred[tid] += sred[tid + off];
                __syncthreads();
            }
            if (tid == 0) {
                float un = 1.0f / (sred[0] + DENOM_SHIFT);
                float d = un - g_u[n];
                atomicAdd(&g_normU[it], d * d);
                g_u[n] = un;
            }
            __syncthreads();
        }
        ++epoch; grid_barrier(epoch, NC);
        for (int blk = cta; blk < (M_PIX / 64); blk += NC) {
            int col0 = blk * 64;
            int c = tid & 63, sl = tid >> 6;
            float t = 0.0f;
            for (int n = sl; n < N_TOK; n += 4)
                t += __expf(-10.0f * g_cost[(size_t)n * M_PIX + col0 + c]) * __ldcg(&g_u[n]);
            sred[tid] = t; __syncthreads();
            if (tid < 64) {
                float tt = sred[tid] + sred[tid + 64] + sred[tid + 128] + sred[tid + 192];
                int m = col0 + tid;
                float vn = 1.0f / (tt + DENOM_SHIFT);
                float d = vn - g_v[m];
                atomicAdd(&g_normV[it], d * d);
                g_v[m] = vn;
            }
            __syncthreads();
        }
        ++epoch; grid_barrier(epoch, NC);
        float nu = __ldcg(&g_normU[it]);
        float nv = __ldcg(&g_normV[it]);
        if (nu < CONV_TOL_SQ && nv < CONV_TOL_SQ) break;
    }
}

// ---------------- launch ----------------
extern "C" void kernel_launch(void* const* d_in, const int* in_sizes, int n_in,
                              void* d_out, int out_size) {
    const float* text  = (const float*)d_in[0];
    const float* image = (const float*)d_in[1];
    float* out_text = (float*)d_out;
    float* out_img  = out_text + (size_t)B_DIM * N_TOK * C_DIM;

    cudaFuncSetAttribute(k_gemm1, cudaFuncAttributeMaxDynamicSharedMemorySize, G1_SMEM);
    cudaFuncSetAttribute(k_gemm23, cudaFuncAttributeMaxDynamicSharedMemorySize, SMEM_G23);

    k_init<<<36, 256>>>();
    k_sq_text<<<N_TOK, 256>>>(text);
    k_sq_image<<<dim3(M_PIX / 256, L_DIM / 256), 256>>>(image);
    k_pack_text<<<dim3(C_DIM / 32, N_TOK / 32, B_DIM), dim3(32, 8)>>>(text);
    k_pack_image<<<dim3(M_PIX / 32, L_DIM / 32), dim3(32, 8)>>>(image);

    // GEMM1: cost (rows n: 8, cols m: 72), single-term bf16
    k_gemm1<<<dim3(M_PIX / 128, N_TOK / 128), 256, G1_SMEM>>>();

    k_sinkhorn<<<148, 256>>>();
    k_pack_T<<<dim3(M_PIX / 32, N_TOK / 32), dim3(32, 8)>>>();

    // GEMM2+3 fused: 128 long-K CTAs first, then 1152 short-K CTAs
    k_gemm23<<<G2_BLOCKS + 1152, 256, SMEM_G23>>>(out_text, out_img);
}

// round 11
// speedup vs baseline: 4.7626x; 1.7190x over previous
#include <cuda_runtime.h>
#include <cuda_fp16.h>
#include <cstdint>

// ---------------- problem dims ----------------
#define B_DIM 8
#define C_DIM 256
#define N_TOK 1024
#define M_PIX 9216
#define L_DIM 2048
#define TEXT_B_STRIDE  262144    // 1024*256
#define IMG_B_STRIDE   2359296   // 256*9216

#define NITER 50
#define CONV_TOL_SQ 1e-4f
#define DENOM_SHIFT 100.0f

// T pre-scale (exact power of two; keeps T in fp16 normal range)
#define TSCALE      1048576.0f          // 2^20
#define TSCALE_INV  9.5367431640625e-7f // 2^-20

// ---------------- device scratch (statics; no mallocs) ----------------
__device__ float g_cost[(size_t)N_TOK * M_PIX];  // 37.75 MB
__device__ float g_sqA[N_TOK];
__device__ float g_sqB[M_PIX];
__device__ float g_u[N_TOK];
__device__ float g_v[M_PIX];
__device__ float g_normU[64];
__device__ float g_normV[64];
__device__ unsigned g_bar_count;
__device__ unsigned g_bar_gen;

// fp16 operand buffers (K-major), single plane each
__device__ __half g_hA1[(size_t)N_TOK * L_DIM];  // text  [n][l]
__device__ __half g_hB1[(size_t)M_PIX * L_DIM];  // image [m][l]
__device__ __half g_hT2[(size_t)N_TOK * M_PIX];  // T*2^20 [n][m]
__device__ __half g_hB2[(size_t)L_DIM * M_PIX];  // image [l][m]
__device__ __half g_hA3[(size_t)L_DIM * N_TOK];  // text  [l][n]
__device__ __half g_hT3[(size_t)M_PIX * N_TOK];  // T*2^20 [m][n]

// ---------------- helpers ----------------
__device__ __forceinline__ uint32_t smem_to_u32(const void* p) {
    uint32_t a;
    asm("{ .reg .u64 t; cvta.to.shared.u64 t, %1; cvt.u32.u64 %0, t; }" : "=r"(a) : "l"(p));
    return a;
}
__device__ __forceinline__ void ldsm_x4(uint32_t* r, uint32_t a) {
    asm volatile("ldmatrix.sync.aligned.m8n8.x4.shared.b16 {%0,%1,%2,%3}, [%4];"
                 : "=r"(r[0]), "=r"(r[1]), "=r"(r[2]), "=r"(r[3]) : "r"(a));
}
__device__ __forceinline__ void mma_f16(float* c, const uint32_t* a, const uint32_t* b) {
    asm volatile(
        "mma.sync.aligned.m16n8k16.row.col.f32.f16.f16.f32 "
        "{%0,%1,%2,%3}, {%4,%5,%6,%7}, {%8,%9}, {%0,%1,%2,%3};"
        : "+f"(c[0]), "+f"(c[1]), "+f"(c[2]), "+f"(c[3])
        : "r"(a[0]), "r"(a[1]), "r"(a[2]), "r"(a[3]), "r"(b[0]), "r"(b[1]));
}
__device__ __forceinline__ void cp16(uint32_t dst, const void* src) {
    asm volatile("cp.async.cg.shared.global [%0], [%1], 16;" :: "r"(dst), "l"(src));
}
__device__ __forceinline__ void cp_commit() {
    asm volatile("cp.async.commit_group;" ::: "memory");
}
template <int N>
__device__ __forceinline__ void cp_wait() {
    asm volatile("cp.async.wait_group %0;" :: "n"(N) : "memory");
}

// ---------------- init ----------------
__global__ void k_init() {
    int tid = blockIdx.x * blockDim.x + threadIdx.x;
    if (tid < N_TOK) g_u[tid] = 1.0f;
    if (tid < M_PIX) { g_v[tid] = 1.0f; g_sqB[tid] = 0.0f; }
    if (tid < 64) { g_normU[tid] = 0.0f; g_normV[tid] = 0.0f; }
    if (tid == 0) { g_bar_count = 0u; g_bar_gen = 0u; }
}

// ---------------- squared norms ----------------
__global__ void k_sq_text(const float* __restrict__ text) {
    __shared__ float sh[256];
    int n = blockIdx.x, c = threadIdx.x;
    float s = 0.0f;
#pragma unroll
    for (int b = 0; b < B_DIM; ++b) {
        float x = text[(size_t)b * TEXT_B_STRIDE + (size_t)n * C_DIM + c];
        s += x * x;
    }
    sh[c] = s; __syncthreads();
    for (int off = 128; off > 0; off >>= 1) {
        if (c < off) sh[c] += sh[c + off];
        __syncthreads();
    }
    if (c == 0) g_sqA[n] = sh[0];
}

__global__ void k_sq_image(const float* __restrict__ image) {
    int m = blockIdx.x * 256 + threadIdx.x;
    int l0 = blockIdx.y * 256;
    float s = 0.0f;
    for (int l = l0; l < l0 + 256; ++l) {
        float x = image[(size_t)l * M_PIX + m];
        s += x * x;
    }
    atomicAdd(&g_sqB[m], s);
}

// ---------------- pack kernels (tiled smem transposes, fp16 single-plane) ----------------
__global__ void k_pack_text(const float* __restrict__ text) {
    __shared__ float t[32][33];
    int b = blockIdx.z, n0 = blockIdx.y * 32, c0 = blockIdx.x * 32;
    int tx = threadIdx.x, ty = threadIdx.y;
    for (int i = ty; i < 32; i += 8)
        t[i][tx] = text[(size_t)b * TEXT_B_STRIDE + (size_t)(n0 + i) * C_DIM + c0 + tx];
    __syncthreads();
    for (int i = ty; i < 32; i += 8) {
        size_t o = (size_t)(n0 + i) * L_DIM + b * C_DIM + c0 + tx;
        g_hA1[o] = __float2half_rn(t[i][tx]);
    }
    for (int i = ty; i < 32; i += 8) {
        size_t o = (size_t)(b * C_DIM + c0 + i) * N_TOK + n0 + tx;
        g_hA3[o] = __float2half_rn(t[tx][i]);
    }
}

__global__ void k_pack_image(const float* __restrict__ image) {
    __shared__ float t[32][33];
    int l0 = blockIdx.y * 32, m0 = blockIdx.x * 32;
    int tx = threadIdx.x, ty = threadIdx.y;
    for (int i = ty; i < 32; i += 8)
        t[i][tx] = image[(size_t)(l0 + i) * M_PIX + m0 + tx];
    __syncthreads();
    for (int i = ty; i < 32; i += 8) {
        size_t o = (size_t)(l0 + i) * M_PIX + m0 + tx;
        g_hB2[o] = __float2half_rn(t[i][tx]);
    }
    for (int i = ty; i < 32; i += 8) {
        size_t o = (size_t)(m0 + i) * L_DIM + l0 + tx;
        g_hB1[o] = __float2half_rn(t[tx][i]);
    }
}

__global__ void k_pack_T() {
    __shared__ float t[32][33];
    int n0 = blockIdx.y * 32, m0 = blockIdx.x * 32;
    int tx = threadIdx.x, ty = threadIdx.y;
    for (int i = ty; i < 32; i += 8) {
        float c = g_cost[(size_t)(n0 + i) * M_PIX + m0 + tx];
        t[i][tx] = expf(-0.1f * c) * g_u[n0 + i] * g_v[m0 + tx] * TSCALE;
    }
    __syncthreads();
    for (int i = ty; i < 32; i += 8) {
        size_t o = (size_t)(n0 + i) * M_PIX + m0 + tx;
        g_hT2[o] = __float2half_rn(t[i][tx]);
    }
    for (int i = ty; i < 32; i += 8) {
        size_t o = (size_t)(m0 + i) * N_TOK + n0 + tx;
        g_hT3[o] = __float2half_rn(t[tx][i]);
    }
}

// ---------------- GEMM geometry (all single-term fp16) ----------------
#define SPAD 40                      // 32 + 8 pad (80B row stride: conflict-free ldmatrix)
#define TILE_BYTES (128 * SPAD * 2)  // 10240 per operand tile
#define OFF_A 0
#define OFF_B (TILE_BYTES)
#define STAGE (2 * TILE_BYTES)       // 20480
#define SMEM_GEMM (3 * STAGE)        // 61440 -> 2 CTAs/SM

// =====================================================================
// GEMM1: cost[n,m] = sqrt(sqA+sqB-2*A.B); A=g_hA1[n][l], B=g_hB1[m][l], K=2048
// =====================================================================
__global__ void __launch_bounds__(256, 2) k_gemm1() {
    extern __shared__ char sm[];
    const int tid = threadIdx.x, wid = tid >> 5, lane = tid & 31;
    const int wy = wid >> 1, wx = wid & 1;   // warp tile 32(rows) x 64(cols)
    const int row0 = blockIdx.y * 128, col0 = blockIdx.x * 128;
    const uint32_t smb = smem_to_u32(sm);

    float acc[2][8][4] = {};

    const int ld_r = tid >> 2, ld_c = (tid & 3) << 3;
    const int a_r = lane & 15, a_c = (lane >> 4) << 3;
    const int b_r = (lane & 7) + (((lane >> 4) & 1) << 3), b_c = ((lane >> 3) & 1) << 3;

    const int KCH = L_DIM >> 5;

    auto issue = [&](int kc) {
        if (kc < KCH) {
            const int k0 = kc << 5;
            const uint32_t sb = smb + (kc % 3) * STAGE;
#pragma unroll
            for (int i = 0; i < 2; ++i) {
                int r = ld_r + i * 64;
                uint32_t so = (uint32_t)(r * SPAD + ld_c) * 2;
                cp16(sb + OFF_A + so, g_hA1 + (size_t)(row0 + r) * L_DIM + k0 + ld_c);
                cp16(sb + OFF_B + so, g_hB1 + (size_t)(col0 + r) * L_DIM + k0 + ld_c);
            }
        }
        cp_commit();
    };

    issue(0); issue(1);
    for (int kc = 0; kc < KCH; ++kc) {
        cp_wait<1>();
        __syncthreads();
        issue(kc + 2);
        const uint32_t sb = smb + (kc % 3) * STAGE;
#pragma unroll
        for (int kk = 0; kk < 2; ++kk) {
            uint32_t ah[2][4], bh[4][4];
#pragma unroll
            for (int mt = 0; mt < 2; ++mt) {
                uint32_t off = (uint32_t)((wy * 32 + mt * 16 + a_r) * SPAD + kk * 16 + a_c) * 2;
                ldsm_x4(ah[mt], sb + OFF_A + off);
            }
#pragma unroll
            for (int p = 0; p < 4; ++p) {
                uint32_t off = (uint32_t)((wx * 64 + p * 16 + b_r) * SPAD + kk * 16 + b_c) * 2;
                ldsm_x4(bh[p], sb + OFF_B + off);
            }
#pragma unroll
            for (int mt = 0; mt < 2; ++mt)
#pragma unroll
                for (int nt = 0; nt < 8; ++nt) {
                    const uint32_t bb[2] = { bh[nt >> 1][(nt & 1) * 2],
                                             bh[nt >> 1][(nt & 1) * 2 + 1] };
                    mma_f16(acc[mt][nt], ah[mt], bb);
                }
        }
    }

    const int rbase = row0 + wy * 32 + (lane >> 2);
    const int cbase = col0 + wx * 64 + ((lane & 3) << 1);
#pragma unroll
    for (int mt = 0; mt < 2; ++mt) {
        int rA = rbase + mt * 16, rB = rA + 8;
        float saA = g_sqA[rA], saB = g_sqA[rB];
#pragma unroll
        for (int nt = 0; nt < 8; ++nt) {
            int cc = cbase + nt * 8;
            float sb0 = g_sqB[cc], sb1 = g_sqB[cc + 1];
            float2 oA, oB;
            oA.x = sqrtf(fmaxf(saA + sb0 - 2.0f * acc[mt][nt][0], 1e-12f));
            oA.y = sqrtf(fmaxf(saA + sb1 - 2.0f * acc[mt][nt][1], 1e-12f));
            oB.x = sqrtf(fmaxf(saB + sb0 - 2.0f * acc[mt][nt][2], 1e-12f));
            oB.y = sqrtf(fmaxf(saB + sb1 - 2.0f * acc[mt][nt][3], 1e-12f));
            *(float2*)(g_cost + (size_t)rA * M_PIX + cc) = oA;
            *(float2*)(g_cost + (size_t)rB * M_PIX + cc) = oB;
        }
    }
}

// =====================================================================
// GEMM2+3 fused, single-term fp16. Flat grid: first 128 CTAs = GEMM2
// (K=9216, dispatched first), remaining 1152 = GEMM3 (K=1024).
//   GEMM2: out_text = T2 [n][m] x B2[l][m] * 2^-20
//   GEMM3: out_img  = A3 [l][n] x T3[m][n] * 2^-20
// =====================================================================
#define G2_BLOCKS 128                    // (L_DIM/128)*(N_TOK/128) = 16*8

__global__ void __launch_bounds__(256, 2) k_gemm23(float* __restrict__ out_text,
                                                   float* __restrict__ out_img) {
    extern __shared__ char sm[];
    const int bid = blockIdx.x;
    const bool isG2 = (bid < G2_BLOCKS);
    int bx, by;
    if (isG2) { bx = bid & 15; by = bid >> 4; }                 // 16 x 8
    else { int b = bid - G2_BLOCKS; bx = b % 72; by = b / 72; } // 72 x 16

    const __half *A_, *B_;
    int Ktot; float* out;
    if (isG2) { A_ = g_hT2; B_ = g_hB2; Ktot = M_PIX; out = out_text; }
    else      { A_ = g_hA3; B_ = g_hT3; Ktot = N_TOK; out = out_img; }

    const int tid = threadIdx.x, wid = tid >> 5, lane = tid & 31;
    const int wy = wid >> 1, wx = wid & 1;
    const int row0 = by * 128, col0 = bx * 128;
    const uint32_t smb = smem_to_u32(sm);

    float acc[2][8][4] = {};

    const int ld_r = tid >> 2, ld_c = (tid & 3) << 3;
    const int a_r = lane & 15, a_c = (lane >> 4) << 3;
    const int b_r = (lane & 7) + (((lane >> 4) & 1) << 3), b_c = ((lane >> 3) & 1) << 3;

    const int KCH = Ktot >> 5;

    auto issue = [&](int kc) {
        if (kc < KCH) {
            const int k0 = kc << 5;
            const uint32_t sb = smb + (kc % 3) * STAGE;
#pragma unroll
            for (int i = 0; i < 2; ++i) {
                int r = ld_r + i * 64;
                uint32_t so = (uint32_t)(r * SPAD + ld_c) * 2;
                cp16(sb + OFF_A + so, A_ + (size_t)(row0 + r) * Ktot + k0 + ld_c);
                cp16(sb + OFF_B + so, B_ + (size_t)(col0 + r) * Ktot + k0 + ld_c);
            }
        }
        cp_commit();
    };

    issue(0); issue(1);
    for (int kc = 0; kc < KCH; ++kc) {
        cp_wait<1>();
        __syncthreads();
        issue(kc + 2);
        const uint32_t sb = smb + (kc % 3) * STAGE;
#pragma unroll
        for (int kk = 0; kk < 2; ++kk) {
            uint32_t ah[2][4], bh[4][4];
#pragma unroll
            for (int mt = 0; mt < 2; ++mt) {
                uint32_t off = (uint32_t)((wy * 32 + mt * 16 + a_r) * SPAD + kk * 16 + a_c) * 2;
                ldsm_x4(ah[mt], sb + OFF_A + off);
            }
#pragma unroll
            for (int p = 0; p < 4; ++p) {
                uint32_t off = (uint32_t)((wx * 64 + p * 16 + b_r) * SPAD + kk * 16 + b_c) * 2;
                ldsm_x4(bh[p], sb + OFF_B + off);
            }
#pragma unroll
            for (int mt = 0; mt < 2; ++mt)
#pragma unroll
                for (int nt = 0; nt < 8; ++nt) {
                    const uint32_t bb[2] = { bh[nt >> 1][(nt & 1) * 2],
                                             bh[nt >> 1][(nt & 1) * 2 + 1] };
                    mma_f16(acc[mt][nt], ah[mt], bb);
                }
        }
    }

    // ---------------- epilogue (unscale T) ----------------
    const int rbase = row0 + wy * 32 + (lane >> 2);
    const int cbase = col0 + wx * 64 + ((lane & 3) << 1);
#pragma unroll
    for (int mt = 0; mt < 2; ++mt) {
        int rA = rbase + mt * 16, rB = rA + 8;
#pragma unroll
        for (int nt = 0; nt < 8; ++nt) {
            int cc = cbase + nt * 8;
            float d0 = acc[mt][nt][0] * TSCALE_INV, d1 = acc[mt][nt][1] * TSCALE_INV;
            float d2 = acc[mt][nt][2] * TSCALE_INV, d3 = acc[mt][nt][3] * TSCALE_INV;
            if (isG2) {
                int b = cc >> 8, c = cc & 255;   // col = l
                float* pA = out + (size_t)b * TEXT_B_STRIDE + (size_t)rA * C_DIM + c;
                float* pB = out + (size_t)b * TEXT_B_STRIDE + (size_t)rB * C_DIM + c;
                *(float2*)pA = make_float2(d0, d1);
                *(float2*)pB = make_float2(d2, d3);
            } else {
                *(float2*)(out + (size_t)rA * M_PIX + cc) = make_float2(d0, d1);
                *(float2*)(out + (size_t)rB * M_PIX + cc) = make_float2(d2, d3);
            }
        }
    }
}

// ---------------- Sinkhorn (persistent kernel, honest convergence break) ----------------
__device__ __forceinline__ void grid_barrier(unsigned e, int nctas) {
    __syncthreads();
    if (threadIdx.x == 0) {
        __threadfence();
        unsigned t = atomicAdd(&g_bar_count, 1u) + 1u;
        if (t == (unsigned)nctas * e) {
            atomicExch(&g_bar_gen, e);
        } else {
            while (*((volatile unsigned*)&g_bar_gen) < e) __nanosleep(64);
        }
        __threadfence();
    }
    __syncthreads();
}

__global__ void k_sinkhorn() {
    __shared__ float sred[256];
    const int cta = blockIdx.x;
    const int tid = threadIdx.x;
    const int NC = gridDim.x;
    unsigned epoch = 0;
    for (int it = 0; it < NITER; ++it) {
        for (int n = cta; n < N_TOK; n += NC) {
            const float* row = g_cost + (size_t)n * M_PIX;
            float s = 0.0f;
            for (int m = tid; m < M_PIX; m += 256)
                s += __expf(-10.0f * row[m]) * __ldcg(&g_v[m]);
            sred[tid] = s; __syncthreads();
            for (int off = 128; off > 0; off >>= 1) {
                if (tid < off) sred[tid] += sred[tid + off];
                __syncthreads();
            }
            if (tid == 0) {
                float un = 1.0f / (sred[0] + DENOM_SHIFT);
                float d = un - g_u[n];
                atomicAdd(&g_normU[it], d * d);
                g_u[n] = un;
            }
            __syncthreads();
        }
        ++epoch; grid_barrier(epoch, NC);
        for (int blk = cta; blk < (M_PIX / 64); blk += NC) {
            int col0 = blk * 64;
            int c = tid & 63, sl = tid >> 6;
            float t = 0.0f;
            for (int n = sl; n < N_TOK; n += 4)
                t += __expf(-10.0f * g_cost[(size_t)n * M_PIX + col0 + c]) * __ldcg(&g_u[n]);
            sred[tid] = t; __syncthreads();
            if (tid < 64) {
                float tt = sred[tid] + sred[tid + 64] + sred[tid + 128] + sred[tid + 192];
                int m = col0 + tid;
                float vn = 1.0f / (tt + DENOM_SHIFT);
                float d = vn - g_v[m];
                atomicAdd(&g_normV[it], d * d);
                g_v[m] = vn;
            }
            __syncthreads();
        }
        ++epoch; grid_barrier(epoch, NC);
        float nu = __ldcg(&g_normU[it]);
        float nv = __ldcg(&g_normV[it]);
        if (nu < CONV_TOL_SQ && nv < CONV_TOL_SQ) break;
    }
}

// ---------------- launch ----------------
extern "C" void kernel_launch(void* const* d_in, const int* in_sizes, int n_in,
                              void* d_out, int out_size) {
    const float* text  = (const float*)d_in[0];
    const float* image = (const float*)d_in[1];
    float* out_text = (float*)d_out;
    float* out_img  = out_text + (size_t)B_DIM * N_TOK * C_DIM;

    cudaFuncSetAttribute(k_gemm1, cudaFuncAttributeMaxDynamicSharedMemorySize, SMEM_GEMM);
    cudaFuncSetAttribute(k_gemm23, cudaFuncAttributeMaxDynamicSharedMemorySize, SMEM_GEMM);

    k_init<<<36, 256>>>();
    k_sq_text<<<N_TOK, 256>>>(text);
    k_sq_image<<<dim3(M_PIX / 256, L_DIM / 256), 256>>>(image);
    k_pack_text<<<dim3(C_DIM / 32, N_TOK / 32, B_DIM), dim3(32, 8)>>>(text);
    k_pack_image<<<dim3(M_PIX / 32, L_DIM / 32), dim3(32, 8)>>>(image);

    // GEMM1: cost (rows n: 8, cols m: 72), single-term fp16
    k_gemm1<<<dim3(M_PIX / 128, N_TOK / 128), 256, SMEM_GEMM>>>();

    k_sinkhorn<<<148, 256>>>();
    k_pack_T<<<dim3(M_PIX / 32, N_TOK / 32), dim3(32, 8)>>>();

    // GEMM2+3 fused: 128 long-K CTAs first, then 1152 short-K CTAs
    k_gemm23<<<G2_BLOCKS + 1152, 256, SMEM_GEMM>>>(out_text, out_img);
}

// round 12
// speedup vs baseline: 6.0163x; 1.2633x over previous
#include <cuda_runtime.h>
#include <cuda_fp16.h>
#include <cstdint>

// ---------------- problem dims ----------------
#define B_DIM 8
#define C_DIM 256
#define N_TOK 1024
#define M_PIX 9216
#define L_DIM 2048
#define TEXT_B_STRIDE  262144    // 1024*256
#define IMG_B_STRIDE   2359296   // 256*9216

#define NITER 50
#define CONV_TOL_SQ 1e-4f
#define DENOM_SHIFT 100.0f

// T pre-scale (exact power of two; keeps T in fp16 normal range)
#define TSCALE      1048576.0f          // 2^20
#define TSCALE_INV  9.5367431640625e-7f // 2^-20

// exp(-10*c) underflows fp32 normals for c > 8.73; contributions below are
// denormal-level (<6.8e-39) and vanish exactly against the +100 shift.
#define KEXP_CUT 8.8f

// ---------------- device scratch (statics; no mallocs) ----------------
__device__ float g_cost[(size_t)N_TOK * M_PIX];  // 37.75 MB
__device__ float g_sqA[N_TOK];
__device__ float g_sqB[M_PIX];
__device__ float g_u[N_TOK];
__device__ float g_v[M_PIX];
__device__ float g_normU[64];
__device__ float g_normV[64];
__device__ unsigned g_bar_count;
__device__ unsigned g_bar_gen;

// fp16 operand buffers (K-major), single plane each
__device__ __half g_hA1[(size_t)N_TOK * L_DIM];  // text  [n][l]
__device__ __half g_hB1[(size_t)M_PIX * L_DIM];  // image [m][l]
__device__ __half g_hT2[(size_t)N_TOK * M_PIX];  // T*2^20 [n][m]
__device__ __half g_hB2[(size_t)L_DIM * M_PIX];  // image [l][m]
__device__ __half g_hA3[(size_t)L_DIM * N_TOK];  // text  [l][n]
__device__ __half g_hT3[(size_t)M_PIX * N_TOK];  // T*2^20 [m][n]

// ---------------- helpers ----------------
__device__ __forceinline__ uint32_t smem_to_u32(const void* p) {
    uint32_t a;
    asm("{ .reg .u64 t; cvta.to.shared.u64 t, %1; cvt.u32.u64 %0, t; }" : "=r"(a) : "l"(p));
    return a;
}
__device__ __forceinline__ void ldsm_x4(uint32_t* r, uint32_t a) {
    asm volatile("ldmatrix.sync.aligned.m8n8.x4.shared.b16 {%0,%1,%2,%3}, [%4];"
                 : "=r"(r[0]), "=r"(r[1]), "=r"(r[2]), "=r"(r[3]) : "r"(a));
}
__device__ __forceinline__ void mma_f16(float* c, const uint32_t* a, const uint32_t* b) {
    asm volatile(
        "mma.sync.aligned.m16n8k16.row.col.f32.f16.f16.f32 "
        "{%0,%1,%2,%3}, {%4,%5,%6,%7}, {%8,%9}, {%0,%1,%2,%3};"
        : "+f"(c[0]), "+f"(c[1]), "+f"(c[2]), "+f"(c[3])
        : "r"(a[0]), "r"(a[1]), "r"(a[2]), "r"(a[3]), "r"(b[0]), "r"(b[1]));
}
__device__ __forceinline__ void cp16(uint32_t dst, const void* src) {
    asm volatile("cp.async.cg.shared.global [%0], [%1], 16;" :: "r"(dst), "l"(src));
}
__device__ __forceinline__ void cp_commit() {
    asm volatile("cp.async.commit_group;" ::: "memory");
}
template <int N>
__device__ __forceinline__ void cp_wait() {
    asm volatile("cp.async.wait_group %0;" :: "n"(N) : "memory");
}

// ---------------- init ----------------
__global__ void k_init() {
    int tid = blockIdx.x * blockDim.x + threadIdx.x;
    if (tid < N_TOK) g_u[tid] = 1.0f;
    if (tid < M_PIX) { g_v[tid] = 1.0f; g_sqB[tid] = 0.0f; }
    if (tid < 64) { g_normU[tid] = 0.0f; g_normV[tid] = 0.0f; }
    if (tid == 0) { g_bar_count = 0u; g_bar_gen = 0u; }
}

// ---------------- text squared norms ----------------
__global__ void k_sq_text(const float* __restrict__ text) {
    __shared__ float sh[256];
    int n = blockIdx.x, c = threadIdx.x;
    float s = 0.0f;
#pragma unroll
    for (int b = 0; b < B_DIM; ++b) {
        float x = text[(size_t)b * TEXT_B_STRIDE + (size_t)n * C_DIM + c];
        s += x * x;
    }
    sh[c] = s; __syncthreads();
    for (int off = 128; off > 0; off >>= 1) {
        if (c < off) sh[c] += sh[c + off];
        __syncthreads();
    }
    if (c == 0) g_sqA[n] = sh[0];
}

// ---------------- pack kernels (tiled smem transposes, fp16 single-plane) ----------------
__global__ void k_pack_text(const float* __restrict__ text) {
    __shared__ float t[32][33];
    int b = blockIdx.z, n0 = blockIdx.y * 32, c0 = blockIdx.x * 32;
    int tx = threadIdx.x, ty = threadIdx.y;
    for (int i = ty; i < 32; i += 8)
        t[i][tx] = text[(size_t)b * TEXT_B_STRIDE + (size_t)(n0 + i) * C_DIM + c0 + tx];
    __syncthreads();
    for (int i = ty; i < 32; i += 8) {
        size_t o = (size_t)(n0 + i) * L_DIM + b * C_DIM + c0 + tx;
        g_hA1[o] = __float2half_rn(t[i][tx]);
    }
    for (int i = ty; i < 32; i += 8) {
        size_t o = (size_t)(b * C_DIM + c0 + i) * N_TOK + n0 + tx;
        g_hA3[o] = __float2half_rn(t[tx][i]);
    }
}

// pack image + fused per-column squared-norm accumulation (saves a 75.5MB pass)
__global__ void k_pack_image(const float* __restrict__ image) {
    __shared__ float t[32][33];
    __shared__ float ss[8][33];
    int l0 = blockIdx.y * 32, m0 = blockIdx.x * 32;
    int tx = threadIdx.x, ty = threadIdx.y;
    for (int i = ty; i < 32; i += 8)
        t[i][tx] = image[(size_t)(l0 + i) * M_PIX + m0 + tx];
    __syncthreads();
    for (int i = ty; i < 32; i += 8) {
        size_t o = (size_t)(l0 + i) * M_PIX + m0 + tx;
        g_hB2[o] = __float2half_rn(t[i][tx]);
    }
    for (int i = ty; i < 32; i += 8) {
        size_t o = (size_t)(m0 + i) * L_DIM + l0 + tx;
        g_hB1[o] = __float2half_rn(t[tx][i]);
    }
    // sqB partial: sum over the 32 l's of this tile for each m
    float acc = 0.0f;
    for (int i = ty; i < 32; i += 8) { float x = t[i][tx]; acc += x * x; }
    ss[ty][tx] = acc;
    __syncthreads();
    if (ty == 0) {
        float s = 0.0f;
#pragma unroll
        for (int j = 0; j < 8; ++j) s += ss[j][tx];
        atomicAdd(&g_sqB[m0 + tx], s);
    }
}

__global__ void k_pack_T() {
    __shared__ float t[32][33];
    int n0 = blockIdx.y * 32, m0 = blockIdx.x * 32;
    int tx = threadIdx.x, ty = threadIdx.y;
    for (int i = ty; i < 32; i += 8) {
        float c = g_cost[(size_t)(n0 + i) * M_PIX + m0 + tx];
        t[i][tx] = expf(-0.1f * c) * g_u[n0 + i] * g_v[m0 + tx] * TSCALE;
    }
    __syncthreads();
    for (int i = ty; i < 32; i += 8) {
        size_t o = (size_t)(n0 + i) * M_PIX + m0 + tx;
        g_hT2[o] = __float2half_rn(t[i][tx]);
    }
    for (int i = ty; i < 32; i += 8) {
        size_t o = (size_t)(m0 + i) * N_TOK + n0 + tx;
        g_hT3[o] = __float2half_rn(t[tx][i]);
    }
}

// ---------------- GEMM geometry (all single-term fp16) ----------------
#define SPAD 40                      // 32 + 8 pad (80B row stride: conflict-free ldmatrix)
#define TILE_BYTES (128 * SPAD * 2)  // 10240 per operand tile
#define OFF_A 0
#define OFF_B (TILE_BYTES)
#define STAGE (2 * TILE_BYTES)       // 20480
#define SMEM_GEMM (3 * STAGE)        // 61440 -> 2 CTAs/SM

// =====================================================================
// GEMM1: cost[n,m] = sqrt(sqA+sqB-2*A.B); A=g_hA1[n][l], B=g_hB1[m][l], K=2048
// =====================================================================
__global__ void __launch_bounds__(256, 2) k_gemm1() {
    extern __shared__ char sm[];
    const int tid = threadIdx.x, wid = tid >> 5, lane = tid & 31;
    const int wy = wid >> 1, wx = wid & 1;   // warp tile 32(rows) x 64(cols)
    const int row0 = blockIdx.y * 128, col0 = blockIdx.x * 128;
    const uint32_t smb = smem_to_u32(sm);

    float acc[2][8][4] = {};

    const int ld_r = tid >> 2, ld_c = (tid & 3) << 3;
    const int a_r = lane & 15, a_c = (lane >> 4) << 3;
    const int b_r = (lane & 7) + (((lane >> 4) & 1) << 3), b_c = ((lane >> 3) & 1) << 3;

    const int KCH = L_DIM >> 5;

    auto issue = [&](int kc) {
        if (kc < KCH) {
            const int k0 = kc << 5;
            const uint32_t sb = smb + (kc % 3) * STAGE;
#pragma unroll
            for (int i = 0; i < 2; ++i) {
                int r = ld_r + i * 64;
                uint32_t so = (uint32_t)(r * SPAD + ld_c) * 2;
                cp16(sb + OFF_A + so, g_hA1 + (size_t)(row0 + r) * L_DIM + k0 + ld_c);
                cp16(sb + OFF_B + so, g_hB1 + (size_t)(col0 + r) * L_DIM + k0 + ld_c);
            }
        }
        cp_commit();
    };

    issue(0); issue(1);
    for (int kc = 0; kc < KCH; ++kc) {
        cp_wait<1>();
        __syncthreads();
        issue(kc + 2);
        const uint32_t sb = smb + (kc % 3) * STAGE;
#pragma unroll
        for (int kk = 0; kk < 2; ++kk) {
            uint32_t ah[2][4], bh[4][4];
#pragma unroll
            for (int mt = 0; mt < 2; ++mt) {
                uint32_t off = (uint32_t)((wy * 32 + mt * 16 + a_r) * SPAD + kk * 16 + a_c) * 2;
                ldsm_x4(ah[mt], sb + OFF_A + off);
            }
#pragma unroll
            for (int p = 0; p < 4; ++p) {
                uint32_t off = (uint32_t)((wx * 64 + p * 16 + b_r) * SPAD + kk * 16 + b_c) * 2;
                ldsm_x4(bh[p], sb + OFF_B + off);
            }
#pragma unroll
            for (int mt = 0; mt < 2; ++mt)
#pragma unroll
                for (int nt = 0; nt < 8; ++nt) {
                    const uint32_t bb[2] = { bh[nt >> 1][(nt & 1) * 2],
                                             bh[nt >> 1][(nt & 1) * 2 + 1] };
                    mma_f16(acc[mt][nt], ah[mt], bb);
                }
        }
    }

    const int rbase = row0 + wy * 32 + (lane >> 2);
    const int cbase = col0 + wx * 64 + ((lane & 3) << 1);
#pragma unroll
    for (int mt = 0; mt < 2; ++mt) {
        int rA = rbase + mt * 16, rB = rA + 8;
        float saA = g_sqA[rA], saB = g_sqA[rB];
#pragma unroll
        for (int nt = 0; nt < 8; ++nt) {
            int cc = cbase + nt * 8;
            float sb0 = g_sqB[cc], sb1 = g_sqB[cc + 1];
            float2 oA, oB;
            oA.x = sqrtf(fmaxf(saA + sb0 - 2.0f * acc[mt][nt][0], 1e-12f));
            oA.y = sqrtf(fmaxf(saA + sb1 - 2.0f * acc[mt][nt][1], 1e-12f));
            oB.x = sqrtf(fmaxf(saB + sb0 - 2.0f * acc[mt][nt][2], 1e-12f));
            oB.y = sqrtf(fmaxf(saB + sb1 - 2.0f * acc[mt][nt][3], 1e-12f));
            *(float2*)(g_cost + (size_t)rA * M_PIX + cc) = oA;
            *(float2*)(g_cost + (size_t)rB * M_PIX + cc) = oB;
        }
    }
}

// =====================================================================
// GEMM2+3 fused, single-term fp16. Flat grid: first 128 CTAs = GEMM2
// (K=9216, dispatched first), remaining 1152 = GEMM3 (K=1024).
// =====================================================================
#define G2_BLOCKS 128                    // (L_DIM/128)*(N_TOK/128) = 16*8

__global__ void __launch_bounds__(256, 2) k_gemm23(float* __restrict__ out_text,
                                                   float* __restrict__ out_img) {
    extern __shared__ char sm[];
    const int bid = blockIdx.x;
    const bool isG2 = (bid < G2_BLOCKS);
    int bx, by;
    if (isG2) { bx = bid & 15; by = bid >> 4; }                 // 16 x 8
    else { int b = bid - G2_BLOCKS; bx = b % 72; by = b / 72; } // 72 x 16

    const __half *A_, *B_;
    int Ktot; float* out;
    if (isG2) { A_ = g_hT2; B_ = g_hB2; Ktot = M_PIX; out = out_text; }
    else      { A_ = g_hA3; B_ = g_hT3; Ktot = N_TOK; out = out_img; }

    const int tid = threadIdx.x, wid = tid >> 5, lane = tid & 31;
    const int wy = wid >> 1, wx = wid & 1;
    const int row0 = by * 128, col0 = bx * 128;
    const uint32_t smb = smem_to_u32(sm);

    float acc[2][8][4] = {};

    const int ld_r = tid >> 2, ld_c = (tid & 3) << 3;
    const int a_r = lane & 15, a_c = (lane >> 4) << 3;
    const int b_r = (lane & 7) + (((lane >> 4) & 1) << 3), b_c = ((lane >> 3) & 1) << 3;

    const int KCH = Ktot >> 5;

    auto issue = [&](int kc) {
        if (kc < KCH) {
            const int k0 = kc << 5;
            const uint32_t sb = smb + (kc % 3) * STAGE;
#pragma unroll
            for (int i = 0; i < 2; ++i) {
                int r = ld_r + i * 64;
                uint32_t so = (uint32_t)(r * SPAD + ld_c) * 2;
                cp16(sb + OFF_A + so, A_ + (size_t)(row0 + r) * Ktot + k0 + ld_c);
                cp16(sb + OFF_B + so, B_ + (size_t)(col0 + r) * Ktot + k0 + ld_c);
            }
        }
        cp_commit();
    };

    issue(0); issue(1);
    for (int kc = 0; kc < KCH; ++kc) {
        cp_wait<1>();
        __syncthreads();
        issue(kc + 2);
        const uint32_t sb = smb + (kc % 3) * STAGE;
#pragma unroll
        for (int kk = 0; kk < 2; ++kk) {
            uint32_t ah[2][4], bh[4][4];
#pragma unroll
            for (int mt = 0; mt < 2; ++mt) {
                uint32_t off = (uint32_t)((wy * 32 + mt * 16 + a_r) * SPAD + kk * 16 + a_c) * 2;
                ldsm_x4(ah[mt], sb + OFF_A + off);
            }
#pragma unroll
            for (int p = 0; p < 4; ++p) {
                uint32_t off = (uint32_t)((wx * 64 + p * 16 + b_r) * SPAD + kk * 16 + b_c) * 2;
                ldsm_x4(bh[p], sb + OFF_B + off);
            }
#pragma unroll
            for (int mt = 0; mt < 2; ++mt)
#pragma unroll
                for (int nt = 0; nt < 8; ++nt) {
                    const uint32_t bb[2] = { bh[nt >> 1][(nt & 1) * 2],
                                             bh[nt >> 1][(nt & 1) * 2 + 1] };
                    mma_f16(acc[mt][nt], ah[mt], bb);
                }
        }
    }

    // ---------------- epilogue (unscale T) ----------------
    const int rbase = row0 + wy * 32 + (lane >> 2);
    const int cbase = col0 + wx * 64 + ((lane & 3) << 1);
#pragma unroll
    for (int mt = 0; mt < 2; ++mt) {
        int rA = rbase + mt * 16, rB = rA + 8;
#pragma unroll
        for (int nt = 0; nt < 8; ++nt) {
            int cc = cbase + nt * 8;
            float d0 = acc[mt][nt][0] * TSCALE_INV, d1 = acc[mt][nt][1] * TSCALE_INV;
            float d2 = acc[mt][nt][2] * TSCALE_INV, d3 = acc[mt][nt][3] * TSCALE_INV;
            if (isG2) {
                int b = cc >> 8, c = cc & 255;   // col = l
                float* pA = out + (size_t)b * TEXT_B_STRIDE + (size_t)rA * C_DIM + c;
                float* pB = out + (size_t)b * TEXT_B_STRIDE + (size_t)rB * C_DIM + c;
                *(float2*)pA = make_float2(d0, d1);
                *(float2*)pB = make_float2(d2, d3);
            } else {
                *(float2*)(out + (size_t)rA * M_PIX + cc) = make_float2(d0, d1);
                *(float2*)(out + (size_t)rB * M_PIX + cc) = make_float2(d2, d3);
            }
        }
    }
}

// ---------------- Sinkhorn (persistent; float4 + exact underflow fast path) ----------------
__device__ __forceinline__ void grid_barrier(unsigned e, int nctas) {
    __syncthreads();
    if (threadIdx.x == 0) {
        __threadfence();
        unsigned t = atomicAdd(&g_bar_count, 1u) + 1u;
        if (t == (unsigned)nctas * e) {
            atomicExch(&g_bar_gen, e);
        } else {
            while (*((volatile unsigned*)&g_bar_gen) < e) __nanosleep(64);
        }
        __threadfence();
    }
    __syncthreads();
}

__global__ void k_sinkhorn() {
    __shared__ float4 sred4[256];
    float* sred = (float*)sred4;
    const int cta = blockIdx.x;
    const int tid = threadIdx.x;
    const int NC = gridDim.x;
    unsigned epoch = 0;
    for (int it = 0; it < NITER; ++it) {
        // ---- U phase: un = 1/(sum_m K[n,m]*v[m] + 100) ----
        for (int n = cta; n < N_TOK; n += NC) {
            const float* row = g_cost + (size_t)n * M_PIX;
            float s = 0.0f;
            for (int m = tid << 2; m < M_PIX; m += 1024) {
                float4 c4 = *(const float4*)(row + m);
                if (c4.x <= KEXP_CUT || c4.y <= KEXP_CUT ||
                    c4.z <= KEXP_CUT || c4.w <= KEXP_CUT) {
                    float4 v4 = __ldcg((const float4*)(g_v + m));
                    s += __expf(-10.0f * c4.x) * v4.x + __expf(-10.0f * c4.y) * v4.y
                       + __expf(-10.0f * c4.z) * v4.z + __expf(-10.0f * c4.w) * v4.w;
                }
            }
            sred[tid] = s; __syncthreads();
            for (int off = 128; off > 0; off >>= 1) {
                if (tid < off) sred[tid] += sred[tid + off];
                __syncthreads();
            }
            if (tid == 0) {
                float un = 1.0f / (sred[0] + DENOM_SHIFT);
                float d = un - __ldcg(&g_u[n]);
                atomicAdd(&g_normU[it], d * d);
                g_u[n] = un;
            }
            __syncthreads();
        }
        ++epoch; grid_barrier(epoch, NC);
        // ---- V phase: vn = 1/(sum_n K[n,m]*u[n] + 100) ----
        for (int blk = cta; blk < (M_PIX / 64); blk += NC) {
            const int col0 = blk * 64;
            const int cg = (tid & 15) << 2;   // col group (4 cols)
            const int sl = tid >> 4;          // n slice (16)
            float4 t4 = make_float4(0.f, 0.f, 0.f, 0.f);
            for (int n = sl; n < N_TOK; n += 16) {
                float4 c4 = *(const float4*)(g_cost + (size_t)n * M_PIX + col0 + cg);
                if (c4.x <= KEXP_CUT || c4.y <= KEXP_CUT ||
                    c4.z <= KEXP_CUT || c4.w <= KEXP_CUT) {
                    float un = __ldcg(&g_u[n]);
                    t4.x += __expf(-10.0f * c4.x) * un;
                    t4.y += __expf(-10.0f * c4.y) * un;
                    t4.z += __expf(-10.0f * c4.z) * un;
                    t4.w += __expf(-10.0f * c4.w) * un;
                }
            }
            sred4[tid] = t4; __syncthreads();
            if (tid < 16) {
                float4 a = sred4[tid];
#pragma unroll
                for (int j = 1; j < 16; ++j) {
                    float4 b = sred4[tid + j * 16];
                    a.x += b.x; a.y += b.y; a.z += b.z; a.w += b.w;
                }
                const int m = col0 + (tid << 2);
                float vs[4] = { a.x, a.y, a.z, a.w };
                float nacc = 0.0f;
#pragma unroll
                for (int j = 0; j < 4; ++j) {
                    float vn = 1.0f / (vs[j] + DENOM_SHIFT);
                    float d = vn - __ldcg(&g_v[m + j]);
                    nacc += d * d;
                    g_v[m + j] = vn;
                }
                atomicAdd(&g_normV[it], nacc);
            }
            __syncthreads();
        }
        ++epoch; grid_barrier(epoch, NC);
        float nu = __ldcg(&g_normU[it]);
        float nv = __ldcg(&g_normV[it]);
        if (nu < CONV_TOL_SQ && nv < CONV_TOL_SQ) break;
    }
}

// ---------------- launch ----------------
extern "C" void kernel_launch(void* const* d_in, const int* in_sizes, int n_in,
                              void* d_out, int out_size) {
    const float* text  = (const float*)d_in[0];
    const float* image = (const float*)d_in[1];
    float* out_text = (float*)d_out;
    float* out_img  = out_text + (size_t)B_DIM * N_TOK * C_DIM;

    cudaFuncSetAttribute(k_gemm1, cudaFuncAttributeMaxDynamicSharedMemorySize, SMEM_GEMM);
    cudaFuncSetAttribute(k_gemm23, cudaFuncAttributeMaxDynamicSharedMemorySize, SMEM_GEMM);

    k_init<<<36, 256>>>();
    k_sq_text<<<N_TOK, 256>>>(text);
    k_pack_text<<<dim3(C_DIM / 32, N_TOK / 32, B_DIM), dim3(32, 8)>>>(text);
    k_pack_image<<<dim3(M_PIX / 32, L_DIM / 32), dim3(32, 8)>>>(image);

    // GEMM1: cost (rows n: 8, cols m: 72), single-term fp16
    k_gemm1<<<dim3(M_PIX / 128, N_TOK / 128), 256, SMEM_GEMM>>>();

    k_sinkhorn<<<148, 256>>>();
    k_pack_T<<<dim3(M_PIX / 32, N_TOK / 32), dim3(32, 8)>>>();

    // GEMM2+3 fused: 128 long-K CTAs first, then 1152 short-K CTAs
    k_gemm23<<<G2_BLOCKS + 1152, 256, SMEM_GEMM>>>(out_text, out_img);
}

// round 13
// speedup vs baseline: 6.4177x; 1.0667x over previous
#include <cuda_runtime.h>
#include <cuda_fp16.h>
#include <cstdint>

// ---------------- problem dims ----------------
#define B_DIM 8
#define C_DIM 256
#define N_TOK 1024
#define M_PIX 9216
#define L_DIM 2048
#define TEXT_B_STRIDE  262144    // 1024*256
#define IMG_B_STRIDE   2359296   // 256*9216

#define NITER 50
#define CONV_TOL_SQ 1e-4f
#define DENOM_SHIFT 100.0f

// T pre-scale (exact power of two; keeps T in fp16 normal range)
#define TSCALE      1048576.0f          // 2^20
#define TSCALE_INV  9.5367431640625e-7f // 2^-20

// exp(-10*c) underflows fp32 normals for c > 8.73; contributions below are
// denormal-level (<6.8e-39) and vanish exactly against the +100 shift.
#define KEXP_CUT 8.8f

// ---------------- device scratch (statics; no mallocs) ----------------
__device__ float g_cost[(size_t)N_TOK * M_PIX];  // 37.75 MB
__device__ float g_sqA[N_TOK];
__device__ float g_sqB[M_PIX];
__device__ float g_u[N_TOK];
__device__ float g_v[M_PIX];
__device__ float g_normU[64];
__device__ float g_normV[64];
__device__ unsigned g_bar_count;
__device__ unsigned g_bar_gen;

// fp16 operand buffers (K-major), single plane each
__device__ __half g_hA1[(size_t)N_TOK * L_DIM];  // text  [n][l]
__device__ __half g_hB1[(size_t)M_PIX * L_DIM];  // image [m][l]; reused as fp32
                                                 // split-K scratch after GEMM1
__device__ __half g_hT2[(size_t)N_TOK * M_PIX];  // T*2^20 [n][m]
__device__ __half g_hB2[(size_t)L_DIM * M_PIX];  // image [l][m]
__device__ __half g_hA3[(size_t)L_DIM * N_TOK];  // text  [l][n]
__device__ __half g_hT3[(size_t)M_PIX * N_TOK];  // T*2^20 [m][n]

// ---------------- helpers ----------------
__device__ __forceinline__ uint32_t smem_to_u32(const void* p) {
    uint32_t a;
    asm("{ .reg .u64 t; cvta.to.shared.u64 t, %1; cvt.u32.u64 %0, t; }" : "=r"(a) : "l"(p));
    return a;
}
__device__ __forceinline__ void ldsm_x4(uint32_t* r, uint32_t a) {
    asm volatile("ldmatrix.sync.aligned.m8n8.x4.shared.b16 {%0,%1,%2,%3}, [%4];"
                 : "=r"(r[0]), "=r"(r[1]), "=r"(r[2]), "=r"(r[3]) : "r"(a));
}
__device__ __forceinline__ void mma_f16(float* c, const uint32_t* a, const uint32_t* b) {
    asm volatile(
        "mma.sync.aligned.m16n8k16.row.col.f32.f16.f16.f32 "
        "{%0,%1,%2,%3}, {%4,%5,%6,%7}, {%8,%9}, {%0,%1,%2,%3};"
        : "+f"(c[0]), "+f"(c[1]), "+f"(c[2]), "+f"(c[3])
        : "r"(a[0]), "r"(a[1]), "r"(a[2]), "r"(a[3]), "r"(b[0]), "r"(b[1]));
}
__device__ __forceinline__ void cp16(uint32_t dst, const void* src) {
    asm volatile("cp.async.cg.shared.global [%0], [%1], 16;" :: "r"(dst), "l"(src));
}
__device__ __forceinline__ void cp_commit() {
    asm volatile("cp.async.commit_group;" ::: "memory");
}
template <int N>
__device__ __forceinline__ void cp_wait() {
    asm volatile("cp.async.wait_group %0;" :: "n"(N) : "memory");
}
__device__ __forceinline__ uint32_t pack2h(float a, float b) {
    __half2 h = __floats2half2_rn(a, b);
    return *(uint32_t*)&h;
}

// ---------------- init ----------------
__global__ void k_init() {
    int tid = blockIdx.x * blockDim.x + threadIdx.x;
    if (tid < N_TOK) g_u[tid] = 1.0f;
    if (tid < M_PIX) { g_v[tid] = 1.0f; g_sqB[tid] = 0.0f; }
    if (tid < 64) { g_normU[tid] = 0.0f; g_normV[tid] = 0.0f; }
    if (tid == 0) { g_bar_count = 0u; g_bar_gen = 0u; }
}

// ---------------- text squared norms ----------------
__global__ void k_sq_text(const float* __restrict__ text) {
    __shared__ float sh[256];
    int n = blockIdx.x, c = threadIdx.x;
    float s = 0.0f;
#pragma unroll
    for (int b = 0; b < B_DIM; ++b) {
        float x = text[(size_t)b * TEXT_B_STRIDE + (size_t)n * C_DIM + c];
        s += x * x;
    }
    sh[c] = s; __syncthreads();
    for (int off = 128; off > 0; off >>= 1) {
        if (c < off) sh[c] += sh[c + off];
        __syncthreads();
    }
    if (c == 0) g_sqA[n] = sh[0];
}

// ---------------- vectorized pack kernels ----------------
// 32x32 float tile, 256 flat threads: r = tid>>3 (row 0-31), c4 = (tid&7)*4.
// Loads float4; straight stores uint2 (4 halves) from registers; transposed
// stores uint2 gathered from smem columns (conflict-free: bank = (r+c) mod 32).

__global__ void k_pack_text(const float* __restrict__ text) {
    __shared__ float t[32][33];
    const int b = blockIdx.z, n0 = blockIdx.y * 32, c0 = blockIdx.x * 32;
    const int tid = threadIdx.x, r = tid >> 3, c4 = (tid & 7) << 2;
    float4 v = *(const float4*)(text + (size_t)b * TEXT_B_STRIDE +
                                (size_t)(n0 + r) * C_DIM + c0 + c4);
    t[r][c4] = v.x; t[r][c4 + 1] = v.y; t[r][c4 + 2] = v.z; t[r][c4 + 3] = v.w;
    // straight: g_hA1[n][l], l = b*256 + c
    uint2 s1; s1.x = pack2h(v.x, v.y); s1.y = pack2h(v.z, v.w);
    *(uint2*)(g_hA1 + (size_t)(n0 + r) * L_DIM + b * C_DIM + c0 + c4) = s1;
    __syncthreads();
    // transposed: g_hA3[l][n], row i = c-dim, col j4 = n-dim
    uint2 s2;
    s2.x = pack2h(t[c4][r], t[c4 + 1][r]);
    s2.y = pack2h(t[c4 + 2][r], t[c4 + 3][r]);
    *(uint2*)(g_hA3 + (size_t)(b * C_DIM + c0 + r) * N_TOK + n0 + c4) = s2;
}

// pack image + fused per-column sqB accumulation
__global__ void k_pack_image(const float* __restrict__ image) {
    __shared__ float t[32][33];
    __shared__ float ss[8][33];
    const int l0 = blockIdx.y * 32, m0 = blockIdx.x * 32;
    const int tid = threadIdx.x, r = tid >> 3, c4 = (tid & 7) << 2;
    float4 v = *(const float4*)(image + (size_t)(l0 + r) * M_PIX + m0 + c4);
    t[r][c4] = v.x; t[r][c4 + 1] = v.y; t[r][c4 + 2] = v.z; t[r][c4 + 3] = v.w;
    // straight: g_hB2[l][m]
    uint2 s1; s1.x = pack2h(v.x, v.y); s1.y = pack2h(v.z, v.w);
    *(uint2*)(g_hB2 + (size_t)(l0 + r) * M_PIX + m0 + c4) = s1;
    __syncthreads();
    // transposed: g_hB1[m][l]
    uint2 s2;
    s2.x = pack2h(t[c4][r], t[c4 + 1][r]);
    s2.y = pack2h(t[c4 + 2][r], t[c4 + 3][r]);
    *(uint2*)(g_hB1 + (size_t)(m0 + r) * L_DIM + l0 + c4) = s2;
    // sqB partials: column sums over the 32 l's of this tile
    {
        const int c = tid & 31, part = tid >> 5;
        float s = 0.0f;
#pragma unroll
        for (int k = 0; k < 4; ++k) s += t[part * 4 + k][c] * t[part * 4 + k][c];
        ss[part][c] = s;
    }
    __syncthreads();
    if (tid < 32) {
        float s = 0.0f;
#pragma unroll
        for (int j = 0; j < 8; ++j) s += ss[j][tid];
        atomicAdd(&g_sqB[m0 + tid], s);
    }
}

__global__ void k_pack_T() {
    __shared__ float t[32][33];
    const int n0 = blockIdx.y * 32, m0 = blockIdx.x * 32;
    const int tid = threadIdx.x, r = tid >> 3, c4 = (tid & 7) << 2;
    float4 c = *(const float4*)(g_cost + (size_t)(n0 + r) * M_PIX + m0 + c4);
    float4 v4 = *(const float4*)(g_v + m0 + c4);
    const float us = g_u[n0 + r] * TSCALE;
    float4 w;
    w.x = expf(-0.1f * c.x) * us * v4.x;
    w.y = expf(-0.1f * c.y) * us * v4.y;
    w.z = expf(-0.1f * c.z) * us * v4.z;
    w.w = expf(-0.1f * c.w) * us * v4.w;
    t[r][c4] = w.x; t[r][c4 + 1] = w.y; t[r][c4 + 2] = w.z; t[r][c4 + 3] = w.w;
    uint2 s1; s1.x = pack2h(w.x, w.y); s1.y = pack2h(w.z, w.w);
    *(uint2*)(g_hT2 + (size_t)(n0 + r) * M_PIX + m0 + c4) = s1;
    __syncthreads();
    uint2 s2;
    s2.x = pack2h(t[c4][r], t[c4 + 1][r]);
    s2.y = pack2h(t[c4 + 2][r], t[c4 + 3][r]);
    *(uint2*)(g_hT3 + (size_t)(m0 + r) * N_TOK + n0 + c4) = s2;
}

// ---------------- GEMM geometry (all single-term fp16) ----------------
#define SPAD 40                      // 32 + 8 pad (80B row stride: conflict-free ldmatrix)
#define TILE_BYTES (128 * SPAD * 2)  // 10240 per operand tile
#define OFF_A 0
#define OFF_B (TILE_BYTES)
#define STAGE (2 * TILE_BYTES)       // 20480
#define SMEM_GEMM (3 * STAGE)        // 61440 -> 2 CTAs/SM

// =====================================================================
// GEMM1: cost[n,m] = sqrt(sqA+sqB-2*A.B); A=g_hA1[n][l], B=g_hB1[m][l], K=2048
// =====================================================================
__global__ void __launch_bounds__(256, 2) k_gemm1() {
    extern __shared__ char sm[];
    const int tid = threadIdx.x, wid = tid >> 5, lane = tid & 31;
    const int wy = wid >> 1, wx = wid & 1;   // warp tile 32(rows) x 64(cols)
    const int row0 = blockIdx.y * 128, col0 = blockIdx.x * 128;
    const uint32_t smb = smem_to_u32(sm);

    float acc[2][8][4] = {};

    const int ld_r = tid >> 2, ld_c = (tid & 3) << 3;
    const int a_r = lane & 15, a_c = (lane >> 4) << 3;
    const int b_r = (lane & 7) + (((lane >> 4) & 1) << 3), b_c = ((lane >> 3) & 1) << 3;

    const int KCH = L_DIM >> 5;

    auto issue = [&](int kc) {
        if (kc < KCH) {
            const int k0 = kc << 5;
            const uint32_t sb = smb + (kc % 3) * STAGE;
#pragma unroll
            for (int i = 0; i < 2; ++i) {
                int r = ld_r + i * 64;
                uint32_t so = (uint32_t)(r * SPAD + ld_c) * 2;
                cp16(sb + OFF_A + so, g_hA1 + (size_t)(row0 + r) * L_DIM + k0 + ld_c);
                cp16(sb + OFF_B + so, g_hB1 + (size_t)(col0 + r) * L_DIM + k0 + ld_c);
            }
        }
        cp_commit();
    };

    issue(0); issue(1);
    for (int kc = 0; kc < KCH; ++kc) {
        cp_wait<1>();
        __syncthreads();
        issue(kc + 2);
        const uint32_t sb = smb + (kc % 3) * STAGE;
#pragma unroll
        for (int kk = 0; kk < 2; ++kk) {
            uint32_t ah[2][4], bh[4][4];
#pragma unroll
            for (int mt = 0; mt < 2; ++mt) {
                uint32_t off = (uint32_t)((wy * 32 + mt * 16 + a_r) * SPAD + kk * 16 + a_c) * 2;
                ldsm_x4(ah[mt], sb + OFF_A + off);
            }
#pragma unroll
            for (int p = 0; p < 4; ++p) {
                uint32_t off = (uint32_t)((wx * 64 + p * 16 + b_r) * SPAD + kk * 16 + b_c) * 2;
                ldsm_x4(bh[p], sb + OFF_B + off);
            }
#pragma unroll
            for (int mt = 0; mt < 2; ++mt)
#pragma unroll
                for (int nt = 0; nt < 8; ++nt) {
                    const uint32_t bb[2] = { bh[nt >> 1][(nt & 1) * 2],
                                             bh[nt >> 1][(nt & 1) * 2 + 1] };
                    mma_f16(acc[mt][nt], ah[mt], bb);
                }
        }
    }

    const int rbase = row0 + wy * 32 + (lane >> 2);
    const int cbase = col0 + wx * 64 + ((lane & 3) << 1);
#pragma unroll
    for (int mt = 0; mt < 2; ++mt) {
        int rA = rbase + mt * 16, rB = rA + 8;
        float saA = g_sqA[rA], saB = g_sqA[rB];
#pragma unroll
        for (int nt = 0; nt < 8; ++nt) {
            int cc = cbase + nt * 8;
            float sb0 = g_sqB[cc], sb1 = g_sqB[cc + 1];
            float2 oA, oB;
            oA.x = sqrtf(fmaxf(saA + sb0 - 2.0f * acc[mt][nt][0], 1e-12f));
            oA.y = sqrtf(fmaxf(saA + sb1 - 2.0f * acc[mt][nt][1], 1e-12f));
            oB.x = sqrtf(fmaxf(saB + sb0 - 2.0f * acc[mt][nt][2], 1e-12f));
            oB.y = sqrtf(fmaxf(saB + sb1 - 2.0f * acc[mt][nt][3], 1e-12f));
            *(float2*)(g_cost + (size_t)rA * M_PIX + cc) = oA;
            *(float2*)(g_cost + (size_t)rB * M_PIX + cc) = oB;
        }
    }
}

// =====================================================================
// GEMM2+3 fused, single-term fp16, split-K=2 on GEMM2 for tail balance.
// Grid: bids [0,256) = GEMM2 (K=9216 halved: 144 kc each; ks=bid>>7),
//       bids [256,1408) = GEMM3 (K=1024, 32 kc).
// GEMM2 ks=0 -> out_text, ks=1 -> fp32 scratch (reused g_hB1); combined after.
// =====================================================================
#define G2_BLOCKS 256
#define G2_KCH_HALF 144

__global__ void __launch_bounds__(256, 2) k_gemm23(float* __restrict__ out_text,
                                                   float* __restrict__ out_img) {
    extern __shared__ char sm[];
    const int bid = blockIdx.x;
    const bool isG2 = (bid < G2_BLOCKS);
    int bx, by, ks = 0;
    if (isG2) { int b2 = bid & 127; bx = b2 & 15; by = b2 >> 4; ks = bid >> 7; } // 16x8 x2
    else { int b = bid - G2_BLOCKS; bx = b % 72; by = b / 72; }                  // 72x16

    const __half *A_, *B_;
    int Ktot; float* out;
    if (isG2) {
        A_ = g_hT2; B_ = g_hB2; Ktot = M_PIX;
        out = ks ? (float*)g_hB1 : out_text;
    } else { A_ = g_hA3; B_ = g_hT3; Ktot = N_TOK; out = out_img; }

    const int tid = threadIdx.x, wid = tid >> 5, lane = tid & 31;
    const int wy = wid >> 1, wx = wid & 1;
    const int row0 = by * 128, col0 = bx * 128;
    const uint32_t smb = smem_to_u32(sm);

    float acc[2][8][4] = {};

    const int ld_r = tid >> 2, ld_c = (tid & 3) << 3;
    const int a_r = lane & 15, a_c = (lane >> 4) << 3;
    const int b_r = (lane & 7) + (((lane >> 4) & 1) << 3), b_c = ((lane >> 3) & 1) << 3;

    const int kc_beg = isG2 ? ks * G2_KCH_HALF : 0;
    const int kc_end = isG2 ? kc_beg + G2_KCH_HALF : (Ktot >> 5);

    auto issue = [&](int kc) {
        if (kc < kc_end) {
            const int k0 = kc << 5;
            const uint32_t sb = smb + (kc % 3) * STAGE;
#pragma unroll
            for (int i = 0; i < 2; ++i) {
                int r = ld_r + i * 64;
                uint32_t so = (uint32_t)(r * SPAD + ld_c) * 2;
                cp16(sb + OFF_A + so, A_ + (size_t)(row0 + r) * Ktot + k0 + ld_c);
                cp16(sb + OFF_B + so, B_ + (size_t)(col0 + r) * Ktot + k0 + ld_c);
            }
        }
        cp_commit();
    };

    issue(kc_beg); issue(kc_beg + 1);
    for (int kc = kc_beg; kc < kc_end; ++kc) {
        cp_wait<1>();
        __syncthreads();
        issue(kc + 2);
        const uint32_t sb = smb + (kc % 3) * STAGE;
#pragma unroll
        for (int kk = 0; kk < 2; ++kk) {
            uint32_t ah[2][4], bh[4][4];
#pragma unroll
            for (int mt = 0; mt < 2; ++mt) {
                uint32_t off = (uint32_t)((wy * 32 + mt * 16 + a_r) * SPAD + kk * 16 + a_c) * 2;
                ldsm_x4(ah[mt], sb + OFF_A + off);
            }
#pragma unroll
            for (int p = 0; p < 4; ++p) {
                uint32_t off = (uint32_t)((wx * 64 + p * 16 + b_r) * SPAD + kk * 16 + b_c) * 2;
                ldsm_x4(bh[p], sb + OFF_B + off);
            }
#pragma unroll
            for (int mt = 0; mt < 2; ++mt)
#pragma unroll
                for (int nt = 0; nt < 8; ++nt) {
                    const uint32_t bb[2] = { bh[nt >> 1][(nt & 1) * 2],
                                             bh[nt >> 1][(nt & 1) * 2 + 1] };
                    mma_f16(acc[mt][nt], ah[mt], bb);
                }
        }
    }

    // ---------------- epilogue (unscale T) ----------------
    const int rbase = row0 + wy * 32 + (lane >> 2);
    const int cbase = col0 + wx * 64 + ((lane & 3) << 1);
#pragma unroll
    for (int mt = 0; mt < 2; ++mt) {
        int rA = rbase + mt * 16, rB = rA + 8;
#pragma unroll
        for (int nt = 0; nt < 8; ++nt) {
            int cc = cbase + nt * 8;
            float d0 = acc[mt][nt][0] * TSCALE_INV, d1 = acc[mt][nt][1] * TSCALE_INV;
            float d2 = acc[mt][nt][2] * TSCALE_INV, d3 = acc[mt][nt][3] * TSCALE_INV;
            if (isG2) {
                // scratch uses the same [b][n][c] layout as out_text
                int b = cc >> 8, c = cc & 255;   // col = l
                float* pA = out + (size_t)b * TEXT_B_STRIDE + (size_t)rA * C_DIM + c;
                float* pB = out + (size_t)b * TEXT_B_STRIDE + (size_t)rB * C_DIM + c;
                *(float2*)pA = make_float2(d0, d1);
                *(float2*)pB = make_float2(d2, d3);
            } else {
                *(float2*)(out + (size_t)rA * M_PIX + cc) = make_float2(d0, d1);
                *(float2*)(out + (size_t)rB * M_PIX + cc) = make_float2(d2, d3);
            }
        }
    }
}

// combine split-K halves: out_text += scratch (deterministic, no atomics)
__global__ void k_combine(float* __restrict__ out_text) {
    const float* scr = (const float*)g_hB1;
    size_t i = ((size_t)blockIdx.x * 256 + threadIdx.x) * 4;
    float4 o = *(float4*)(out_text + i);
    float4 s = *(const float4*)(scr + i);
    o.x += s.x; o.y += s.y; o.z += s.z; o.w += s.w;
    *(float4*)(out_text + i) = o;
}

// ---------------- Sinkhorn (persistent; float4 + exact underflow fast path) ----------------
__device__ __forceinline__ void grid_barrier(unsigned e, int nctas) {
    __syncthreads();
    if (threadIdx.x == 0) {
        __threadfence();
        unsigned t = atomicAdd(&g_bar_count, 1u) + 1u;
        if (t == (unsigned)nctas * e) {
            atomicExch(&g_bar_gen, e);
        } else {
            while (*((volatile unsigned*)&g_bar_gen) < e) __nanosleep(64);
        }
        __threadfence();
    }
    __syncthreads();
}

__global__ void k_sinkhorn() {
    __shared__ float4 sred4[256];
    float* sred = (float*)sred4;
    const int cta = blockIdx.x;
    const int tid = threadIdx.x;
    const int NC = gridDim.x;
    unsigned epoch = 0;
    for (int it = 0; it < NITER; ++it) {
        // ---- U phase ----
        for (int n = cta; n < N_TOK; n += NC) {
            const float* row = g_cost + (size_t)n * M_PIX;
            float s = 0.0f;
            for (int m = tid << 2; m < M_PIX; m += 1024) {
                float4 c4 = *(const float4*)(row + m);
                if (c4.x <= KEXP_CUT || c4.y <= KEXP_CUT ||
                    c4.z <= KEXP_CUT || c4.w <= KEXP_CUT) {
                    float4 v4 = __ldcg((const float4*)(g_v + m));
                    s += __expf(-10.0f * c4.x) * v4.x + __expf(-10.0f * c4.y) * v4.y
                       + __expf(-10.0f * c4.z) * v4.z + __expf(-10.0f * c4.w) * v4.w;
                }
            }
            sred[tid] = s; __syncthreads();
            for (int off = 128; off > 0; off >>= 1) {
                if (tid < off) sred[tid] += sred[tid + off];
                __syncthreads();
            }
            if (tid == 0) {
                float un = 1.0f / (sred[0] + DENOM_SHIFT);
                float d = un - __ldcg(&g_u[n]);
                atomicAdd(&g_normU[it], d * d);
                g_u[n] = un;
            }
            __syncthreads();
        }
        ++epoch; grid_barrier(epoch, NC);
        // ---- V phase ----
        for (int blk = cta; blk < (M_PIX / 64); blk += NC) {
            const int col0 = blk * 64;
            const int cg = (tid & 15) << 2;
            const int sl = tid >> 4;
            float4 t4 = make_float4(0.f, 0.f, 0.f, 0.f);
            for (int n = sl; n < N_TOK; n += 16) {
                float4 c4 = *(const float4*)(g_cost + (size_t)n * M_PIX + col0 + cg);
                if (c4.x <= KEXP_CUT || c4.y <= KEXP_CUT ||
                    c4.z <= KEXP_CUT || c4.w <= KEXP_CUT) {
                    float un = __ldcg(&g_u[n]);
                    t4.x += __expf(-10.0f * c4.x) * un;
                    t4.y += __expf(-10.0f * c4.y) * un;
                    t4.z += __expf(-10.0f * c4.z) * un;
                    t4.w += __expf(-10.0f * c4.w) * un;
                }
            }
            sred4[tid] = t4; __syncthreads();
            if (tid < 16) {
                float4 a = sred4[tid];
#pragma unroll
                for (int j = 1; j < 16; ++j) {
                    float4 b = sred4[tid + j * 16];
                    a.x += b.x; a.y += b.y; a.z += b.z; a.w += b.w;
                }
                const int m = col0 + (tid << 2);
                float vs[4] = { a.x, a.y, a.z, a.w };
                float nacc = 0.0f;
#pragma unroll
                for (int j = 0; j < 4; ++j) {
                    float vn = 1.0f / (vs[j] + DENOM_SHIFT);
                    float d = vn - __ldcg(&g_v[m + j]);
                    nacc += d * d;
                    g_v[m + j] = vn;
                }
                atomicAdd(&g_normV[it], nacc);
            }
            __syncthreads();
        }
        ++epoch; grid_barrier(epoch, NC);
        float nu = __ldcg(&g_normU[it]);
        float nv = __ldcg(&g_normV[it]);
        if (nu < CONV_TOL_SQ && nv < CONV_TOL_SQ) break;
    }
}

// ---------------- launch ----------------
extern "C" void kernel_launch(void* const* d_in, const int* in_sizes, int n_in,
                              void* d_out, int out_size) {
    const float* text  = (const float*)d_in[0];
    const float* image = (const float*)d_in[1];
    float* out_text = (float*)d_out;
    float* out_img  = out_text + (size_t)B_DIM * N_TOK * C_DIM;

    cudaFuncSetAttribute(k_gemm1, cudaFuncAttributeMaxDynamicSharedMemorySize, SMEM_GEMM);
    cudaFuncSetAttribute(k_gemm23, cudaFuncAttributeMaxDynamicSharedMemorySize, SMEM_GEMM);

    k_init<<<36, 256>>>();
    k_sq_text<<<N_TOK, 256>>>(text);
    k_pack_text<<<dim3(C_DIM / 32, N_TOK / 32, B_DIM), 256>>>(text);
    k_pack_image<<<dim3(M_PIX / 32, L_DIM / 32), 256>>>(image);

    // GEMM1: cost (rows n: 8, cols m: 72), single-term fp16
    k_gemm1<<<dim3(M_PIX / 128, N_TOK / 128), 256, SMEM_GEMM>>>();

    k_sinkhorn<<<148, 256>>>();
    k_pack_T<<<dim3(M_PIX / 32, N_TOK / 32), 256>>>();

    // GEMM2 (split-K=2, 256 CTAs) + GEMM3 (1152 CTAs) fused
    k_gemm23<<<G2_BLOCKS + 1152, 256, SMEM_GEMM>>>(out_text, out_img);
    // fold split-K half 1 into out_text
    k_combine<<<(B_DIM * N_TOK * C_DIM) / (256 * 4), 256>>>(out_text);
}

// round 14
// speedup vs baseline: 7.1078x; 1.1075x over previous
#include <cuda_runtime.h>
#include <cuda_fp16.h>
#include <cstdint>

// ---------------- problem dims ----------------
#define B_DIM 8
#define C_DIM 256
#define N_TOK 1024
#define M_PIX 9216
#define L_DIM 2048
#define TEXT_B_STRIDE  262144    // 1024*256
#define IMG_B_STRIDE   2359296   // 256*9216

#define NITER 50
#define CONV_TOL_SQ 1e-4f
#define DENOM_SHIFT 100.0f

// T pre-scale (exact power of two; keeps T in fp16 normal range)
#define TSCALE      1048576.0f          // 2^20
#define TSCALE_INV  9.5367431640625e-7f // 2^-20

// exp(-10*c) underflows fp32 normals for c > 8.73; contributions below are
// denormal-level (<6.8e-39) and vanish exactly against the +100 shift.
#define KEXP_CUT 8.8f
#define NCB 144                          // M_PIX / 64 column blocks

// ---------------- device scratch (statics; no mallocs) ----------------
__device__ float g_cost[(size_t)N_TOK * M_PIX];  // 37.75 MB
__device__ float g_sqA[N_TOK];
__device__ float g_sqB[M_PIX];
__device__ float g_u[N_TOK];
__device__ float g_v[M_PIX];
__device__ float g_normU[64];
__device__ float g_normV[64];
__device__ unsigned g_bar_count;
__device__ unsigned g_bar_gen;

// per-(row, 64-col-block) min of cost, written by GEMM1 epilogue
__device__ float g_minc[(size_t)N_TOK * NCB];
__device__ int g_rowAny[N_TOK];   // row n has any block with min <= cut
__device__ int g_colAny[NCB];     // col block has any row with min <= cut

// fp16 operand buffers (K-major), single plane each
__device__ __half g_hA1[(size_t)N_TOK * L_DIM];  // text  [n][l]
__device__ __half g_hB1[(size_t)M_PIX * L_DIM];  // image [m][l]; reused as fp32
                                                 // split-K scratch after GEMM1
__device__ __half g_hT2[(size_t)N_TOK * M_PIX];  // T*2^20 [n][m]
__device__ __half g_hB2[(size_t)L_DIM * M_PIX];  // image [l][m]
__device__ __half g_hA3[(size_t)L_DIM * N_TOK];  // text  [l][n]
__device__ __half g_hT3[(size_t)M_PIX * N_TOK];  // T*2^20 [m][n]

// ---------------- helpers ----------------
__device__ __forceinline__ uint32_t smem_to_u32(const void* p) {
    uint32_t a;
    asm("{ .reg .u64 t; cvta.to.shared.u64 t, %1; cvt.u32.u64 %0, t; }" : "=r"(a) : "l"(p));
    return a;
}
__device__ __forceinline__ void ldsm_x4(uint32_t* r, uint32_t a) {
    asm volatile("ldmatrix.sync.aligned.m8n8.x4.shared.b16 {%0,%1,%2,%3}, [%4];"
                 : "=r"(r[0]), "=r"(r[1]), "=r"(r[2]), "=r"(r[3]) : "r"(a));
}
__device__ __forceinline__ void mma_f16(float* c, const uint32_t* a, const uint32_t* b) {
    asm volatile(
        "mma.sync.aligned.m16n8k16.row.col.f32.f16.f16.f32 "
        "{%0,%1,%2,%3}, {%4,%5,%6,%7}, {%8,%9}, {%0,%1,%2,%3};"
        : "+f"(c[0]), "+f"(c[1]), "+f"(c[2]), "+f"(c[3])
        : "r"(a[0]), "r"(a[1]), "r"(a[2]), "r"(a[3]), "r"(b[0]), "r"(b[1]));
}
__device__ __forceinline__ void cp16(uint32_t dst, const void* src) {
    asm volatile("cp.async.cg.shared.global [%0], [%1], 16;" :: "r"(dst), "l"(src));
}
__device__ __forceinline__ void cp_commit() {
    asm volatile("cp.async.commit_group;" ::: "memory");
}
template <int N>
__device__ __forceinline__ void cp_wait() {
    asm volatile("cp.async.wait_group %0;" :: "n"(N) : "memory");
}
__device__ __forceinline__ uint32_t pack2h(float a, float b) {
    __half2 h = __floats2half2_rn(a, b);
    return *(uint32_t*)&h;
}

// ---------------- init ----------------
__global__ void k_init() {
    int tid = blockIdx.x * blockDim.x + threadIdx.x;
    if (tid < N_TOK) g_u[tid] = 1.0f;
    if (tid < M_PIX) { g_v[tid] = 1.0f; g_sqB[tid] = 0.0f; }
    if (tid < 64) { g_normU[tid] = 0.0f; g_normV[tid] = 0.0f; }
    if (tid == 0) { g_bar_count = 0u; g_bar_gen = 0u; }
}

// ---------------- text squared norms ----------------
__global__ void k_sq_text(const float* __restrict__ text) {
    __shared__ float sh[256];
    int n = blockIdx.x, c = threadIdx.x;
    float s = 0.0f;
#pragma unroll
    for (int b = 0; b < B_DIM; ++b) {
        float x = text[(size_t)b * TEXT_B_STRIDE + (size_t)n * C_DIM + c];
        s += x * x;
    }
    sh[c] = s; __syncthreads();
    for (int off = 128; off > 0; off >>= 1) {
        if (c < off) sh[c] += sh[c + off];
        __syncthreads();
    }
    if (c == 0) g_sqA[n] = sh[0];
}

// ---------------- vectorized pack kernels ----------------
__global__ void k_pack_text(const float* __restrict__ text) {
    __shared__ float t[32][33];
    const int b = blockIdx.z, n0 = blockIdx.y * 32, c0 = blockIdx.x * 32;
    const int tid = threadIdx.x, r = tid >> 3, c4 = (tid & 7) << 2;
    float4 v = *(const float4*)(text + (size_t)b * TEXT_B_STRIDE +
                                (size_t)(n0 + r) * C_DIM + c0 + c4);
    t[r][c4] = v.x; t[r][c4 + 1] = v.y; t[r][c4 + 2] = v.z; t[r][c4 + 3] = v.w;
    uint2 s1; s1.x = pack2h(v.x, v.y); s1.y = pack2h(v.z, v.w);
    *(uint2*)(g_hA1 + (size_t)(n0 + r) * L_DIM + b * C_DIM + c0 + c4) = s1;
    __syncthreads();
    uint2 s2;
    s2.x = pack2h(t[c4][r], t[c4 + 1][r]);
    s2.y = pack2h(t[c4 + 2][r], t[c4 + 3][r]);
    *(uint2*)(g_hA3 + (size_t)(b * C_DIM + c0 + r) * N_TOK + n0 + c4) = s2;
}

__global__ void k_pack_image(const float* __restrict__ image) {
    __shared__ float t[32][33];
    __shared__ float ss[8][33];
    const int l0 = blockIdx.y * 32, m0 = blockIdx.x * 32;
    const int tid = threadIdx.x, r = tid >> 3, c4 = (tid & 7) << 2;
    float4 v = *(const float4*)(image + (size_t)(l0 + r) * M_PIX + m0 + c4);
    t[r][c4] = v.x; t[r][c4 + 1] = v.y; t[r][c4 + 2] = v.z; t[r][c4 + 3] = v.w;
    uint2 s1; s1.x = pack2h(v.x, v.y); s1.y = pack2h(v.z, v.w);
    *(uint2*)(g_hB2 + (size_t)(l0 + r) * M_PIX + m0 + c4) = s1;
    __syncthreads();
    uint2 s2;
    s2.x = pack2h(t[c4][r], t[c4 + 1][r]);
    s2.y = pack2h(t[c4 + 2][r], t[c4 + 3][r]);
    *(uint2*)(g_hB1 + (size_t)(m0 + r) * L_DIM + l0 + c4) = s2;
    {
        const int c = tid & 31, part = tid >> 5;
        float s = 0.0f;
#pragma unroll
        for (int k = 0; k < 4; ++k) s += t[part * 4 + k][c] * t[part * 4 + k][c];
        ss[part][c] = s;
    }
    __syncthreads();
    if (tid < 32) {
        float s = 0.0f;
#pragma unroll
        for (int j = 0; j < 8; ++j) s += ss[j][tid];
        atomicAdd(&g_sqB[m0 + tid], s);
    }
}

__global__ void k_pack_T() {
    __shared__ float t[32][33];
    const int n0 = blockIdx.y * 32, m0 = blockIdx.x * 32;
    const int tid = threadIdx.x, r = tid >> 3, c4 = (tid & 7) << 2;
    float4 c = *(const float4*)(g_cost + (size_t)(n0 + r) * M_PIX + m0 + c4);
    float4 v4 = *(const float4*)(g_v + m0 + c4);
    const float us = g_u[n0 + r] * TSCALE;
    float4 w;
    w.x = expf(-0.1f * c.x) * us * v4.x;
    w.y = expf(-0.1f * c.y) * us * v4.y;
    w.z = expf(-0.1f * c.z) * us * v4.z;
    w.w = expf(-0.1f * c.w) * us * v4.w;
    t[r][c4] = w.x; t[r][c4 + 1] = w.y; t[r][c4 + 2] = w.z; t[r][c4 + 3] = w.w;
    uint2 s1; s1.x = pack2h(w.x, w.y); s1.y = pack2h(w.z, w.w);
    *(uint2*)(g_hT2 + (size_t)(n0 + r) * M_PIX + m0 + c4) = s1;
    __syncthreads();
    uint2 s2;
    s2.x = pack2h(t[c4][r], t[c4 + 1][r]);
    s2.y = pack2h(t[c4 + 2][r], t[c4 + 3][r]);
    *(uint2*)(g_hT3 + (size_t)(m0 + r) * N_TOK + n0 + c4) = s2;
}

// ---------------- GEMM geometry (all single-term fp16) ----------------
#define SPAD 40
#define TILE_BYTES (128 * SPAD * 2)
#define OFF_A 0
#define OFF_B (TILE_BYTES)
#define STAGE (2 * TILE_BYTES)
#define SMEM_GEMM (3 * STAGE)        // 61440 -> 2 CTAs/SM

// =====================================================================
// GEMM1: cost = sqrt(sqA+sqB-2*A.B); also writes g_minc per 32x64 warp block.
// =====================================================================
__global__ void __launch_bounds__(256, 2) k_gemm1() {
    extern __shared__ char sm[];
    const int tid = threadIdx.x, wid = tid >> 5, lane = tid & 31;
    const int wy = wid >> 1, wx = wid & 1;
    const int row0 = blockIdx.y * 128, col0 = blockIdx.x * 128;
    const uint32_t smb = smem_to_u32(sm);

    float acc[2][8][4] = {};

    const int ld_r = tid >> 2, ld_c = (tid & 3) << 3;
    const int a_r = lane & 15, a_c = (lane >> 4) << 3;
    const int b_r = (lane & 7) + (((lane >> 4) & 1) << 3), b_c = ((lane >> 3) & 1) << 3;

    const int KCH = L_DIM >> 5;

    auto issue = [&](int kc) {
        if (kc < KCH) {
            const int k0 = kc << 5;
            const uint32_t sb = smb + (kc % 3) * STAGE;
#pragma unroll
            for (int i = 0; i < 2; ++i) {
                int r = ld_r + i * 64;
                uint32_t so = (uint32_t)(r * SPAD + ld_c) * 2;
                cp16(sb + OFF_A + so, g_hA1 + (size_t)(row0 + r) * L_DIM + k0 + ld_c);
                cp16(sb + OFF_B + so, g_hB1 + (size_t)(col0 + r) * L_DIM + k0 + ld_c);
            }
        }
        cp_commit();
    };

    issue(0); issue(1);
    for (int kc = 0; kc < KCH; ++kc) {
        cp_wait<1>();
        __syncthreads();
        issue(kc + 2);
        const uint32_t sb = smb + (kc % 3) * STAGE;
#pragma unroll
        for (int kk = 0; kk < 2; ++kk) {
            uint32_t ah[2][4], bh[4][4];
#pragma unroll
            for (int mt = 0; mt < 2; ++mt) {
                uint32_t off = (uint32_t)((wy * 32 + mt * 16 + a_r) * SPAD + kk * 16 + a_c) * 2;
                ldsm_x4(ah[mt], sb + OFF_A + off);
            }
#pragma unroll
            for (int p = 0; p < 4; ++p) {
                uint32_t off = (uint32_t)((wx * 64 + p * 16 + b_r) * SPAD + kk * 16 + b_c) * 2;
                ldsm_x4(bh[p], sb + OFF_B + off);
            }
#pragma unroll
            for (int mt = 0; mt < 2; ++mt)
#pragma unroll
                for (int nt = 0; nt < 8; ++nt) {
                    const uint32_t bb[2] = { bh[nt >> 1][(nt & 1) * 2],
                                             bh[nt >> 1][(nt & 1) * 2 + 1] };
                    mma_f16(acc[mt][nt], ah[mt], bb);
                }
        }
    }

    const int rbase = row0 + wy * 32 + (lane >> 2);
    const int cbase = col0 + wx * 64 + ((lane & 3) << 1);
    float rmin[4] = { 1e30f, 1e30f, 1e30f, 1e30f };  // rows rA0, rB0, rA1, rB1
#pragma unroll
    for (int mt = 0; mt < 2; ++mt) {
        int rA = rbase + mt * 16, rB = rA + 8;
        float saA = g_sqA[rA], saB = g_sqA[rB];
#pragma unroll
        for (int nt = 0; nt < 8; ++nt) {
            int cc = cbase + nt * 8;
            float sb0 = g_sqB[cc], sb1 = g_sqB[cc + 1];
            float2 oA, oB;
            oA.x = sqrtf(fmaxf(saA + sb0 - 2.0f * acc[mt][nt][0], 1e-12f));
            oA.y = sqrtf(fmaxf(saA + sb1 - 2.0f * acc[mt][nt][1], 1e-12f));
            oB.x = sqrtf(fmaxf(saB + sb0 - 2.0f * acc[mt][nt][2], 1e-12f));
            oB.y = sqrtf(fmaxf(saB + sb1 - 2.0f * acc[mt][nt][3], 1e-12f));
            rmin[mt * 2]     = fminf(rmin[mt * 2],     fminf(oA.x, oA.y));
            rmin[mt * 2 + 1] = fminf(rmin[mt * 2 + 1], fminf(oB.x, oB.y));
            *(float2*)(g_cost + (size_t)rA * M_PIX + cc) = oA;
            *(float2*)(g_cost + (size_t)rB * M_PIX + cc) = oB;
        }
    }
    // per-row min over the warp's 64-col block (4 lanes share a row)
#pragma unroll
    for (int i = 0; i < 4; ++i) {
        rmin[i] = fminf(rmin[i], __shfl_xor_sync(0xffffffffu, rmin[i], 1));
        rmin[i] = fminf(rmin[i], __shfl_xor_sync(0xffffffffu, rmin[i], 2));
    }
    if ((lane & 3) == 0) {
        const int cb = (col0 + wx * 64) >> 6;
        g_minc[(size_t)(rbase)      * NCB + cb] = rmin[0];
        g_minc[(size_t)(rbase + 8)  * NCB + cb] = rmin[1];
        g_minc[(size_t)(rbase + 16) * NCB + cb] = rmin[2];
        g_minc[(size_t)(rbase + 24) * NCB + cb] = rmin[3];
    }
}

// ---------------- min-table scan: row/col any-active flags ----------------
__global__ void k_minscan() {
    __shared__ float sh[256];
    const int bid = blockIdx.x, tid = threadIdx.x;
    if (bid < 4) {
        // rows: 256 rows per block, each thread scans its row's 144 mins
        const int n = bid * 256 + tid;
        const float* p = g_minc + (size_t)n * NCB;
        float mn = 1e30f;
        for (int cb = 0; cb < NCB; ++cb) mn = fminf(mn, p[cb]);
        g_rowAny[n] = (mn <= KEXP_CUT) ? 1 : 0;
    } else {
        // cols: one block per cb, min over 1024 rows
        const int cb = bid - 4;
        float mn = 1e30f;
        for (int n = tid; n < N_TOK; n += 256)
            mn = fminf(mn, g_minc[(size_t)n * NCB + cb]);
        sh[tid] = mn; __syncthreads();
        for (int off = 128; off > 0; off >>= 1) {
            if (tid < off) sh[tid] = fminf(sh[tid], sh[tid + off]);
            __syncthreads();
        }
        if (tid == 0) g_colAny[cb] = (sh[0] <= KEXP_CUT) ? 1 : 0;
    }
}

// =====================================================================
// GEMM2+3 fused, single-term fp16, split-K=2 on GEMM2 for tail balance.
// =====================================================================
#define G2_BLOCKS 256
#define G2_KCH_HALF 144

__global__ void __launch_bounds__(256, 2) k_gemm23(float* __restrict__ out_text,
                                                   float* __restrict__ out_img) {
    extern __shared__ char sm[];
    const int bid = blockIdx.x;
    const bool isG2 = (bid < G2_BLOCKS);
    int bx, by, ks = 0;
    if (isG2) { int b2 = bid & 127; bx = b2 & 15; by = b2 >> 4; ks = bid >> 7; }
    else { int b = bid - G2_BLOCKS; bx = b % 72; by = b / 72; }

    const __half *A_, *B_;
    int Ktot; float* out;
    if (isG2) {
        A_ = g_hT2; B_ = g_hB2; Ktot = M_PIX;
        out = ks ? (float*)g_hB1 : out_text;
    } else { A_ = g_hA3; B_ = g_hT3; Ktot = N_TOK; out = out_img; }

    const int tid = threadIdx.x, wid = tid >> 5, lane = tid & 31;
    const int wy = wid >> 1, wx = wid & 1;
    const int row0 = by * 128, col0 = bx * 128;
    const uint32_t smb = smem_to_u32(sm);

    float acc[2][8][4] = {};

    const int ld_r = tid >> 2, ld_c = (tid & 3) << 3;
    const int a_r = lane & 15, a_c = (lane >> 4) << 3;
    const int b_r = (lane & 7) + (((lane >> 4) & 1) << 3), b_c = ((lane >> 3) & 1) << 3;

    const int kc_beg = isG2 ? ks * G2_KCH_HALF : 0;
    const int kc_end = isG2 ? kc_beg + G2_KCH_HALF : (Ktot >> 5);

    auto issue = [&](int kc) {
        if (kc < kc_end) {
            const int k0 = kc << 5;
            const uint32_t sb = smb + (kc % 3) * STAGE;
#pragma unroll
            for (int i = 0; i < 2; ++i) {
                int r = ld_r + i * 64;
                uint32_t so = (uint32_t)(r * SPAD + ld_c) * 2;
                cp16(sb + OFF_A + so, A_ + (size_t)(row0 + r) * Ktot + k0 + ld_c);
                cp16(sb + OFF_B + so, B_ + (size_t)(col0 + r) * Ktot + k0 + ld_c);
            }
        }
        cp_commit();
    };

    issue(kc_beg); issue(kc_beg + 1);
    for (int kc = kc_beg; kc < kc_end; ++kc) {
        cp_wait<1>();
        __syncthreads();
        issue(kc + 2);
        const uint32_t sb = smb + (kc % 3) * STAGE;
#pragma unroll
        for (int kk = 0; kk < 2; ++kk) {
            uint32_t ah[2][4], bh[4][4];
#pragma unroll
            for (int mt = 0; mt < 2; ++mt) {
                uint32_t off = (uint32_t)((wy * 32 + mt * 16 + a_r) * SPAD + kk * 16 + a_c) * 2;
                ldsm_x4(ah[mt], sb + OFF_A + off);
            }
#pragma unroll
            for (int p = 0; p < 4; ++p) {
                uint32_t off = (uint32_t)((wx * 64 + p * 16 + b_r) * SPAD + kk * 16 + b_c) * 2;
                ldsm_x4(bh[p], sb + OFF_B + off);
            }
#pragma unroll
            for (int mt = 0; mt < 2; ++mt)
#pragma unroll
                for (int nt = 0; nt < 8; ++nt) {
                    const uint32_t bb[2] = { bh[nt >> 1][(nt & 1) * 2],
                                             bh[nt >> 1][(nt & 1) * 2 + 1] };
                    mma_f16(acc[mt][nt], ah[mt], bb);
                }
        }
    }

    const int rbase = row0 + wy * 32 + (lane >> 2);
    const int cbase = col0 + wx * 64 + ((lane & 3) << 1);
#pragma unroll
    for (int mt = 0; mt < 2; ++mt) {
        int rA = rbase + mt * 16, rB = rA + 8;
#pragma unroll
        for (int nt = 0; nt < 8; ++nt) {
            int cc = cbase + nt * 8;
            float d0 = acc[mt][nt][0] * TSCALE_INV, d1 = acc[mt][nt][1] * TSCALE_INV;
            float d2 = acc[mt][nt][2] * TSCALE_INV, d3 = acc[mt][nt][3] * TSCALE_INV;
            if (isG2) {
                int b = cc >> 8, c = cc & 255;
                float* pA = out + (size_t)b * TEXT_B_STRIDE + (size_t)rA * C_DIM + c;
                float* pB = out + (size_t)b * TEXT_B_STRIDE + (size_t)rB * C_DIM + c;
                *(float2*)pA = make_float2(d0, d1);
                *(float2*)pB = make_float2(d2, d3);
            } else {
                *(float2*)(out + (size_t)rA * M_PIX + cc) = make_float2(d0, d1);
                *(float2*)(out + (size_t)rB * M_PIX + cc) = make_float2(d2, d3);
            }
        }
    }
}

// combine split-K halves: out_text += scratch (deterministic, no atomics)
__global__ void k_combine(float* __restrict__ out_text) {
    const float* scr = (const float*)g_hB1;
    size_t i = ((size_t)blockIdx.x * 256 + threadIdx.x) * 4;
    float4 o = *(float4*)(out_text + i);
    float4 s = *(const float4*)(scr + i);
    o.x += s.x; o.y += s.y; o.z += s.z; o.w += s.w;
    *(float4*)(out_text + i) = o;
}

// ---------------- Sinkhorn (persistent; block-level underflow mask) ----------------
__device__ __forceinline__ void grid_barrier(unsigned e, int nctas) {
    __syncthreads();
    if (threadIdx.x == 0) {
        __threadfence();
        unsigned t = atomicAdd(&g_bar_count, 1u) + 1u;
        if (t == (unsigned)nctas * e) {
            atomicExch(&g_bar_gen, e);
        } else {
            while (*((volatile unsigned*)&g_bar_gen) < e) __nanosleep(64);
        }
        __threadfence();
    }
    __syncthreads();
}

__global__ void k_sinkhorn() {
    __shared__ float4 sred4[256];
    float* sred = (float*)sred4;
    const int cta = blockIdx.x;
    const int tid = threadIdx.x;
    const int NC = gridDim.x;
    unsigned epoch = 0;
    for (int it = 0; it < NITER; ++it) {
        // ---- U phase ----
        for (int n = cta; n < N_TOK; n += NC) {
            const int any = __ldcg(&g_rowAny[n]);   // uniform across block
            if (any) {
                const float* row = g_cost + (size_t)n * M_PIX;
                float s = 0.0f;
                for (int m = tid << 2; m < M_PIX; m += 1024) {
                    float4 c4 = *(const float4*)(row + m);
                    if (c4.x <= KEXP_CUT || c4.y <= KEXP_CUT ||
                        c4.z <= KEXP_CUT || c4.w <= KEXP_CUT) {
                        float4 v4 = __ldcg((const float4*)(g_v + m));
                        s += __expf(-10.0f * c4.x) * v4.x + __expf(-10.0f * c4.y) * v4.y
                           + __expf(-10.0f * c4.z) * v4.z + __expf(-10.0f * c4.w) * v4.w;
                    }
                }
                sred[tid] = s; __syncthreads();
                for (int off = 128; off > 0; off >>= 1) {
                    if (tid < off) sred[tid] += sred[tid + off];
                    __syncthreads();
                }
            }
            if (tid == 0) {
                float base = any ? sred[0] : 0.0f;
                float un = 1.0f / (base + DENOM_SHIFT);
                float d = un - __ldcg(&g_u[n]);
                atomicAdd(&g_normU[it], d * d);
                g_u[n] = un;
            }
            __syncthreads();
        }
        ++epoch; grid_barrier(epoch, NC);
        // ---- V phase ----
        for (int blk = cta; blk < NCB; blk += NC) {
            const int col0 = blk * 64;
            const int any = __ldcg(&g_colAny[blk]);   // uniform across block
            if (any) {
                const int cg = (tid & 15) << 2;
                const int sl = tid >> 4;
                float4 t4 = make_float4(0.f, 0.f, 0.f, 0.f);
                for (int n = sl; n < N_TOK; n += 16) {
                    float4 c4 = *(const float4*)(g_cost + (size_t)n * M_PIX + col0 + cg);
                    if (c4.x <= KEXP_CUT || c4.y <= KEXP_CUT ||
                        c4.z <= KEXP_CUT || c4.w <= KEXP_CUT) {
                        float un = __ldcg(&g_u[n]);
                        t4.x += __expf(-10.0f * c4.x) * un;
                        t4.y += __expf(-10.0f * c4.y) * un;
                        t4.z += __expf(-10.0f * c4.z) * un;
                        t4.w += __expf(-10.0f * c4.w) * un;
                    }
                }
                sred4[tid] = t4; __syncthreads();
            }
            if (tid < 16) {
                float4 a = make_float4(0.f, 0.f, 0.f, 0.f);
                if (any) {
                    a = sred4[tid];
#pragma unroll
                    for (int j = 1; j < 16; ++j) {
                        float4 b = sred4[tid + j * 16];
                        a.x += b.x; a.y += b.y; a.z += b.z; a.w += b.w;
                    }
                }
                const int m = col0 + (tid << 2);
                float vs[4] = { a.x, a.y, a.z, a.w };
                float nacc = 0.0f;
#pragma unroll
                for (int j = 0; j < 4; ++j) {
                    float vn = 1.0f / (vs[j] + DENOM_SHIFT);
                    float d = vn - __ldcg(&g_v[m + j]);
                    nacc += d * d;
                    g_v[m + j] = vn;
                }
                atomicAdd(&g_normV[it], nacc);
            }
            __syncthreads();
        }
        ++epoch; grid_barrier(epoch, NC);
        float nu = __ldcg(&g_normU[it]);
        float nv = __ldcg(&g_normV[it]);
        if (nu < CONV_TOL_SQ && nv < CONV_TOL_SQ) break;
    }
}

// ---------------- launch ----------------
extern "C" void kernel_launch(void* const* d_in, const int* in_sizes, int n_in,
                              void* d_out, int out_size) {
    const float* text  = (const float*)d_in[0];
    const float* image = (const float*)d_in[1];
    float* out_text = (float*)d_out;
    float* out_img  = out_text + (size_t)B_DIM * N_TOK * C_DIM;

    cudaFuncSetAttribute(k_gemm1, cudaFuncAttributeMaxDynamicSharedMemorySize, SMEM_GEMM);
    cudaFuncSetAttribute(k_gemm23, cudaFuncAttributeMaxDynamicSharedMemorySize, SMEM_GEMM);

    k_init<<<36, 256>>>();
    k_sq_text<<<N_TOK, 256>>>(text);
    k_pack_text<<<dim3(C_DIM / 32, N_TOK / 32, B_DIM), 256>>>(text);
    k_pack_image<<<dim3(M_PIX / 32, L_DIM / 32), 256>>>(image);

    // GEMM1: cost + per-block min table
    k_gemm1<<<dim3(M_PIX / 128, N_TOK / 128), 256, SMEM_GEMM>>>();
    k_minscan<<<4 + NCB, 256>>>();

    k_sinkhorn<<<148, 256>>>();
    k_pack_T<<<dim3(M_PIX / 32, N_TOK / 32), 256>>>();

    // GEMM2 (split-K=2, 256 CTAs) + GEMM3 (1152 CTAs) fused
    k_gemm23<<<G2_BLOCKS + 1152, 256, SMEM_GEMM>>>(out_text, out_img);
    k_combine<<<(B_DIM * N_TOK * C_DIM) / (256 * 4), 256>>>(out_text);
}